// round 3
// baseline (speedup 1.0000x reference)
#include <cuda_runtime.h>
#include <cuda_bf16.h>
#include <math.h>
#include <stdint.h>

#define T_  12
#define E_  8192
#define H_  256
#define V_  800
#define B_  256
#define NB_ 8
#define M_  (T_*E_)   // 98304 messages; h has 1+M rows (row 0 = pad)

// ---------------- scratch (static device arrays; no allocs allowed) ----------
__device__ float g_hU[(size_t)(M_+1)*H_];   // h @ Ur (fp32), incrementally extended
__device__ float g_Ez[(size_t)V_*H_];       // embedding @ Wz[0:H]
__device__ float g_Er[(size_t)V_*H_];       // embedding @ Wr
__device__ float g_Eh[(size_t)V_*H_];       // embedding @ Wh[0:H]
__device__ float g_Eo[(size_t)V_*H_];       // embedding @ Wo[0:H]

// bf16 hi/lo split weights for MMA GEMMs
__device__ __nv_bfloat16 g_Wzh_hi[H_*H_], g_Wzh_lo[H_*H_];
__device__ __nv_bfloat16 g_Whh_hi[H_*H_], g_Whh_lo[H_*H_];
__device__ __nv_bfloat16 g_Ur_hi [H_*H_], g_Ur_lo [H_*H_];

__device__ __forceinline__ float sigf(float x) { return 1.0f / (1.0f + __expf(-x)); }

// ---------------- PTX helpers -------------------------------------------------
__device__ __forceinline__ uint32_t smem_u32(const void* p) {
    return (uint32_t)__cvta_generic_to_shared(p);
}
__device__ __forceinline__ void ldsm4(uint32_t* r, uint32_t a) {
    asm volatile("ldmatrix.sync.aligned.m8n8.x4.shared.b16 {%0,%1,%2,%3},[%4];\n"
                 : "=r"(r[0]), "=r"(r[1]), "=r"(r[2]), "=r"(r[3]) : "r"(a));
}
__device__ __forceinline__ void ldsm4t(uint32_t* r, uint32_t a) {
    asm volatile("ldmatrix.sync.aligned.m8n8.x4.trans.shared.b16 {%0,%1,%2,%3},[%4];\n"
                 : "=r"(r[0]), "=r"(r[1]), "=r"(r[2]), "=r"(r[3]) : "r"(a));
}
__device__ __forceinline__ void mma16816(float* d, const uint32_t* a, const uint32_t* b) {
    asm volatile("mma.sync.aligned.m16n8k16.row.col.f32.bf16.bf16.f32 "
                 "{%0,%1,%2,%3},{%4,%5,%6,%7},{%8,%9},{%0,%1,%2,%3};\n"
                 : "+f"(d[0]), "+f"(d[1]), "+f"(d[2]), "+f"(d[3])
                 : "r"(a[0]), "r"(a[1]), "r"(a[2]), "r"(a[3]), "r"(b[0]), "r"(b[1]));
}
__device__ __forceinline__ uint32_t pack_bf2(float a, float b) {
    __nv_bfloat162 t; t.x = __float2bfloat16(a); t.y = __float2bfloat16(b);
    return *reinterpret_cast<uint32_t*>(&t);
}

// ---------------- init --------------------------------------------------------
__global__ void init_zero(float* __restrict__ h)
{
    int c = threadIdx.x;
    h[c]    = 0.0f;
    g_hU[c] = 0.0f;
}

// ---------------- preamble: 4 embedding projections in one launch -------------
__global__ void gemm_pre(const float* __restrict__ emb,
                         const float* __restrict__ Wz, const float* __restrict__ Wr,
                         const float* __restrict__ Wh, const float* __restrict__ Wo)
{
    const float* Bw; float* C;
    switch (blockIdx.z) {
        case 0:  Bw = Wz; C = g_Ez; break;
        case 1:  Bw = Wr; C = g_Er; break;
        case 2:  Bw = Wh; C = g_Eh; break;
        default: Bw = Wo; C = g_Eo; break;
    }
    __shared__ float As[16][64];
    __shared__ float Bs[16][64];
    const int tid = threadIdx.x;
    const int tx = tid & 15, ty = tid >> 4;
    const int rowBase = blockIdx.y * 64;
    const int colBase = blockIdx.x * 64;
    const int lm  = tid >> 2;
    const int lk  = (tid & 3) * 4;
    const int blk = tid >> 4;
    const int bln = (tid & 15) * 4;
    float acc[4][4] = {};
    for (int kb = 0; kb < 256; kb += 16) {
        int ar = rowBase + lm;
        float4 av = make_float4(0.f, 0.f, 0.f, 0.f);
        if (ar < V_)
            av = *reinterpret_cast<const float4*>(&emb[(size_t)ar * 256 + kb + lk]);
        As[lk + 0][lm] = av.x; As[lk + 1][lm] = av.y;
        As[lk + 2][lm] = av.z; As[lk + 3][lm] = av.w;
        float4 bv = *reinterpret_cast<const float4*>(&Bw[(size_t)(kb + blk) * 256 + colBase + bln]);
        *reinterpret_cast<float4*>(&Bs[blk][bln]) = bv;
        __syncthreads();
#pragma unroll
        for (int k = 0; k < 16; ++k) {
            float4 a4 = *reinterpret_cast<const float4*>(&As[k][ty * 4]);
            float4 b4 = *reinterpret_cast<const float4*>(&Bs[k][tx * 4]);
            float aa[4] = {a4.x, a4.y, a4.z, a4.w};
            float bb[4] = {b4.x, b4.y, b4.z, b4.w};
#pragma unroll
            for (int i = 0; i < 4; ++i)
#pragma unroll
                for (int j = 0; j < 4; ++j)
                    acc[i][j] += aa[i] * bb[j];
        }
        __syncthreads();
    }
#pragma unroll
    for (int i = 0; i < 4; ++i) {
        int r = rowBase + ty * 4 + i;
        if (r < V_)
            *reinterpret_cast<float4*>(&C[(size_t)r * 256 + colBase + tx * 4]) =
                make_float4(acc[i][0], acc[i][1], acc[i][2], acc[i][3]);
    }
}

// ---------------- preamble: 3 weight splits in one launch ---------------------
__global__ void split3(const float* __restrict__ Wz, const float* __restrict__ Wh,
                       const float* __restrict__ Ur)
{
    const float* W; __nv_bfloat16 *hi, *lo;
    switch (blockIdx.y) {
        case 0:  W = Wz + H_ * H_; hi = g_Wzh_hi; lo = g_Wzh_lo; break;
        case 1:  W = Wh + H_ * H_; hi = g_Whh_hi; lo = g_Whh_lo; break;
        default: W = Ur;           hi = g_Ur_hi;  lo = g_Ur_lo;  break;
    }
    int i = blockIdx.x * 256 + threadIdx.x;
    float v = W[i];
    __nv_bfloat16 h = __float2bfloat16(v);
    hi[i] = h;
    lo[i] = __float2bfloat16(v - __bfloat162float(h));
}

// ---------------- fused step kernel -------------------------------------------
// 64 rows x full N=256, 512 threads = 16 warps (2 M x 8 N), warp tile 32x32.
#define A_STRIDE 40      // 32 + 8 pad (bf16)
#define B_STRIDE 264     // 256 + 8 pad (bf16)
#define S_STRIDE 264     // fp32 sum buffers, 264 floats/row (66 float4)

#define SMEM_SUM   (64 * S_STRIDE * 4)                 // 67584 each
#define SMEM_STEP  (2*SMEM_SUM + 2*(64*A_STRIDE*2) + 2*(32*B_STRIDE*2) + 512*4 + 64*4)

// one 3-term bf16-split GEMM: acc += A(fp32 smem)[64,256] @ (Bhi+Blo)[256,256]
__device__ __forceinline__ void gemm_smem(
    const float* __restrict__ sSrc,
    const __nv_bfloat16* __restrict__ Bhi, const __nv_bfloat16* __restrict__ Blo,
    float acc[2][4][4],
    __nv_bfloat16* sAhi, __nv_bfloat16* sAlo,
    __nv_bfloat16* sBhi, __nv_bfloat16* sBlo)
{
    const int tid  = threadIdx.x;
    const int lane = tid & 31;
    const int wid  = tid >> 5;
    const int warp_m = wid & 1;      // 2 warps along M
    const int warp_n = wid >> 1;     // 8 warps along N

    const int arow = tid >> 3;            // 0..63
    const int ak4  = (tid & 7) * 4;       // 0..28 (float4 col within 32-wide K tile)
    const int brow = tid >> 4;            // 0..31
    const int bcol = (tid & 15) * 8;      // 0..120

    const uint32_t bAhi = smem_u32(sAhi), bAlo = smem_u32(sAlo);
    const uint32_t bBhi = smem_u32(sBhi), bBlo = smem_u32(sBlo);

    for (int kb = 0; kb < 256; kb += 32) {
        __syncthreads();
        // stage A: fp32 smem -> bf16 hi/lo
        {
            float4 v = *reinterpret_cast<const float4*>(&sSrc[arow * S_STRIDE + kb + ak4]);
            __nv_bfloat16 h0 = __float2bfloat16(v.x), h1 = __float2bfloat16(v.y),
                          h2 = __float2bfloat16(v.z), h3 = __float2bfloat16(v.w);
            uint2 uh;
            { __nv_bfloat162 a; a.x = h0; a.y = h1; uh.x = *reinterpret_cast<uint32_t*>(&a); }
            { __nv_bfloat162 a; a.x = h2; a.y = h3; uh.y = *reinterpret_cast<uint32_t*>(&a); }
            *reinterpret_cast<uint2*>(&sAhi[arow * A_STRIDE + ak4]) = uh;
            uint2 ul;
            ul.x = pack_bf2(v.x - __bfloat162float(h0), v.y - __bfloat162float(h1));
            ul.y = pack_bf2(v.z - __bfloat162float(h2), v.w - __bfloat162float(h3));
            *reinterpret_cast<uint2*>(&sAlo[arow * A_STRIDE + ak4]) = ul;
        }
        // stage B from global (weights, L2-resident)
        *reinterpret_cast<uint4*>(&sBhi[brow * B_STRIDE + bcol]) =
            *reinterpret_cast<const uint4*>(&Bhi[(size_t)(kb + brow) * 256 + bcol]);
        *reinterpret_cast<uint4*>(&sBhi[brow * B_STRIDE + bcol + 128]) =
            *reinterpret_cast<const uint4*>(&Bhi[(size_t)(kb + brow) * 256 + bcol + 128]);
        *reinterpret_cast<uint4*>(&sBlo[brow * B_STRIDE + bcol]) =
            *reinterpret_cast<const uint4*>(&Blo[(size_t)(kb + brow) * 256 + bcol]);
        *reinterpret_cast<uint4*>(&sBlo[brow * B_STRIDE + bcol + 128]) =
            *reinterpret_cast<const uint4*>(&Blo[(size_t)(kb + brow) * 256 + bcol + 128]);
        __syncthreads();

#pragma unroll
        for (int ks = 0; ks < 32; ks += 16) {
            uint32_t ahi[2][4], alo[2][4];
#pragma unroll
            for (int mt = 0; mt < 2; ++mt) {
                const int el = (warp_m * 32 + mt * 16 + (lane & 15)) * A_STRIDE
                             + ks + (lane >> 4) * 8;
                ldsm4(ahi[mt], bAhi + el * 2);
                ldsm4(alo[mt], bAlo + el * 2);
            }
#pragma unroll
            for (int np = 0; np < 2; ++np) {
                const int n0 = warp_n * 32 + np * 16;
                const int el = (ks + (lane & 7) + ((lane >> 3) & 1) * 8) * B_STRIDE
                             + n0 + (lane >> 4) * 8;
                uint32_t bh_[4], bl_[4];
                ldsm4t(bh_, bBhi + el * 2);
                ldsm4t(bl_, bBlo + el * 2);
#pragma unroll
                for (int mt = 0; mt < 2; ++mt) {
#pragma unroll
                    for (int s = 0; s < 2; ++s) {
                        float* d = acc[mt][np * 2 + s];
                        mma16816(d, ahi[mt], &bh_[2 * s]);
                        mma16816(d, ahi[mt], &bl_[2 * s]);
                        mma16816(d, alo[mt], &bh_[2 * s]);
                    }
                }
            }
        }
    }
}

__global__ void __launch_bounds__(512) step_fused(
    const float* __restrict__ hglob,     // d_out base (row 0 = pad)
    float* __restrict__ hout,            // d_out + (1+t*E)*H
    float* __restrict__ hUout,           // g_hU + (1+t*E)*H
    const int* __restrict__ nei,         // + t*E*NB
    const int* __restrict__ xids,        // + t*E
    const float* __restrict__ bur,
    const float* __restrict__ bz, const float* __restrict__ bhb)
{
    extern __shared__ char smem[];
    float* s_sumh = (float*)smem;                          // [64][S_STRIDE]
    float* s_sumg = (float*)(smem + SMEM_SUM);             // [64][S_STRIDE], later new_h
    __nv_bfloat16* sAhi = (__nv_bfloat16*)(smem + 2*SMEM_SUM);
    __nv_bfloat16* sAlo = sAhi + 64 * A_STRIDE;
    __nv_bfloat16* sBhi = sAlo + 64 * A_STRIDE;
    __nv_bfloat16* sBlo = sBhi + 32 * B_STRIDE;
    int* s_nei = (int*)(sBlo + 32 * B_STRIDE);             // 512
    int* s_xid = s_nei + 512;                              // 64

    const int tid = threadIdx.x;
    const int rowBase = blockIdx.x * 64;

    s_nei[tid] = nei[rowBase * NB_ + tid];
    if (tid < 64) s_xid[tid] = xids[rowBase + tid];
    __syncthreads();

    // ---- phase A: gather sum_h, sum_gated into smem (fp32) ----
    {
        const int msg   = tid >> 3;      // 0..63
        const int lane8 = tid & 7;
        const int xid = s_xid[msg];
        const float4* hv4 = (const float4*)hglob;
        const float4* uv4 = (const float4*)g_hU;
        const float4* bu4 = (const float4*)bur;
        const float4* er4 = (const float4*)&g_Er[(size_t)xid * H_];
#pragma unroll
        for (int i = 0; i < 8; ++i) {
            const int c4 = lane8 + i * 8;   // 0..63
            const float4 bu = bu4[c4];
            const float4 er = er4[c4];
            const float bx = er.x + bu.x, by = er.y + bu.y;
            const float bz2 = er.z + bu.z, bw = er.w + bu.w;
            float4 sh = make_float4(0.f, 0.f, 0.f, 0.f);
            float4 sg = make_float4(0.f, 0.f, 0.f, 0.f);
#pragma unroll
            for (int n = 0; n < NB_; ++n) {
                const int j = s_nei[msg * NB_ + n];
                const float4 hv = hv4[(size_t)j * 64 + c4];
                const float4 uv = uv4[(size_t)j * 64 + c4];
                sh.x += hv.x; sh.y += hv.y; sh.z += hv.z; sh.w += hv.w;
                sg.x += sigf(bx  + uv.x) * hv.x;
                sg.y += sigf(by  + uv.y) * hv.y;
                sg.z += sigf(bz2 + uv.z) * hv.z;
                sg.w += sigf(bw  + uv.w) * hv.w;
            }
            *reinterpret_cast<float4*>(&s_sumh[msg * S_STRIDE + c4 * 4]) = sh;
            *reinterpret_cast<float4*>(&s_sumg[msg * S_STRIDE + c4 * 4]) = sg;
        }
    }

    // ---- phase B: acc1 = sum_h @ Wzh, acc2 = sum_gated @ Whh ----
    float acc1[2][4][4] = {};
    float acc2[2][4][4] = {};
    gemm_smem(s_sumh, g_Wzh_hi, g_Wzh_lo, acc1, sAhi, sAlo, sBhi, sBlo);
    gemm_smem(s_sumg, g_Whh_hi, g_Whh_lo, acc2, sAhi, sAlo, sBhi, sBlo);

    // ---- phase C: GRU epilogue -> hout (global) + new_h (smem, reuse s_sumg) --
    const int lane = tid & 31;
    const int wid  = tid >> 5;
    const int warp_m = wid & 1, warp_n = wid >> 1;
#pragma unroll
    for (int mt = 0; mt < 2; ++mt) {
#pragma unroll
        for (int nt = 0; nt < 4; ++nt) {
            const int col = warp_n * 32 + nt * 8 + (lane & 3) * 2;
#pragma unroll
            for (int half = 0; half < 2; ++half) {
                const int lr = warp_m * 32 + mt * 16 + (lane >> 2) + half * 8;
                const int gr = rowBase + lr;
                const float a1x = acc1[mt][nt][half * 2 + 0];
                const float a1y = acc1[mt][nt][half * 2 + 1];
                const float a2x = acc2[mt][nt][half * 2 + 0];
                const float a2y = acc2[mt][nt][half * 2 + 1];
                const int xid = s_xid[lr];
                const float2 ez  = *reinterpret_cast<const float2*>(&g_Ez[(size_t)xid * H_ + col]);
                const float2 eh  = *reinterpret_cast<const float2*>(&g_Eh[(size_t)xid * H_ + col]);
                const float2 bzv = *reinterpret_cast<const float2*>(&bz[col]);
                const float2 bhv = *reinterpret_cast<const float2*>(&bhb[col]);
                const float2 sh  = *reinterpret_cast<const float2*>(&s_sumh[lr * S_STRIDE + col]);
                const float z0 = sigf(ez.x + bzv.x + a1x);
                const float z1 = sigf(ez.y + bzv.y + a1y);
                const float p0 = tanhf(eh.x + bhv.x + a2x);
                const float p1 = tanhf(eh.y + bhv.y + a2y);
                const float o0 = (1.0f - z0) * sh.x + z0 * p0;
                const float o1 = (1.0f - z1) * sh.y + z1 * p1;
                *reinterpret_cast<float2*>(&hout[(size_t)gr * H_ + col]) = make_float2(o0, o1);
                *reinterpret_cast<float2*>(&s_sumg[lr * S_STRIDE + col]) = make_float2(o0, o1);
            }
        }
    }

    // ---- phase D: hU rows = new_h @ Ur ----
    float acc3[2][4][4] = {};
    gemm_smem(s_sumg, g_Ur_hi, g_Ur_lo, acc3, sAhi, sAlo, sBhi, sBlo);
#pragma unroll
    for (int mt = 0; mt < 2; ++mt) {
#pragma unroll
        for (int nt = 0; nt < 4; ++nt) {
            const int col = warp_n * 32 + nt * 8 + (lane & 3) * 2;
            const int lr0 = warp_m * 32 + mt * 16 + (lane >> 2);
            *reinterpret_cast<float2*>(&hUout[(size_t)(rowBase + lr0) * H_ + col]) =
                make_float2(acc3[mt][nt][0], acc3[mt][nt][1]);
            *reinterpret_cast<float2*>(&hUout[(size_t)(rowBase + lr0 + 8) * H_ + col]) =
                make_float2(acc3[mt][nt][2], acc3[mt][nt][3]);
        }
    }
}

// ---------------- fused root aggregate ----------------------------------------
__global__ void root_fused(const float* __restrict__ h, const int* __restrict__ rnei,
                           const int* __restrict__ rwid, const float* __restrict__ Woh,
                           const float* __restrict__ bo, float* __restrict__ out)
{
    __shared__ float s_sum[256];
    __shared__ int sj[NB_];
    const int b = blockIdx.x;
    const int c = threadIdx.x;
    if (c < NB_) sj[c] = rnei[b * NB_ + c];
    __syncthreads();
    float s = 0.f;
#pragma unroll
    for (int n = 0; n < NB_; ++n)
        s += h[(size_t)sj[n] * 256 + c];
    s_sum[c] = s;
    __syncthreads();
    float acc = 0.f;
#pragma unroll 8
    for (int k = 0; k < 256; ++k)
        acc += s_sum[k] * Woh[(size_t)k * 256 + c];
    const int xid = rwid[b];
    float v = g_Eo[(size_t)xid * 256 + c] + bo[c] + acc;
    out[(size_t)b * 256 + c] = fmaxf(v, 0.0f);
}

// ---------------- launch ------------------------------------------------------
extern "C" void kernel_launch(void* const* d_in, const int* in_sizes, int n_in,
                              void* d_out, int out_size)
{
    const int*   x_ids    = (const int*)  d_in[0];
    const int*   nei_idx  = (const int*)  d_in[1];
    const int*   root_wid = (const int*)  d_in[2];
    const int*   root_nei = (const int*)  d_in[3];
    const float* emb      = (const float*)d_in[4];
    const float* Wz       = (const float*)d_in[5];
    const float* bz       = (const float*)d_in[6];
    const float* Wr       = (const float*)d_in[7];
    const float* Ur       = (const float*)d_in[8];
    const float* bur      = (const float*)d_in[9];
    const float* Wh       = (const float*)d_in[10];
    const float* bh       = (const float*)d_in[11];
    const float* Wo       = (const float*)d_in[12];
    const float* bo       = (const float*)d_in[13];

    float* out  = (float*)d_out;
    float* h    = out;
    float* rvec = out + (size_t)(M_ + 1) * H_;

    float* p_hU;
    cudaGetSymbolAddress((void**)&p_hU, g_hU);

    static bool attr_done = false;
    if (!attr_done) {
        cudaFuncSetAttribute(step_fused, cudaFuncAttributeMaxDynamicSharedMemorySize,
                             SMEM_STEP);
        attr_done = true;
    }

    init_zero<<<1, 256>>>(h);

    dim3 gpre(4, (V_ + 63) / 64, 4);
    gemm_pre<<<gpre, 256>>>(emb, Wz, Wr, Wh, Wo);
    split3<<<dim3(256, 3), 256>>>(Wz, Wh, Ur);

    for (int t = 0; t < T_; ++t) {
        step_fused<<<E_ / 64, 512, SMEM_STEP>>>(
            h,
            h + (size_t)(1 + t * E_) * H_,
            p_hU + (size_t)(1 + t * E_) * H_,
            nei_idx + (size_t)t * E_ * NB_,
            x_ids + (size_t)t * E_,
            bur, bz, bh);
    }

    root_fused<<<B_, 256>>>(h, root_nei, root_wid, Wo + (size_t)H_ * H_, bo, rvec);
}

// round 4
// speedup vs baseline: 1.1683x; 1.1683x over previous
#include <cuda_runtime.h>
#include <cuda_bf16.h>
#include <math.h>
#include <stdint.h>

#define T_  12
#define E_  8192
#define H_  256
#define V_  800
#define B_  256
#define NB_ 8
#define M_  (T_*E_)   // 98304 messages; h has 1+M rows (row 0 = pad)

// ---------------- scratch (static device arrays; no allocs allowed) ----------
__device__ float g_hU[(size_t)(M_+1)*H_];   // h @ Ur (fp32), incrementally extended
__device__ float g_Ez[(size_t)V_*H_];
__device__ float g_Er[(size_t)V_*H_];
__device__ float g_Eh[(size_t)V_*H_];
__device__ float g_Eo[(size_t)V_*H_];
__device__ float g_rootsum[(size_t)B_*H_];

// bf16 hi/lo split operands for MMA GEMMs
__device__ __nv_bfloat16 g_sh_hi[(size_t)E_*H_], g_sh_lo[(size_t)E_*H_];
__device__ __nv_bfloat16 g_sg_hi[(size_t)E_*H_], g_sg_lo[(size_t)E_*H_];
__device__ __nv_bfloat16 g_hA_hi[(size_t)E_*H_], g_hA_lo[(size_t)E_*H_];
__device__ __nv_bfloat16 g_Wzh_hi[H_*H_], g_Wzh_lo[H_*H_];
__device__ __nv_bfloat16 g_Whh_hi[H_*H_], g_Whh_lo[H_*H_];
__device__ __nv_bfloat16 g_Ur_hi [H_*H_], g_Ur_lo [H_*H_];

__device__ __forceinline__ float sigf(float x) { return 1.0f / (1.0f + __expf(-x)); }

// ---------------- PTX helpers -------------------------------------------------
__device__ __forceinline__ uint32_t smem_u32(const void* p) {
    return (uint32_t)__cvta_generic_to_shared(p);
}
__device__ __forceinline__ void ldsm4(uint32_t* r, uint32_t a) {
    asm volatile("ldmatrix.sync.aligned.m8n8.x4.shared.b16 {%0,%1,%2,%3},[%4];\n"
                 : "=r"(r[0]), "=r"(r[1]), "=r"(r[2]), "=r"(r[3]) : "r"(a));
}
__device__ __forceinline__ void ldsm4t(uint32_t* r, uint32_t a) {
    asm volatile("ldmatrix.sync.aligned.m8n8.x4.trans.shared.b16 {%0,%1,%2,%3},[%4];\n"
                 : "=r"(r[0]), "=r"(r[1]), "=r"(r[2]), "=r"(r[3]) : "r"(a));
}
__device__ __forceinline__ void mma16816(float* d, const uint32_t* a, const uint32_t* b) {
    asm volatile("mma.sync.aligned.m16n8k16.row.col.f32.bf16.bf16.f32 "
                 "{%0,%1,%2,%3},{%4,%5,%6,%7},{%8,%9},{%0,%1,%2,%3};\n"
                 : "+f"(d[0]), "+f"(d[1]), "+f"(d[2]), "+f"(d[3])
                 : "r"(a[0]), "r"(a[1]), "r"(a[2]), "r"(a[3]), "r"(b[0]), "r"(b[1]));
}
__device__ __forceinline__ uint32_t pack_bf2(float a, float b) {
    __nv_bfloat162 t; t.x = __float2bfloat16(a); t.y = __float2bfloat16(b);
    return *reinterpret_cast<uint32_t*>(&t);
}
__device__ __forceinline__ float2 unpack_bf2(uint32_t u) {
    __nv_bfloat162 t = *reinterpret_cast<__nv_bfloat162*>(&u);
    return make_float2(__bfloat162float(t.x), __bfloat162float(t.y));
}

// ---------------- init --------------------------------------------------------
__global__ void init_zero(float* __restrict__ h)
{
    int c = threadIdx.x;
    h[c]    = 0.0f;
    g_hU[c] = 0.0f;
}

// ---------------- preamble: 4 embedding projections in one launch -------------
__global__ void gemm_pre(const float* __restrict__ emb,
                         const float* __restrict__ Wz, const float* __restrict__ Wr,
                         const float* __restrict__ Wh, const float* __restrict__ Wo)
{
    const float* Bw; float* C;
    switch (blockIdx.z) {
        case 0:  Bw = Wz; C = g_Ez; break;
        case 1:  Bw = Wr; C = g_Er; break;
        case 2:  Bw = Wh; C = g_Eh; break;
        default: Bw = Wo; C = g_Eo; break;
    }
    __shared__ float As[16][64];
    __shared__ float Bs[16][64];
    const int tid = threadIdx.x;
    const int tx = tid & 15, ty = tid >> 4;
    const int rowBase = blockIdx.y * 64;
    const int colBase = blockIdx.x * 64;
    const int lm  = tid >> 2;
    const int lk  = (tid & 3) * 4;
    const int blk = tid >> 4;
    const int bln = (tid & 15) * 4;
    float acc[4][4] = {};
    for (int kb = 0; kb < 256; kb += 16) {
        int ar = rowBase + lm;
        float4 av = make_float4(0.f, 0.f, 0.f, 0.f);
        if (ar < V_)
            av = *reinterpret_cast<const float4*>(&emb[(size_t)ar * 256 + kb + lk]);
        As[lk + 0][lm] = av.x; As[lk + 1][lm] = av.y;
        As[lk + 2][lm] = av.z; As[lk + 3][lm] = av.w;
        float4 bv = *reinterpret_cast<const float4*>(&Bw[(size_t)(kb + blk) * 256 + colBase + bln]);
        *reinterpret_cast<float4*>(&Bs[blk][bln]) = bv;
        __syncthreads();
#pragma unroll
        for (int k = 0; k < 16; ++k) {
            float4 a4 = *reinterpret_cast<const float4*>(&As[k][ty * 4]);
            float4 b4 = *reinterpret_cast<const float4*>(&Bs[k][tx * 4]);
            float aa[4] = {a4.x, a4.y, a4.z, a4.w};
            float bb[4] = {b4.x, b4.y, b4.z, b4.w};
#pragma unroll
            for (int i = 0; i < 4; ++i)
#pragma unroll
                for (int j = 0; j < 4; ++j)
                    acc[i][j] += aa[i] * bb[j];
        }
        __syncthreads();
    }
#pragma unroll
    for (int i = 0; i < 4; ++i) {
        int r = rowBase + ty * 4 + i;
        if (r < V_)
            *reinterpret_cast<float4*>(&C[(size_t)r * 256 + colBase + tx * 4]) =
                make_float4(acc[i][0], acc[i][1], acc[i][2], acc[i][3]);
    }
}

// ---------------- preamble: 3 weight splits in one launch ---------------------
__global__ void split3(const float* __restrict__ Wz, const float* __restrict__ Wh,
                       const float* __restrict__ Ur)
{
    const float* W; __nv_bfloat16 *hi, *lo;
    switch (blockIdx.y) {
        case 0:  W = Wz + H_ * H_; hi = g_Wzh_hi; lo = g_Wzh_lo; break;
        case 1:  W = Wh + H_ * H_; hi = g_Whh_hi; lo = g_Whh_lo; break;
        default: W = Ur;           hi = g_Ur_hi;  lo = g_Ur_lo;  break;
    }
    int i = blockIdx.x * 256 + threadIdx.x;
    float v = W[i];
    __nv_bfloat16 h = __float2bfloat16(v);
    hi[i] = h;
    lo[i] = __float2bfloat16(v - __bfloat162float(h));
}

// ---------------- per-step gather: sum_h / sum_gated -> bf16 hi/lo ------------
__global__ void gather_step(const float* __restrict__ h,
                            const int*   __restrict__ nei,
                            const int*   __restrict__ xids,
                            const float* __restrict__ bur)
{
    const int msg = blockIdx.x * 4 + (threadIdx.x >> 6);
    const int c4  = threadIdx.x & 63;          // float4 chunk within H

    const int xid = xids[msg];
    const float4 bu = reinterpret_cast<const float4*>(bur)[c4];
    const float4 er = reinterpret_cast<const float4*>(&g_Er[(size_t)xid * H_])[c4];
    const float bx = er.x + bu.x, by = er.y + bu.y, bz2 = er.z + bu.z, bw = er.w + bu.w;

    float4 sh = make_float4(0.f, 0.f, 0.f, 0.f);
    float4 sg = make_float4(0.f, 0.f, 0.f, 0.f);
#pragma unroll
    for (int n = 0; n < NB_; ++n) {
        const int j = nei[msg * NB_ + n];
        const float4 hv = reinterpret_cast<const float4*>(h)[(size_t)j * 64 + c4];
        const float4 uv = reinterpret_cast<const float4*>(g_hU)[(size_t)j * 64 + c4];
        sh.x += hv.x; sh.y += hv.y; sh.z += hv.z; sh.w += hv.w;
        sg.x += sigf(bx  + uv.x) * hv.x;
        sg.y += sigf(by  + uv.y) * hv.y;
        sg.z += sigf(bz2 + uv.z) * hv.z;
        sg.w += sigf(bw  + uv.w) * hv.w;
    }
    const size_t o4 = (size_t)msg * 64 + c4;
    {
        __nv_bfloat16 h0 = __float2bfloat16(sh.x), h1 = __float2bfloat16(sh.y),
                      h2 = __float2bfloat16(sh.z), h3 = __float2bfloat16(sh.w);
        uint2 u;
        { __nv_bfloat162 a; a.x = h0; a.y = h1; u.x = *reinterpret_cast<uint32_t*>(&a); }
        { __nv_bfloat162 a; a.x = h2; a.y = h3; u.y = *reinterpret_cast<uint32_t*>(&a); }
        reinterpret_cast<uint2*>(g_sh_hi)[o4] = u;
        uint2 v;
        v.x = pack_bf2(sh.x - __bfloat162float(h0), sh.y - __bfloat162float(h1));
        v.y = pack_bf2(sh.z - __bfloat162float(h2), sh.w - __bfloat162float(h3));
        reinterpret_cast<uint2*>(g_sh_lo)[o4] = v;
    }
    {
        __nv_bfloat16 h0 = __float2bfloat16(sg.x), h1 = __float2bfloat16(sg.y),
                      h2 = __float2bfloat16(sg.z), h3 = __float2bfloat16(sg.w);
        uint2 u;
        { __nv_bfloat162 a; a.x = h0; a.y = h1; u.x = *reinterpret_cast<uint32_t*>(&a); }
        { __nv_bfloat162 a; a.x = h2; a.y = h3; u.y = *reinterpret_cast<uint32_t*>(&a); }
        reinterpret_cast<uint2*>(g_sg_hi)[o4] = u;
        uint2 v;
        v.x = pack_bf2(sg.x - __bfloat162float(h0), sg.y - __bfloat162float(h1));
        v.y = pack_bf2(sg.z - __bfloat162float(h2), sg.w - __bfloat162float(h3));
        reinterpret_cast<uint2*>(g_sg_lo)[o4] = v;
    }
}

// ---------------- zpre: interleaved dual MMA GEMM + GRU epilogue --------------
// BM=64, BN=128, BK=32; 256 threads = 8 warps (2 M x 4 N), warp tile 32x32.
// acc1 = sum_h @ Wzh, acc2 = sum_gated @ Whh computed in ONE k-loop.
#define A_STRIDE 40    // 32 + 8 pad (bf16 elements)
#define B_STRIDE 136   // 128 + 8 pad

#define ZP_A_SZ  (64 * A_STRIDE * 2)   // bytes per A stage buffer
#define ZP_B_SZ  (32 * B_STRIDE * 2)   // bytes per B stage buffer
#define ZP_SMEM  (4 * ZP_A_SZ + 4 * ZP_B_SZ)

__global__ void __launch_bounds__(256) zpre_mma(
    const float* __restrict__ bz, const float* __restrict__ bhb,
    const int*   __restrict__ xids, float* __restrict__ hout)
{
    extern __shared__ char dsm[];
    __nv_bfloat16* sA1hi = (__nv_bfloat16*)dsm;
    __nv_bfloat16* sA1lo = (__nv_bfloat16*)(dsm + 1 * ZP_A_SZ);
    __nv_bfloat16* sA2hi = (__nv_bfloat16*)(dsm + 2 * ZP_A_SZ);
    __nv_bfloat16* sA2lo = (__nv_bfloat16*)(dsm + 3 * ZP_A_SZ);
    __nv_bfloat16* sB1hi = (__nv_bfloat16*)(dsm + 4 * ZP_A_SZ);
    __nv_bfloat16* sB1lo = (__nv_bfloat16*)(dsm + 4 * ZP_A_SZ + 1 * ZP_B_SZ);
    __nv_bfloat16* sB2hi = (__nv_bfloat16*)(dsm + 4 * ZP_A_SZ + 2 * ZP_B_SZ);
    __nv_bfloat16* sB2lo = (__nv_bfloat16*)(dsm + 4 * ZP_A_SZ + 3 * ZP_B_SZ);

    const int tid  = threadIdx.x;
    const int lane = tid & 31;
    const int wid  = tid >> 5;
    const int warp_m = wid & 1;
    const int warp_n = wid >> 1;
    const int rowBase = blockIdx.y * 64;
    const int colBase = blockIdx.x * 128;

    const int arow = tid >> 2;            // 0..63
    const int ak   = (tid & 3) * 8;       // 0,8,16,24
    const int brow = tid >> 3;            // 0..31
    const int bcol = (tid & 7) * 8;       // 0..56

    const uint32_t bA1hi = smem_u32(sA1hi), bA1lo = smem_u32(sA1lo);
    const uint32_t bA2hi = smem_u32(sA2hi), bA2lo = smem_u32(sA2lo);
    const uint32_t bB1hi = smem_u32(sB1hi), bB1lo = smem_u32(sB1lo);
    const uint32_t bB2hi = smem_u32(sB2hi), bB2lo = smem_u32(sB2lo);

    float acc1[2][4][4] = {};
    float acc2[2][4][4] = {};

    for (int kb = 0; kb < 256; kb += 32) {
        __syncthreads();
        const size_t aoff = (size_t)(rowBase + arow) * 256 + kb + ak;
        *reinterpret_cast<uint4*>(&sA1hi[arow * A_STRIDE + ak]) =
            *reinterpret_cast<const uint4*>(&g_sh_hi[aoff]);
        *reinterpret_cast<uint4*>(&sA1lo[arow * A_STRIDE + ak]) =
            *reinterpret_cast<const uint4*>(&g_sh_lo[aoff]);
        *reinterpret_cast<uint4*>(&sA2hi[arow * A_STRIDE + ak]) =
            *reinterpret_cast<const uint4*>(&g_sg_hi[aoff]);
        *reinterpret_cast<uint4*>(&sA2lo[arow * A_STRIDE + ak]) =
            *reinterpret_cast<const uint4*>(&g_sg_lo[aoff]);
        const size_t boff0 = (size_t)(kb + brow) * 256 + colBase + bcol;
#pragma unroll
        for (int half = 0; half < 2; ++half) {
            const size_t boff = boff0 + half * 64;
            const int sidx = brow * B_STRIDE + bcol + half * 64;
            *reinterpret_cast<uint4*>(&sB1hi[sidx]) =
                *reinterpret_cast<const uint4*>(&g_Wzh_hi[boff]);
            *reinterpret_cast<uint4*>(&sB1lo[sidx]) =
                *reinterpret_cast<const uint4*>(&g_Wzh_lo[boff]);
            *reinterpret_cast<uint4*>(&sB2hi[sidx]) =
                *reinterpret_cast<const uint4*>(&g_Whh_hi[boff]);
            *reinterpret_cast<uint4*>(&sB2lo[sidx]) =
                *reinterpret_cast<const uint4*>(&g_Whh_lo[boff]);
        }
        __syncthreads();

#pragma unroll
        for (int ks = 0; ks < 32; ks += 16) {
            uint32_t a1h[2][4], a1l[2][4], a2h[2][4], a2l[2][4];
#pragma unroll
            for (int mt = 0; mt < 2; ++mt) {
                const int el = (warp_m * 32 + mt * 16 + (lane & 15)) * A_STRIDE
                             + ks + (lane >> 4) * 8;
                ldsm4(a1h[mt], bA1hi + el * 2);
                ldsm4(a1l[mt], bA1lo + el * 2);
                ldsm4(a2h[mt], bA2hi + el * 2);
                ldsm4(a2l[mt], bA2lo + el * 2);
            }
#pragma unroll
            for (int np = 0; np < 2; ++np) {
                const int n0 = warp_n * 32 + np * 16;
                const int el = (ks + (lane & 7) + ((lane >> 3) & 1) * 8) * B_STRIDE
                             + n0 + (lane >> 4) * 8;
                uint32_t b1h[4], b1l[4], b2h[4], b2l[4];
                ldsm4t(b1h, bB1hi + el * 2);
                ldsm4t(b1l, bB1lo + el * 2);
                ldsm4t(b2h, bB2hi + el * 2);
                ldsm4t(b2l, bB2lo + el * 2);
#pragma unroll
                for (int mt = 0; mt < 2; ++mt) {
#pragma unroll
                    for (int s = 0; s < 2; ++s) {
                        float* d1 = acc1[mt][np * 2 + s];
                        float* d2 = acc2[mt][np * 2 + s];
                        mma16816(d1, a1h[mt], &b1h[2 * s]);
                        mma16816(d2, a2h[mt], &b2h[2 * s]);
                        mma16816(d1, a1h[mt], &b1l[2 * s]);
                        mma16816(d2, a2h[mt], &b2l[2 * s]);
                        mma16816(d1, a1l[mt], &b1h[2 * s]);
                        mma16816(d2, a2l[mt], &b2h[2 * s]);
                    }
                }
            }
        }
    }

    // epilogue
#pragma unroll
    for (int mt = 0; mt < 2; ++mt) {
#pragma unroll
        for (int nt = 0; nt < 4; ++nt) {
            const int col = colBase + warp_n * 32 + nt * 8 + (lane & 3) * 2;
#pragma unroll
            for (int half = 0; half < 2; ++half) {
                const int r = blockIdx.y * 64 + warp_m * 32 + mt * 16 + (lane >> 2) + half * 8;
                const float a1x = acc1[mt][nt][half * 2 + 0];
                const float a1y = acc1[mt][nt][half * 2 + 1];
                const float a2x = acc2[mt][nt][half * 2 + 0];
                const float a2y = acc2[mt][nt][half * 2 + 1];
                const int xid = xids[r];
                const float2 ez  = *reinterpret_cast<const float2*>(&g_Ez[(size_t)xid * H_ + col]);
                const float2 eh  = *reinterpret_cast<const float2*>(&g_Eh[(size_t)xid * H_ + col]);
                const float2 bzv = *reinterpret_cast<const float2*>(&bz[col]);
                const float2 bhv = *reinterpret_cast<const float2*>(&bhb[col]);
                // reconstruct sum_h from bf16 hi+lo
                const uint32_t shh = *reinterpret_cast<const uint32_t*>(&g_sh_hi[(size_t)r * H_ + col]);
                const uint32_t shl = *reinterpret_cast<const uint32_t*>(&g_sh_lo[(size_t)r * H_ + col]);
                const float2 sh_h = unpack_bf2(shh);
                const float2 sh_l = unpack_bf2(shl);
                const float sh0 = sh_h.x + sh_l.x;
                const float sh1 = sh_h.y + sh_l.y;
                const float z0 = sigf(ez.x + bzv.x + a1x);
                const float z1 = sigf(ez.y + bzv.y + a1y);
                const float p0 = tanhf(eh.x + bhv.x + a2x);
                const float p1 = tanhf(eh.y + bhv.y + a2y);
                const float o0 = (1.0f - z0) * sh0 + z0 * p0;
                const float o1 = (1.0f - z1) * sh1 + z1 * p1;
                *reinterpret_cast<float2*>(&hout[(size_t)r * H_ + col]) = make_float2(o0, o1);
                __nv_bfloat162 hp; hp.x = __float2bfloat16(o0); hp.y = __float2bfloat16(o1);
                *reinterpret_cast<__nv_bfloat162*>(&g_hA_hi[(size_t)r * H_ + col]) = hp;
                __nv_bfloat162 lp;
                lp.x = __float2bfloat16(o0 - __bfloat162float(hp.x));
                lp.y = __float2bfloat16(o1 - __bfloat162float(hp.y));
                *reinterpret_cast<__nv_bfloat162*>(&g_hA_lo[(size_t)r * H_ + col]) = lp;
            }
        }
    }
}

// ---------------- Ur MMA GEMM: g_hU rows = new_h @ Ur -------------------------
__global__ void __launch_bounds__(256) gemmUr_mma(float* __restrict__ C)
{
    __shared__ __nv_bfloat16 sAhi[64 * A_STRIDE], sAlo[64 * A_STRIDE];
    __shared__ __nv_bfloat16 sBhi[32 * B_STRIDE], sBlo[32 * B_STRIDE];

    const int tid  = threadIdx.x;
    const int lane = tid & 31;
    const int wid  = tid >> 5;
    const int warp_m = wid & 1;
    const int warp_n = wid >> 1;
    const int rowBase = blockIdx.y * 64;
    const int colBase = blockIdx.x * 128;

    const int arow = tid >> 2;
    const int ak   = (tid & 3) * 8;
    const int brow = tid >> 3;
    const int bcol = (tid & 7) * 8;

    const uint32_t bAhi = smem_u32(sAhi), bAlo = smem_u32(sAlo);
    const uint32_t bBhi = smem_u32(sBhi), bBlo = smem_u32(sBlo);

    float acc[2][4][4] = {};

    for (int kb = 0; kb < 256; kb += 32) {
        __syncthreads();
        const size_t aoff = (size_t)(rowBase + arow) * 256 + kb + ak;
        *reinterpret_cast<uint4*>(&sAhi[arow * A_STRIDE + ak]) =
            *reinterpret_cast<const uint4*>(&g_hA_hi[aoff]);
        *reinterpret_cast<uint4*>(&sAlo[arow * A_STRIDE + ak]) =
            *reinterpret_cast<const uint4*>(&g_hA_lo[aoff]);
        const size_t boff0 = (size_t)(kb + brow) * 256 + colBase + bcol;
#pragma unroll
        for (int half = 0; half < 2; ++half) {
            const size_t boff = boff0 + half * 64;
            const int sidx = brow * B_STRIDE + bcol + half * 64;
            *reinterpret_cast<uint4*>(&sBhi[sidx]) =
                *reinterpret_cast<const uint4*>(&g_Ur_hi[boff]);
            *reinterpret_cast<uint4*>(&sBlo[sidx]) =
                *reinterpret_cast<const uint4*>(&g_Ur_lo[boff]);
        }
        __syncthreads();

#pragma unroll
        for (int ks = 0; ks < 32; ks += 16) {
            uint32_t ahi[2][4], alo[2][4];
#pragma unroll
            for (int mt = 0; mt < 2; ++mt) {
                const int el = (warp_m * 32 + mt * 16 + (lane & 15)) * A_STRIDE
                             + ks + (lane >> 4) * 8;
                ldsm4(ahi[mt], bAhi + el * 2);
                ldsm4(alo[mt], bAlo + el * 2);
            }
#pragma unroll
            for (int np = 0; np < 2; ++np) {
                const int n0 = warp_n * 32 + np * 16;
                const int el = (ks + (lane & 7) + ((lane >> 3) & 1) * 8) * B_STRIDE
                             + n0 + (lane >> 4) * 8;
                uint32_t bh_[4], bl_[4];
                ldsm4t(bh_, bBhi + el * 2);
                ldsm4t(bl_, bBlo + el * 2);
#pragma unroll
                for (int mt = 0; mt < 2; ++mt) {
#pragma unroll
                    for (int s = 0; s < 2; ++s) {
                        float* d = acc[mt][np * 2 + s];
                        mma16816(d, ahi[mt], &bh_[2 * s]);
                        mma16816(d, ahi[mt], &bl_[2 * s]);
                        mma16816(d, alo[mt], &bh_[2 * s]);
                    }
                }
            }
        }
    }

#pragma unroll
    for (int mt = 0; mt < 2; ++mt) {
#pragma unroll
        for (int nt = 0; nt < 4; ++nt) {
            const int col = colBase + warp_n * 32 + nt * 8 + (lane & 3) * 2;
            const int r0  = rowBase + warp_m * 32 + mt * 16 + (lane >> 2);
            *reinterpret_cast<float2*>(&C[(size_t)r0 * H_ + col]) =
                make_float2(acc[mt][nt][0], acc[mt][nt][1]);
            *reinterpret_cast<float2*>(&C[(size_t)(r0 + 8) * H_ + col]) =
                make_float2(acc[mt][nt][2], acc[mt][nt][3]);
        }
    }
}

// ---------------- fused root aggregate ----------------------------------------
__global__ void root_fused(const float* __restrict__ h, const int* __restrict__ rnei,
                           const int* __restrict__ rwid, const float* __restrict__ Woh,
                           const float* __restrict__ bo, float* __restrict__ out)
{
    __shared__ float s_sum[256];
    __shared__ int sj[NB_];
    const int b = blockIdx.x;
    const int c = threadIdx.x;
    if (c < NB_) sj[c] = rnei[b * NB_ + c];
    __syncthreads();
    float s = 0.f;
#pragma unroll
    for (int n = 0; n < NB_; ++n)
        s += h[(size_t)sj[n] * 256 + c];
    s_sum[c] = s;
    __syncthreads();
    float acc = 0.f;
#pragma unroll 8
    for (int k = 0; k < 256; ++k)
        acc += s_sum[k] * Woh[(size_t)k * 256 + c];
    const int xid = rwid[b];
    float v = g_Eo[(size_t)xid * 256 + c] + bo[c] + acc;
    out[(size_t)b * 256 + c] = fmaxf(v, 0.0f);
}

// ---------------- launch ------------------------------------------------------
extern "C" void kernel_launch(void* const* d_in, const int* in_sizes, int n_in,
                              void* d_out, int out_size)
{
    const int*   x_ids    = (const int*)  d_in[0];
    const int*   nei_idx  = (const int*)  d_in[1];
    const int*   root_wid = (const int*)  d_in[2];
    const int*   root_nei = (const int*)  d_in[3];
    const float* emb      = (const float*)d_in[4];
    const float* Wz       = (const float*)d_in[5];
    const float* bz       = (const float*)d_in[6];
    const float* Wr       = (const float*)d_in[7];
    const float* Ur       = (const float*)d_in[8];
    const float* bur      = (const float*)d_in[9];
    const float* Wh       = (const float*)d_in[10];
    const float* bh       = (const float*)d_in[11];
    const float* Wo       = (const float*)d_in[12];
    const float* bo       = (const float*)d_in[13];

    float* out  = (float*)d_out;
    float* h    = out;
    float* rvec = out + (size_t)(M_ + 1) * H_;

    float* p_hU;
    cudaGetSymbolAddress((void**)&p_hU, g_hU);

    cudaFuncSetAttribute(zpre_mma, cudaFuncAttributeMaxDynamicSharedMemorySize, ZP_SMEM);

    init_zero<<<1, 256>>>(h);

    dim3 gpre(4, (V_ + 63) / 64, 4);
    gemm_pre<<<gpre, 256>>>(emb, Wz, Wr, Wh, Wo);
    split3<<<dim3(256, 3), 256>>>(Wz, Wh, Ur);

    dim3 gmma(2, E_ / 64);   // (N/128, M/64)
    for (int t = 0; t < T_; ++t) {
        gather_step<<<E_ / 4, 256>>>(h, nei_idx + (size_t)t * E_ * NB_,
                                     x_ids + (size_t)t * E_, bur);
        zpre_mma<<<gmma, 256, ZP_SMEM>>>(bz, bh, x_ids + (size_t)t * E_,
                                         h + (size_t)(1 + t * E_) * H_);
        gemmUr_mma<<<gmma, 256>>>(p_hU + (size_t)(1 + t * E_) * H_);
    }

    root_fused<<<B_, 256>>>(h, root_nei, root_wid, Wo + (size_t)H_ * H_, bo, rvec);
}

// round 5
// speedup vs baseline: 1.3980x; 1.1966x over previous
#include <cuda_runtime.h>
#include <cuda_bf16.h>
#include <math.h>
#include <stdint.h>

#define T_  12
#define E_  8192
#define H_  256
#define V_  800
#define B_  256
#define NB_ 8
#define M_  (T_*E_)   // 98304 messages; h has 1+M rows (row 0 = pad)

// ---------------- scratch (static device arrays; no allocs allowed) ----------
__device__ float g_hU[(size_t)(M_+1)*H_];   // h @ Ur (fp32), incrementally extended
__device__ float g_Ez[(size_t)V_*H_];
__device__ float g_Er[(size_t)V_*H_];
__device__ float g_Eh[(size_t)V_*H_];
__device__ float g_Eo[(size_t)V_*H_];

// bf16 hi/lo split operands for MMA GEMMs
__device__ __nv_bfloat16 g_sh_hi[(size_t)E_*H_], g_sh_lo[(size_t)E_*H_];
__device__ __nv_bfloat16 g_sg_hi[(size_t)E_*H_], g_sg_lo[(size_t)E_*H_];
__device__ __nv_bfloat16 g_hA_hi[(size_t)E_*H_], g_hA_lo[(size_t)E_*H_];
__device__ __nv_bfloat16 g_Wzh_hi[H_*H_], g_Wzh_lo[H_*H_];
__device__ __nv_bfloat16 g_Whh_hi[H_*H_], g_Whh_lo[H_*H_];
__device__ __nv_bfloat16 g_Ur_hi [H_*H_], g_Ur_lo [H_*H_];

__device__ __forceinline__ float sigf(float x) { return 1.0f / (1.0f + __expf(-x)); }

// ---------------- PTX helpers -------------------------------------------------
__device__ __forceinline__ uint32_t smem_u32(const void* p) {
    return (uint32_t)__cvta_generic_to_shared(p);
}
__device__ __forceinline__ void ldsm4(uint32_t* r, uint32_t a) {
    asm volatile("ldmatrix.sync.aligned.m8n8.x4.shared.b16 {%0,%1,%2,%3},[%4];\n"
                 : "=r"(r[0]), "=r"(r[1]), "=r"(r[2]), "=r"(r[3]) : "r"(a));
}
__device__ __forceinline__ void ldsm4t(uint32_t* r, uint32_t a) {
    asm volatile("ldmatrix.sync.aligned.m8n8.x4.trans.shared.b16 {%0,%1,%2,%3},[%4];\n"
                 : "=r"(r[0]), "=r"(r[1]), "=r"(r[2]), "=r"(r[3]) : "r"(a));
}
__device__ __forceinline__ void mma16816(float* d, const uint32_t* a, const uint32_t* b) {
    asm volatile("mma.sync.aligned.m16n8k16.row.col.f32.bf16.bf16.f32 "
                 "{%0,%1,%2,%3},{%4,%5,%6,%7},{%8,%9},{%0,%1,%2,%3};\n"
                 : "+f"(d[0]), "+f"(d[1]), "+f"(d[2]), "+f"(d[3])
                 : "r"(a[0]), "r"(a[1]), "r"(a[2]), "r"(a[3]), "r"(b[0]), "r"(b[1]));
}
__device__ __forceinline__ void cpa16(uint32_t dst, const void* src) {
    asm volatile("cp.async.cg.shared.global [%0],[%1],16;\n" :: "r"(dst), "l"(src));
}
#define CP_COMMIT()  asm volatile("cp.async.commit_group;\n" ::: "memory")
#define CP_WAIT1()   asm volatile("cp.async.wait_group 1;\n" ::: "memory")

__device__ __forceinline__ uint32_t pack_bf2(float a, float b) {
    __nv_bfloat162 t; t.x = __float2bfloat16(a); t.y = __float2bfloat16(b);
    return *reinterpret_cast<uint32_t*>(&t);
}
__device__ __forceinline__ float2 unpack_bf2(uint32_t u) {
    __nv_bfloat162 t = *reinterpret_cast<__nv_bfloat162*>(&u);
    return make_float2(__bfloat162float(t.x), __bfloat162float(t.y));
}

// ---------------- init --------------------------------------------------------
__global__ void init_zero(float* __restrict__ h)
{
    int c = threadIdx.x;
    h[c]    = 0.0f;
    g_hU[c] = 0.0f;
}

// ---------------- preamble: 4 embedding projections in one launch -------------
__global__ void gemm_pre(const float* __restrict__ emb,
                         const float* __restrict__ Wz, const float* __restrict__ Wr,
                         const float* __restrict__ Wh, const float* __restrict__ Wo)
{
    const float* Bw; float* C;
    switch (blockIdx.z) {
        case 0:  Bw = Wz; C = g_Ez; break;
        case 1:  Bw = Wr; C = g_Er; break;
        case 2:  Bw = Wh; C = g_Eh; break;
        default: Bw = Wo; C = g_Eo; break;
    }
    __shared__ float As[16][64];
    __shared__ float Bs[16][64];
    const int tid = threadIdx.x;
    const int tx = tid & 15, ty = tid >> 4;
    const int rowBase = blockIdx.y * 64;
    const int colBase = blockIdx.x * 64;
    const int lm  = tid >> 2;
    const int lk  = (tid & 3) * 4;
    const int blk = tid >> 4;
    const int bln = (tid & 15) * 4;
    float acc[4][4] = {};
    for (int kb = 0; kb < 256; kb += 16) {
        int ar = rowBase + lm;
        float4 av = make_float4(0.f, 0.f, 0.f, 0.f);
        if (ar < V_)
            av = *reinterpret_cast<const float4*>(&emb[(size_t)ar * 256 + kb + lk]);
        As[lk + 0][lm] = av.x; As[lk + 1][lm] = av.y;
        As[lk + 2][lm] = av.z; As[lk + 3][lm] = av.w;
        float4 bv = *reinterpret_cast<const float4*>(&Bw[(size_t)(kb + blk) * 256 + colBase + bln]);
        *reinterpret_cast<float4*>(&Bs[blk][bln]) = bv;
        __syncthreads();
#pragma unroll
        for (int k = 0; k < 16; ++k) {
            float4 a4 = *reinterpret_cast<const float4*>(&As[k][ty * 4]);
            float4 b4 = *reinterpret_cast<const float4*>(&Bs[k][tx * 4]);
            float aa[4] = {a4.x, a4.y, a4.z, a4.w};
            float bb[4] = {b4.x, b4.y, b4.z, b4.w};
#pragma unroll
            for (int i = 0; i < 4; ++i)
#pragma unroll
                for (int j = 0; j < 4; ++j)
                    acc[i][j] += aa[i] * bb[j];
        }
        __syncthreads();
    }
#pragma unroll
    for (int i = 0; i < 4; ++i) {
        int r = rowBase + ty * 4 + i;
        if (r < V_)
            *reinterpret_cast<float4*>(&C[(size_t)r * 256 + colBase + tx * 4]) =
                make_float4(acc[i][0], acc[i][1], acc[i][2], acc[i][3]);
    }
}

// ---------------- preamble: 3 weight splits in one launch ---------------------
__global__ void split3(const float* __restrict__ Wz, const float* __restrict__ Wh,
                       const float* __restrict__ Ur)
{
    const float* W; __nv_bfloat16 *hi, *lo;
    switch (blockIdx.y) {
        case 0:  W = Wz + H_ * H_; hi = g_Wzh_hi; lo = g_Wzh_lo; break;
        case 1:  W = Wh + H_ * H_; hi = g_Whh_hi; lo = g_Whh_lo; break;
        default: W = Ur;           hi = g_Ur_hi;  lo = g_Ur_lo;  break;
    }
    int i = blockIdx.x * 256 + threadIdx.x;
    float v = W[i];
    __nv_bfloat16 h = __float2bfloat16(v);
    hi[i] = h;
    lo[i] = __float2bfloat16(v - __bfloat162float(h));
}

// ---------------- per-step gather: sum_h / sum_gated -> bf16 hi/lo ------------
__global__ void gather_step(const float* __restrict__ h,
                            const int*   __restrict__ nei,
                            const int*   __restrict__ xids,
                            const float* __restrict__ bur)
{
    const int msg = blockIdx.x * 4 + (threadIdx.x >> 6);
    const int c4  = threadIdx.x & 63;          // float4 chunk within H

    const int xid = xids[msg];
    const float4 bu = reinterpret_cast<const float4*>(bur)[c4];
    const float4 er = reinterpret_cast<const float4*>(&g_Er[(size_t)xid * H_])[c4];
    const float bx = er.x + bu.x, by = er.y + bu.y, bz2 = er.z + bu.z, bw = er.w + bu.w;

    float4 sh = make_float4(0.f, 0.f, 0.f, 0.f);
    float4 sg = make_float4(0.f, 0.f, 0.f, 0.f);
#pragma unroll
    for (int n = 0; n < NB_; ++n) {
        const int j = nei[msg * NB_ + n];
        const float4 hv = reinterpret_cast<const float4*>(h)[(size_t)j * 64 + c4];
        const float4 uv = reinterpret_cast<const float4*>(g_hU)[(size_t)j * 64 + c4];
        sh.x += hv.x; sh.y += hv.y; sh.z += hv.z; sh.w += hv.w;
        sg.x += sigf(bx  + uv.x) * hv.x;
        sg.y += sigf(by  + uv.y) * hv.y;
        sg.z += sigf(bz2 + uv.z) * hv.z;
        sg.w += sigf(bw  + uv.w) * hv.w;
    }
    const size_t o4 = (size_t)msg * 64 + c4;
    {
        __nv_bfloat16 h0 = __float2bfloat16(sh.x), h1 = __float2bfloat16(sh.y),
                      h2 = __float2bfloat16(sh.z), h3 = __float2bfloat16(sh.w);
        uint2 u;
        { __nv_bfloat162 a; a.x = h0; a.y = h1; u.x = *reinterpret_cast<uint32_t*>(&a); }
        { __nv_bfloat162 a; a.x = h2; a.y = h3; u.y = *reinterpret_cast<uint32_t*>(&a); }
        reinterpret_cast<uint2*>(g_sh_hi)[o4] = u;
        uint2 v;
        v.x = pack_bf2(sh.x - __bfloat162float(h0), sh.y - __bfloat162float(h1));
        v.y = pack_bf2(sh.z - __bfloat162float(h2), sh.w - __bfloat162float(h3));
        reinterpret_cast<uint2*>(g_sh_lo)[o4] = v;
    }
    {
        __nv_bfloat16 h0 = __float2bfloat16(sg.x), h1 = __float2bfloat16(sg.y),
                      h2 = __float2bfloat16(sg.z), h3 = __float2bfloat16(sg.w);
        uint2 u;
        { __nv_bfloat162 a; a.x = h0; a.y = h1; u.x = *reinterpret_cast<uint32_t*>(&a); }
        { __nv_bfloat162 a; a.x = h2; a.y = h3; u.y = *reinterpret_cast<uint32_t*>(&a); }
        reinterpret_cast<uint2*>(g_sg_hi)[o4] = u;
        uint2 v;
        v.x = pack_bf2(sg.x - __bfloat162float(h0), sg.y - __bfloat162float(h1));
        v.y = pack_bf2(sg.z - __bfloat162float(h2), sg.w - __bfloat162float(h3));
        reinterpret_cast<uint2*>(g_sg_lo)[o4] = v;
    }
}

// ---------------- cp.async double-buffered 3-term MMA GEMM pass ---------------
// BM=64, BN=128, BK=32; 256 threads = 8 warps (2 M x 4 N), warp tile 32x32.
#define A_STRIDE 40    // 32 + 8 pad (bf16 elements)
#define B_STRIDE 136   // 128 + 8 pad

#define STG_A_HI 0
#define STG_A_LO 5120
#define STG_B_HI 10240
#define STG_B_LO 18944
#define STG_SZ   27648
#define GM_SMEM  (2 * STG_SZ)      // 55296 bytes dynamic

__device__ __forceinline__ void gemm_pass_ca(
    const __nv_bfloat16* __restrict__ Ahi, const __nv_bfloat16* __restrict__ Alo,
    const __nv_bfloat16* __restrict__ Bhi, const __nv_bfloat16* __restrict__ Blo,
    int rowBase, int colBase, float acc[2][4][4], uint32_t sbase)
{
    const int tid  = threadIdx.x;
    const int lane = tid & 31;
    const int wid  = tid >> 5;
    const int warp_m = wid & 1;
    const int warp_n = wid >> 1;

    const int arow = tid >> 2;            // 0..63
    const int ak   = (tid & 3) * 8;       // 0,8,16,24
    const int brow = tid >> 3;            // 0..31
    const int bcol = (tid & 7) * 8;       // 0..56

    const uint32_t aoffA = (uint32_t)(arow * A_STRIDE + ak) * 2;
    const uint32_t boffB0 = (uint32_t)(brow * B_STRIDE + bcol) * 2;
    const uint32_t boffB1 = (uint32_t)(brow * B_STRIDE + bcol + 64) * 2;
    const size_t agrow = (size_t)(rowBase + arow) * 256 + ak;
    const size_t bgrow = (size_t)brow * 256 + colBase + bcol;

    // prologue: tile 0 into stage 0
    cpa16(sbase + STG_A_HI + aoffA, &Ahi[agrow]);
    cpa16(sbase + STG_A_LO + aoffA, &Alo[agrow]);
    cpa16(sbase + STG_B_HI + boffB0, &Bhi[bgrow]);
    cpa16(sbase + STG_B_HI + boffB1, &Bhi[bgrow + 64]);
    cpa16(sbase + STG_B_LO + boffB0, &Blo[bgrow]);
    cpa16(sbase + STG_B_LO + boffB1, &Blo[bgrow + 64]);
    CP_COMMIT();

    for (int it = 0; it < 8; ++it) {
        const uint32_t scur = sbase + (uint32_t)(it & 1) * STG_SZ;
        __syncthreads();     // all reads of the stage we're about to overwrite are done
        if (it < 7) {
            const uint32_t snxt = sbase + (uint32_t)((it + 1) & 1) * STG_SZ;
            const int kb = (it + 1) * 32;
            cpa16(snxt + STG_A_HI + aoffA, &Ahi[agrow + kb]);
            cpa16(snxt + STG_A_LO + aoffA, &Alo[agrow + kb]);
            cpa16(snxt + STG_B_HI + boffB0, &Bhi[bgrow + (size_t)kb * 256]);
            cpa16(snxt + STG_B_HI + boffB1, &Bhi[bgrow + (size_t)kb * 256 + 64]);
            cpa16(snxt + STG_B_LO + boffB0, &Blo[bgrow + (size_t)kb * 256]);
            cpa16(snxt + STG_B_LO + boffB1, &Blo[bgrow + (size_t)kb * 256 + 64]);
        }
        CP_COMMIT();
        CP_WAIT1();          // current tile's group complete
        __syncthreads();

#pragma unroll
        for (int ks = 0; ks < 32; ks += 16) {
            uint32_t ahi[2][4], alo[2][4];
#pragma unroll
            for (int mt = 0; mt < 2; ++mt) {
                const int el = (warp_m * 32 + mt * 16 + (lane & 15)) * A_STRIDE
                             + ks + (lane >> 4) * 8;
                ldsm4(ahi[mt], scur + STG_A_HI + el * 2);
                ldsm4(alo[mt], scur + STG_A_LO + el * 2);
            }
#pragma unroll
            for (int np = 0; np < 2; ++np) {
                const int n0 = warp_n * 32 + np * 16;
                const int el = (ks + (lane & 7) + ((lane >> 3) & 1) * 8) * B_STRIDE
                             + n0 + (lane >> 4) * 8;
                uint32_t bh_[4], bl_[4];
                ldsm4t(bh_, scur + STG_B_HI + el * 2);
                ldsm4t(bl_, scur + STG_B_LO + el * 2);
#pragma unroll
                for (int mt = 0; mt < 2; ++mt) {
#pragma unroll
                    for (int s = 0; s < 2; ++s) {
                        float* d = acc[mt][np * 2 + s];
                        mma16816(d, ahi[mt], &bh_[2 * s]);
                        mma16816(d, ahi[mt], &bl_[2 * s]);
                        mma16816(d, alo[mt], &bh_[2 * s]);
                    }
                }
            }
        }
    }
}

// ---------------- zpre: dual MMA GEMM (two pipelined passes) + GRU epilogue ---
__global__ void __launch_bounds__(256) zpre_mma(
    const float* __restrict__ bz, const float* __restrict__ bhb,
    const int*   __restrict__ xids, float* __restrict__ hout)
{
    extern __shared__ char dsm[];
    const uint32_t sbase = smem_u32(dsm);

    const int rowBase = blockIdx.y * 64;
    const int colBase = blockIdx.x * 128;

    float acc1[2][4][4] = {};
    float acc2[2][4][4] = {};
    gemm_pass_ca(g_sh_hi, g_sh_lo, g_Wzh_hi, g_Wzh_lo, rowBase, colBase, acc1, sbase);
    gemm_pass_ca(g_sg_hi, g_sg_lo, g_Whh_hi, g_Whh_lo, rowBase, colBase, acc2, sbase);

    const int lane = threadIdx.x & 31;
    const int wid  = threadIdx.x >> 5;
    const int warp_m = wid & 1, warp_n = wid >> 1;

#pragma unroll
    for (int mt = 0; mt < 2; ++mt) {
#pragma unroll
        for (int nt = 0; nt < 4; ++nt) {
            const int col = colBase + warp_n * 32 + nt * 8 + (lane & 3) * 2;
#pragma unroll
            for (int half = 0; half < 2; ++half) {
                const int r = rowBase + warp_m * 32 + mt * 16 + (lane >> 2) + half * 8;
                const float a1x = acc1[mt][nt][half * 2 + 0];
                const float a1y = acc1[mt][nt][half * 2 + 1];
                const float a2x = acc2[mt][nt][half * 2 + 0];
                const float a2y = acc2[mt][nt][half * 2 + 1];
                const int xid = xids[r];
                const float2 ez  = *reinterpret_cast<const float2*>(&g_Ez[(size_t)xid * H_ + col]);
                const float2 eh  = *reinterpret_cast<const float2*>(&g_Eh[(size_t)xid * H_ + col]);
                const float2 bzv = *reinterpret_cast<const float2*>(&bz[col]);
                const float2 bhv = *reinterpret_cast<const float2*>(&bhb[col]);
                const uint32_t shh = *reinterpret_cast<const uint32_t*>(&g_sh_hi[(size_t)r * H_ + col]);
                const uint32_t shl = *reinterpret_cast<const uint32_t*>(&g_sh_lo[(size_t)r * H_ + col]);
                const float2 sh_h = unpack_bf2(shh);
                const float2 sh_l = unpack_bf2(shl);
                const float sh0 = sh_h.x + sh_l.x;
                const float sh1 = sh_h.y + sh_l.y;
                const float z0 = sigf(ez.x + bzv.x + a1x);
                const float z1 = sigf(ez.y + bzv.y + a1y);
                const float p0 = tanhf(eh.x + bhv.x + a2x);
                const float p1 = tanhf(eh.y + bhv.y + a2y);
                const float o0 = (1.0f - z0) * sh0 + z0 * p0;
                const float o1 = (1.0f - z1) * sh1 + z1 * p1;
                *reinterpret_cast<float2*>(&hout[(size_t)r * H_ + col]) = make_float2(o0, o1);
                __nv_bfloat162 hp; hp.x = __float2bfloat16(o0); hp.y = __float2bfloat16(o1);
                *reinterpret_cast<__nv_bfloat162*>(&g_hA_hi[(size_t)r * H_ + col]) = hp;
                __nv_bfloat162 lp;
                lp.x = __float2bfloat16(o0 - __bfloat162float(hp.x));
                lp.y = __float2bfloat16(o1 - __bfloat162float(hp.y));
                *reinterpret_cast<__nv_bfloat162*>(&g_hA_lo[(size_t)r * H_ + col]) = lp;
            }
        }
    }
}

// ---------------- Ur MMA GEMM: g_hU rows = new_h @ Ur -------------------------
__global__ void __launch_bounds__(256) gemmUr_mma(float* __restrict__ C)
{
    extern __shared__ char dsm[];
    const uint32_t sbase = smem_u32(dsm);

    const int rowBase = blockIdx.y * 64;
    const int colBase = blockIdx.x * 128;

    float acc[2][4][4] = {};
    gemm_pass_ca(g_hA_hi, g_hA_lo, g_Ur_hi, g_Ur_lo, rowBase, colBase, acc, sbase);

    const int lane = threadIdx.x & 31;
    const int wid  = threadIdx.x >> 5;
    const int warp_m = wid & 1, warp_n = wid >> 1;

#pragma unroll
    for (int mt = 0; mt < 2; ++mt) {
#pragma unroll
        for (int nt = 0; nt < 4; ++nt) {
            const int col = colBase + warp_n * 32 + nt * 8 + (lane & 3) * 2;
            const int r0  = rowBase + warp_m * 32 + mt * 16 + (lane >> 2);
            *reinterpret_cast<float2*>(&C[(size_t)r0 * H_ + col]) =
                make_float2(acc[mt][nt][0], acc[mt][nt][1]);
            *reinterpret_cast<float2*>(&C[(size_t)(r0 + 8) * H_ + col]) =
                make_float2(acc[mt][nt][2], acc[mt][nt][3]);
        }
    }
}

// ---------------- fused root aggregate ----------------------------------------
__global__ void root_fused(const float* __restrict__ h, const int* __restrict__ rnei,
                           const int* __restrict__ rwid, const float* __restrict__ Woh,
                           const float* __restrict__ bo, float* __restrict__ out)
{
    __shared__ float s_sum[256];
    __shared__ int sj[NB_];
    const int b = blockIdx.x;
    const int c = threadIdx.x;
    if (c < NB_) sj[c] = rnei[b * NB_ + c];
    __syncthreads();
    float s = 0.f;
#pragma unroll
    for (int n = 0; n < NB_; ++n)
        s += h[(size_t)sj[n] * 256 + c];
    s_sum[c] = s;
    __syncthreads();
    float acc = 0.f;
#pragma unroll 8
    for (int k = 0; k < 256; ++k)
        acc += s_sum[k] * Woh[(size_t)k * 256 + c];
    const int xid = rwid[b];
    float v = g_Eo[(size_t)xid * 256 + c] + bo[c] + acc;
    out[(size_t)b * 256 + c] = fmaxf(v, 0.0f);
}

// ---------------- launch ------------------------------------------------------
extern "C" void kernel_launch(void* const* d_in, const int* in_sizes, int n_in,
                              void* d_out, int out_size)
{
    const int*   x_ids    = (const int*)  d_in[0];
    const int*   nei_idx  = (const int*)  d_in[1];
    const int*   root_wid = (const int*)  d_in[2];
    const int*   root_nei = (const int*)  d_in[3];
    const float* emb      = (const float*)d_in[4];
    const float* Wz       = (const float*)d_in[5];
    const float* bz       = (const float*)d_in[6];
    const float* Wr       = (const float*)d_in[7];
    const float* Ur       = (const float*)d_in[8];
    const float* bur      = (const float*)d_in[9];
    const float* Wh       = (const float*)d_in[10];
    const float* bh       = (const float*)d_in[11];
    const float* Wo       = (const float*)d_in[12];
    const float* bo       = (const float*)d_in[13];

    float* out  = (float*)d_out;
    float* h    = out;
    float* rvec = out + (size_t)(M_ + 1) * H_;

    float* p_hU;
    cudaGetSymbolAddress((void**)&p_hU, g_hU);

    cudaFuncSetAttribute(zpre_mma,   cudaFuncAttributeMaxDynamicSharedMemorySize, GM_SMEM);
    cudaFuncSetAttribute(gemmUr_mma, cudaFuncAttributeMaxDynamicSharedMemorySize, GM_SMEM);

    init_zero<<<1, 256>>>(h);

    dim3 gpre(4, (V_ + 63) / 64, 4);
    gemm_pre<<<gpre, 256>>>(emb, Wz, Wr, Wh, Wo);
    split3<<<dim3(256, 3), 256>>>(Wz, Wh, Ur);

    dim3 gmma(2, E_ / 64);   // (N/128, M/64)
    for (int t = 0; t < T_; ++t) {
        gather_step<<<E_ / 4, 256>>>(h, nei_idx + (size_t)t * E_ * NB_,
                                     x_ids + (size_t)t * E_, bur);
        zpre_mma<<<gmma, 256, GM_SMEM>>>(bz, bh, x_ids + (size_t)t * E_,
                                         h + (size_t)(1 + t * E_) * H_);
        gemmUr_mma<<<gmma, 256, GM_SMEM>>>(p_hU + (size_t)(1 + t * E_) * H_);
    }

    root_fused<<<B_, 256>>>(h, root_nei, root_wid, Wo + (size_t)H_ * H_, bo, rvec);
}

// round 6
// speedup vs baseline: 1.5313x; 1.0954x over previous
#include <cuda_runtime.h>
#include <cuda_bf16.h>
#include <math.h>
#include <stdint.h>

#define T_  12
#define E_  8192
#define H_  256
#define V_  800
#define B_  256
#define NB_ 8
#define M_  (T_*E_)   // 98304 messages; h has 1+M rows (row 0 = pad)

// ---------------- scratch (static device arrays; no allocs allowed) ----------
__device__ float g_hU[(size_t)(M_+1)*H_];
__device__ float g_Ez[(size_t)V_*H_];
__device__ float g_Er[(size_t)V_*H_];
__device__ float g_Eh[(size_t)V_*H_];
__device__ float g_Eo[(size_t)V_*H_];

__device__ __nv_bfloat16 g_sh_hi[(size_t)E_*H_], g_sh_lo[(size_t)E_*H_];
__device__ __nv_bfloat16 g_sg_hi[(size_t)E_*H_], g_sg_lo[(size_t)E_*H_];
__device__ __nv_bfloat16 g_Wzh_hi[H_*H_], g_Wzh_lo[H_*H_];
__device__ __nv_bfloat16 g_Whh_hi[H_*H_], g_Whh_lo[H_*H_];
__device__ __nv_bfloat16 g_Ur_hi [H_*H_], g_Ur_lo [H_*H_];

__device__ __forceinline__ float sigf(float x) { return 1.0f / (1.0f + __expf(-x)); }

// ---------------- PTX helpers -------------------------------------------------
__device__ __forceinline__ uint32_t smem_u32(const void* p) {
    return (uint32_t)__cvta_generic_to_shared(p);
}
__device__ __forceinline__ void ldsm4(uint32_t* r, uint32_t a) {
    asm volatile("ldmatrix.sync.aligned.m8n8.x4.shared.b16 {%0,%1,%2,%3},[%4];\n"
                 : "=r"(r[0]), "=r"(r[1]), "=r"(r[2]), "=r"(r[3]) : "r"(a));
}
__device__ __forceinline__ void ldsm4t(uint32_t* r, uint32_t a) {
    asm volatile("ldmatrix.sync.aligned.m8n8.x4.trans.shared.b16 {%0,%1,%2,%3},[%4];\n"
                 : "=r"(r[0]), "=r"(r[1]), "=r"(r[2]), "=r"(r[3]) : "r"(a));
}
__device__ __forceinline__ void mma16816(float* d, const uint32_t* a, const uint32_t* b) {
    asm volatile("mma.sync.aligned.m16n8k16.row.col.f32.bf16.bf16.f32 "
                 "{%0,%1,%2,%3},{%4,%5,%6,%7},{%8,%9},{%0,%1,%2,%3};\n"
                 : "+f"(d[0]), "+f"(d[1]), "+f"(d[2]), "+f"(d[3])
                 : "r"(a[0]), "r"(a[1]), "r"(a[2]), "r"(a[3]), "r"(b[0]), "r"(b[1]));
}
__device__ __forceinline__ void cpa16(uint32_t dst, const void* src) {
    asm volatile("cp.async.cg.shared.global [%0],[%1],16;\n" :: "r"(dst), "l"(src));
}
#define CP_COMMIT()  asm volatile("cp.async.commit_group;\n" ::: "memory")
#define CP_WAIT1()   asm volatile("cp.async.wait_group 1;\n" ::: "memory")

__device__ __forceinline__ uint32_t pack_bf2(float a, float b) {
    __nv_bfloat162 t; t.x = __float2bfloat16(a); t.y = __float2bfloat16(b);
    return *reinterpret_cast<uint32_t*>(&t);
}
__device__ __forceinline__ float2 unpack_bf2(uint32_t u) {
    __nv_bfloat162 t = *reinterpret_cast<__nv_bfloat162*>(&u);
    return make_float2(__bfloat162float(t.x), __bfloat162float(t.y));
}

// ---------------- init --------------------------------------------------------
__global__ void init_zero(float* __restrict__ h)
{
    int c = threadIdx.x;
    h[c]    = 0.0f;
    g_hU[c] = 0.0f;
}

// ---------------- preamble: 4 embedding projections in one launch -------------
__global__ void gemm_pre(const float* __restrict__ emb,
                         const float* __restrict__ Wz, const float* __restrict__ Wr,
                         const float* __restrict__ Wh, const float* __restrict__ Wo)
{
    const float* Bw; float* C;
    switch (blockIdx.z) {
        case 0:  Bw = Wz; C = g_Ez; break;
        case 1:  Bw = Wr; C = g_Er; break;
        case 2:  Bw = Wh; C = g_Eh; break;
        default: Bw = Wo; C = g_Eo; break;
    }
    __shared__ float As[16][64];
    __shared__ float Bs[16][64];
    const int tid = threadIdx.x;
    const int tx = tid & 15, ty = tid >> 4;
    const int rowBase = blockIdx.y * 64;
    const int colBase = blockIdx.x * 64;
    const int lm  = tid >> 2;
    const int lk  = (tid & 3) * 4;
    const int blk = tid >> 4;
    const int bln = (tid & 15) * 4;
    float acc[4][4] = {};
    for (int kb = 0; kb < 256; kb += 16) {
        int ar = rowBase + lm;
        float4 av = make_float4(0.f, 0.f, 0.f, 0.f);
        if (ar < V_)
            av = *reinterpret_cast<const float4*>(&emb[(size_t)ar * 256 + kb + lk]);
        As[lk + 0][lm] = av.x; As[lk + 1][lm] = av.y;
        As[lk + 2][lm] = av.z; As[lk + 3][lm] = av.w;
        float4 bv = *reinterpret_cast<const float4*>(&Bw[(size_t)(kb + blk) * 256 + colBase + bln]);
        *reinterpret_cast<float4*>(&Bs[blk][bln]) = bv;
        __syncthreads();
#pragma unroll
        for (int k = 0; k < 16; ++k) {
            float4 a4 = *reinterpret_cast<const float4*>(&As[k][ty * 4]);
            float4 b4 = *reinterpret_cast<const float4*>(&Bs[k][tx * 4]);
            float aa[4] = {a4.x, a4.y, a4.z, a4.w};
            float bb[4] = {b4.x, b4.y, b4.z, b4.w};
#pragma unroll
            for (int i = 0; i < 4; ++i)
#pragma unroll
                for (int j = 0; j < 4; ++j)
                    acc[i][j] += aa[i] * bb[j];
        }
        __syncthreads();
    }
#pragma unroll
    for (int i = 0; i < 4; ++i) {
        int r = rowBase + ty * 4 + i;
        if (r < V_)
            *reinterpret_cast<float4*>(&C[(size_t)r * 256 + colBase + tx * 4]) =
                make_float4(acc[i][0], acc[i][1], acc[i][2], acc[i][3]);
    }
}

// ---------------- preamble: 3 weight splits in one launch ---------------------
__global__ void split3(const float* __restrict__ Wz, const float* __restrict__ Wh,
                       const float* __restrict__ Ur)
{
    const float* W; __nv_bfloat16 *hi, *lo;
    switch (blockIdx.y) {
        case 0:  W = Wz + H_ * H_; hi = g_Wzh_hi; lo = g_Wzh_lo; break;
        case 1:  W = Wh + H_ * H_; hi = g_Whh_hi; lo = g_Whh_lo; break;
        default: W = Ur;           hi = g_Ur_hi;  lo = g_Ur_lo;  break;
    }
    int i = blockIdx.x * 256 + threadIdx.x;
    float v = W[i];
    __nv_bfloat16 h = __float2bfloat16(v);
    hi[i] = h;
    lo[i] = __float2bfloat16(v - __bfloat162float(h));
}

// ---------------- per-step gather: sum_h / sum_gated -> bf16 hi/lo ------------
__global__ void gather_step(const float* __restrict__ h,
                            const int*   __restrict__ nei,
                            const int*   __restrict__ xids,
                            const float* __restrict__ bur)
{
    const int msg = blockIdx.x * 4 + (threadIdx.x >> 6);
    const int c4  = threadIdx.x & 63;

    const int xid = xids[msg];
    const float4 bu = reinterpret_cast<const float4*>(bur)[c4];
    const float4 er = reinterpret_cast<const float4*>(&g_Er[(size_t)xid * H_])[c4];
    const float bx = er.x + bu.x, by = er.y + bu.y, bz2 = er.z + bu.z, bw = er.w + bu.w;

    float4 sh = make_float4(0.f, 0.f, 0.f, 0.f);
    float4 sg = make_float4(0.f, 0.f, 0.f, 0.f);
#pragma unroll
    for (int n = 0; n < NB_; ++n) {
        const int j = nei[msg * NB_ + n];
        const float4 hv = reinterpret_cast<const float4*>(h)[(size_t)j * 64 + c4];
        const float4 uv = reinterpret_cast<const float4*>(g_hU)[(size_t)j * 64 + c4];
        sh.x += hv.x; sh.y += hv.y; sh.z += hv.z; sh.w += hv.w;
        sg.x += sigf(bx  + uv.x) * hv.x;
        sg.y += sigf(by  + uv.y) * hv.y;
        sg.z += sigf(bz2 + uv.z) * hv.z;
        sg.w += sigf(bw  + uv.w) * hv.w;
    }
    const size_t o4 = (size_t)msg * 64 + c4;
    {
        __nv_bfloat16 h0 = __float2bfloat16(sh.x), h1 = __float2bfloat16(sh.y),
                      h2 = __float2bfloat16(sh.z), h3 = __float2bfloat16(sh.w);
        uint2 u;
        { __nv_bfloat162 a; a.x = h0; a.y = h1; u.x = *reinterpret_cast<uint32_t*>(&a); }
        { __nv_bfloat162 a; a.x = h2; a.y = h3; u.y = *reinterpret_cast<uint32_t*>(&a); }
        reinterpret_cast<uint2*>(g_sh_hi)[o4] = u;
        uint2 v;
        v.x = pack_bf2(sh.x - __bfloat162float(h0), sh.y - __bfloat162float(h1));
        v.y = pack_bf2(sh.z - __bfloat162float(h2), sh.w - __bfloat162float(h3));
        reinterpret_cast<uint2*>(g_sh_lo)[o4] = v;
    }
    {
        __nv_bfloat16 h0 = __float2bfloat16(sg.x), h1 = __float2bfloat16(sg.y),
                      h2 = __float2bfloat16(sg.z), h3 = __float2bfloat16(sg.w);
        uint2 u;
        { __nv_bfloat162 a; a.x = h0; a.y = h1; u.x = *reinterpret_cast<uint32_t*>(&a); }
        { __nv_bfloat162 a; a.x = h2; a.y = h3; u.y = *reinterpret_cast<uint32_t*>(&a); }
        reinterpret_cast<uint2*>(g_sg_hi)[o4] = u;
        uint2 v;
        v.x = pack_bf2(sg.x - __bfloat162float(h0), sg.y - __bfloat162float(h1));
        v.y = pack_bf2(sg.z - __bfloat162float(h2), sg.w - __bfloat162float(h3));
        reinterpret_cast<uint2*>(g_sg_lo)[o4] = v;
    }
}

// ---------------- fused step GEMM: BM=64, BN=256, 512 threads -----------------
// 16 warps = 2(M) x 8(N); warp tile 32x32.
#define A_STRIDE  40     // 32 + 8 pad (bf16)
#define BW_STRIDE 264    // 256 + 8 pad (bf16)
#define NH_STRIDE 264

#define ST_A_HI 0
#define ST_A_LO 5120
#define ST_B_HI 10240
#define ST_B_LO 27136            // 10240 + 16896
#define ST_SZ   44032            // 10240 + 2*16896
#define P_SZ    (2*ST_SZ)        // 88064 (pass1/2 double buffer)
#define U_ST_SZ 33792            // pass3 stage: hi[16896] + lo[16896]
#define NH_HI   P_SZ             // 88064
#define NH_LO   (P_SZ + 33792)
#define SM_TOTAL (P_SZ + 2*33792) // 155648 bytes

// pass over K=256: acc += A(hi+lo) @ B(hi+lo), A/B from global
__device__ __forceinline__ void pass_AB(
    const __nv_bfloat16* __restrict__ Ahi, const __nv_bfloat16* __restrict__ Alo,
    const __nv_bfloat16* __restrict__ Bhi, const __nv_bfloat16* __restrict__ Blo,
    int rowBase, float acc[2][4][4], uint32_t sbase)
{
    const int tid  = threadIdx.x;
    const int lane = tid & 31;
    const int wid  = tid >> 5;
    const int warp_m = wid & 1;
    const int warp_n = wid >> 1;   // 0..7

    // A: one cpa16 per thread (hi or lo)
    const int ahalf = tid & 1;
    const int aidx  = tid >> 1;          // 0..255
    const int arow  = aidx >> 2;         // 0..63
    const int ak    = (aidx & 3) * 8;
    const uint32_t a_soff = (ahalf ? ST_A_LO : ST_A_HI) + (uint32_t)(arow * A_STRIDE + ak) * 2;
    const __nv_bfloat16* Ag = ahalf ? Alo : Ahi;
    const size_t a_goff = (size_t)(rowBase + arow) * 256 + ak;

    // B: [32 k, 256 n] tile; 4 cpa16 per thread (hi x2, lo x2)
    const int brow = tid >> 4;           // 0..31
    const int bcol = (tid & 15) * 8;     // 0..120
    const uint32_t b_soff0 = (uint32_t)(brow * BW_STRIDE + bcol) * 2;
    const uint32_t b_soff1 = (uint32_t)(brow * BW_STRIDE + bcol + 128) * 2;
    const size_t b_goff = (size_t)brow * 256 + bcol;

    cpa16(sbase + a_soff, &Ag[a_goff]);
    cpa16(sbase + ST_B_HI + b_soff0, &Bhi[b_goff]);
    cpa16(sbase + ST_B_HI + b_soff1, &Bhi[b_goff + 128]);
    cpa16(sbase + ST_B_LO + b_soff0, &Blo[b_goff]);
    cpa16(sbase + ST_B_LO + b_soff1, &Blo[b_goff + 128]);
    CP_COMMIT();

    for (int it = 0; it < 8; ++it) {
        const uint32_t scur = sbase + (uint32_t)(it & 1) * ST_SZ;
        __syncthreads();
        if (it < 7) {
            const uint32_t snxt = sbase + (uint32_t)((it + 1) & 1) * ST_SZ;
            const int kb = (it + 1) * 32;
            cpa16(snxt + a_soff, &Ag[a_goff + kb]);
            cpa16(snxt + ST_B_HI + b_soff0, &Bhi[b_goff + (size_t)kb * 256]);
            cpa16(snxt + ST_B_HI + b_soff1, &Bhi[b_goff + (size_t)kb * 256 + 128]);
            cpa16(snxt + ST_B_LO + b_soff0, &Blo[b_goff + (size_t)kb * 256]);
            cpa16(snxt + ST_B_LO + b_soff1, &Blo[b_goff + (size_t)kb * 256 + 128]);
        }
        CP_COMMIT();
        CP_WAIT1();
        __syncthreads();

#pragma unroll
        for (int ks = 0; ks < 32; ks += 16) {
            uint32_t ahi[2][4], alo[2][4];
#pragma unroll
            for (int mt = 0; mt < 2; ++mt) {
                const int el = (warp_m * 32 + mt * 16 + (lane & 15)) * A_STRIDE
                             + ks + (lane >> 4) * 8;
                ldsm4(ahi[mt], scur + ST_A_HI + el * 2);
                ldsm4(alo[mt], scur + ST_A_LO + el * 2);
            }
#pragma unroll
            for (int np = 0; np < 2; ++np) {
                const int n0 = warp_n * 32 + np * 16;
                const int el = (ks + (lane & 7) + ((lane >> 3) & 1) * 8) * BW_STRIDE
                             + n0 + (lane >> 4) * 8;
                uint32_t bh_[4], bl_[4];
                ldsm4t(bh_, scur + ST_B_HI + el * 2);
                ldsm4t(bl_, scur + ST_B_LO + el * 2);
#pragma unroll
                for (int mt = 0; mt < 2; ++mt) {
#pragma unroll
                    for (int s = 0; s < 2; ++s) {
                        float* d = acc[mt][np * 2 + s];
                        mma16816(d, ahi[mt], &bh_[2 * s]);
                        mma16816(d, ahi[mt], &bl_[2 * s]);
                        mma16816(d, alo[mt], &bh_[2 * s]);
                    }
                }
            }
        }
    }
}

// pass3: acc += new_h(smem hi/lo) @ Ur(hi+lo from global)
__device__ __forceinline__ void pass_U(float acc[2][4][4], uint32_t sbase)
{
    const int tid  = threadIdx.x;
    const int lane = tid & 31;
    const int wid  = tid >> 5;
    const int warp_m = wid & 1;
    const int warp_n = wid >> 1;

    const int brow = tid >> 4;
    const int bcol = (tid & 15) * 8;
    const uint32_t b_soff0 = (uint32_t)(brow * BW_STRIDE + bcol) * 2;
    const uint32_t b_soff1 = (uint32_t)(brow * BW_STRIDE + bcol + 128) * 2;
    const size_t b_goff = (size_t)brow * 256 + bcol;

    cpa16(sbase + b_soff0,         &g_Ur_hi[b_goff]);
    cpa16(sbase + b_soff1,         &g_Ur_hi[b_goff + 128]);
    cpa16(sbase + 16896 + b_soff0, &g_Ur_lo[b_goff]);
    cpa16(sbase + 16896 + b_soff1, &g_Ur_lo[b_goff + 128]);
    CP_COMMIT();

    for (int it = 0; it < 8; ++it) {
        const uint32_t scur = sbase + (uint32_t)(it & 1) * U_ST_SZ;
        __syncthreads();
        if (it < 7) {
            const uint32_t snxt = sbase + (uint32_t)((it + 1) & 1) * U_ST_SZ;
            const int kb = (it + 1) * 32;
            cpa16(snxt + b_soff0,         &g_Ur_hi[b_goff + (size_t)kb * 256]);
            cpa16(snxt + b_soff1,         &g_Ur_hi[b_goff + (size_t)kb * 256 + 128]);
            cpa16(snxt + 16896 + b_soff0, &g_Ur_lo[b_goff + (size_t)kb * 256]);
            cpa16(snxt + 16896 + b_soff1, &g_Ur_lo[b_goff + (size_t)kb * 256 + 128]);
        }
        CP_COMMIT();
        CP_WAIT1();
        __syncthreads();

        const int kb = it * 32;
#pragma unroll
        for (int ks = 0; ks < 32; ks += 16) {
            uint32_t ahi[2][4], alo[2][4];
#pragma unroll
            for (int mt = 0; mt < 2; ++mt) {
                const int el = (warp_m * 32 + mt * 16 + (lane & 15)) * NH_STRIDE
                             + kb + ks + (lane >> 4) * 8;
                ldsm4(ahi[mt], sbase + NH_HI + el * 2);
                ldsm4(alo[mt], sbase + NH_LO + el * 2);
            }
#pragma unroll
            for (int np = 0; np < 2; ++np) {
                const int n0 = warp_n * 32 + np * 16;
                const int el = (ks + (lane & 7) + ((lane >> 3) & 1) * 8) * BW_STRIDE
                             + n0 + (lane >> 4) * 8;
                uint32_t bh_[4], bl_[4];
                ldsm4t(bh_, scur + el * 2);
                ldsm4t(bl_, scur + 16896 + el * 2);
#pragma unroll
                for (int mt = 0; mt < 2; ++mt) {
#pragma unroll
                    for (int s = 0; s < 2; ++s) {
                        float* d = acc[mt][np * 2 + s];
                        mma16816(d, ahi[mt], &bh_[2 * s]);
                        mma16816(d, ahi[mt], &bl_[2 * s]);
                        mma16816(d, alo[mt], &bh_[2 * s]);
                    }
                }
            }
        }
    }
}

__global__ void __launch_bounds__(512, 1) step_mma(
    const float* __restrict__ bz, const float* __restrict__ bhb,
    const int*   __restrict__ xids,
    float* __restrict__ hout, float* __restrict__ hUout, int first)
{
    extern __shared__ char dsm[];
    const uint32_t sbase = smem_u32(dsm);
    const int rowBase = blockIdx.x * 64;

    float acc1[2][4][4] = {};
    float acc2[2][4][4] = {};
    if (!first) {
        pass_AB(g_sh_hi, g_sh_lo, g_Wzh_hi, g_Wzh_lo, rowBase, acc1, sbase);
        pass_AB(g_sg_hi, g_sg_lo, g_Whh_hi, g_Whh_lo, rowBase, acc2, sbase);
    }

    const int lane = threadIdx.x & 31;
    const int wid  = threadIdx.x >> 5;
    const int warp_m = wid & 1, warp_n = wid >> 1;

    // GRU epilogue -> hout (global) + new_h hi/lo into smem (NH region)
#pragma unroll
    for (int mt = 0; mt < 2; ++mt) {
#pragma unroll
        for (int nt = 0; nt < 4; ++nt) {
            const int col = warp_n * 32 + nt * 8 + (lane & 3) * 2;
#pragma unroll
            for (int half = 0; half < 2; ++half) {
                const int lr = warp_m * 32 + mt * 16 + (lane >> 2) + half * 8;
                const int r  = rowBase + lr;
                const float a1x = acc1[mt][nt][half * 2 + 0];
                const float a1y = acc1[mt][nt][half * 2 + 1];
                const float a2x = acc2[mt][nt][half * 2 + 0];
                const float a2y = acc2[mt][nt][half * 2 + 1];
                const int xid = xids[r];
                const float2 ez  = *reinterpret_cast<const float2*>(&g_Ez[(size_t)xid * H_ + col]);
                const float2 eh  = *reinterpret_cast<const float2*>(&g_Eh[(size_t)xid * H_ + col]);
                const float2 bzv = *reinterpret_cast<const float2*>(&bz[col]);
                const float2 bhv = *reinterpret_cast<const float2*>(&bhb[col]);
                float sh0 = 0.f, sh1 = 0.f;
                if (!first) {
                    const uint32_t shh = *reinterpret_cast<const uint32_t*>(&g_sh_hi[(size_t)r * H_ + col]);
                    const uint32_t shl = *reinterpret_cast<const uint32_t*>(&g_sh_lo[(size_t)r * H_ + col]);
                    const float2 sh_h = unpack_bf2(shh);
                    const float2 sh_l = unpack_bf2(shl);
                    sh0 = sh_h.x + sh_l.x;
                    sh1 = sh_h.y + sh_l.y;
                }
                const float z0 = sigf(ez.x + bzv.x + a1x);
                const float z1 = sigf(ez.y + bzv.y + a1y);
                const float p0 = tanhf(eh.x + bhv.x + a2x);
                const float p1 = tanhf(eh.y + bhv.y + a2y);
                const float o0 = (1.0f - z0) * sh0 + z0 * p0;
                const float o1 = (1.0f - z1) * sh1 + z1 * p1;
                *reinterpret_cast<float2*>(&hout[(size_t)r * H_ + col]) = make_float2(o0, o1);
                const uint32_t soff = (uint32_t)(lr * NH_STRIDE + col) * 2;
                __nv_bfloat162 hp; hp.x = __float2bfloat16(o0); hp.y = __float2bfloat16(o1);
                *reinterpret_cast<__nv_bfloat162*>(dsm + NH_HI + soff) = hp;
                __nv_bfloat162 lp;
                lp.x = __float2bfloat16(o0 - __bfloat162float(hp.x));
                lp.y = __float2bfloat16(o1 - __bfloat162float(hp.y));
                *reinterpret_cast<__nv_bfloat162*>(dsm + NH_LO + soff) = lp;
            }
        }
    }

    // pass3: hU = new_h @ Ur (A from smem)
    float acc3[2][4][4] = {};
    pass_U(acc3, sbase);

#pragma unroll
    for (int mt = 0; mt < 2; ++mt) {
#pragma unroll
        for (int nt = 0; nt < 4; ++nt) {
            const int col = warp_n * 32 + nt * 8 + (lane & 3) * 2;
            const int r0  = rowBase + warp_m * 32 + mt * 16 + (lane >> 2);
            *reinterpret_cast<float2*>(&hUout[(size_t)r0 * H_ + col]) =
                make_float2(acc3[mt][nt][0], acc3[mt][nt][1]);
            *reinterpret_cast<float2*>(&hUout[(size_t)(r0 + 8) * H_ + col]) =
                make_float2(acc3[mt][nt][2], acc3[mt][nt][3]);
        }
    }
}

// ---------------- fused root aggregate ----------------------------------------
__global__ void root_fused(const float* __restrict__ h, const int* __restrict__ rnei,
                           const int* __restrict__ rwid, const float* __restrict__ Woh,
                           const float* __restrict__ bo, float* __restrict__ out)
{
    __shared__ float s_sum[256];
    __shared__ int sj[NB_];
    const int b = blockIdx.x;
    const int c = threadIdx.x;
    if (c < NB_) sj[c] = rnei[b * NB_ + c];
    __syncthreads();
    float s = 0.f;
#pragma unroll
    for (int n = 0; n < NB_; ++n)
        s += h[(size_t)sj[n] * 256 + c];
    s_sum[c] = s;
    __syncthreads();
    float acc = 0.f;
#pragma unroll 8
    for (int k = 0; k < 256; ++k)
        acc += s_sum[k] * Woh[(size_t)k * 256 + c];
    const int xid = rwid[b];
    float v = g_Eo[(size_t)xid * 256 + c] + bo[c] + acc;
    out[(size_t)b * 256 + c] = fmaxf(v, 0.0f);
}

// ---------------- launch ------------------------------------------------------
extern "C" void kernel_launch(void* const* d_in, const int* in_sizes, int n_in,
                              void* d_out, int out_size)
{
    const int*   x_ids    = (const int*)  d_in[0];
    const int*   nei_idx  = (const int*)  d_in[1];
    const int*   root_wid = (const int*)  d_in[2];
    const int*   root_nei = (const int*)  d_in[3];
    const float* emb      = (const float*)d_in[4];
    const float* Wz       = (const float*)d_in[5];
    const float* bz       = (const float*)d_in[6];
    const float* Wr       = (const float*)d_in[7];
    const float* Ur       = (const float*)d_in[8];
    const float* bur      = (const float*)d_in[9];
    const float* Wh       = (const float*)d_in[10];
    const float* bh       = (const float*)d_in[11];
    const float* Wo       = (const float*)d_in[12];
    const float* bo       = (const float*)d_in[13];

    float* out  = (float*)d_out;
    float* h    = out;
    float* rvec = out + (size_t)(M_ + 1) * H_;

    float* p_hU;
    cudaGetSymbolAddress((void**)&p_hU, g_hU);

    cudaFuncSetAttribute(step_mma, cudaFuncAttributeMaxDynamicSharedMemorySize, SM_TOTAL);

    init_zero<<<1, 256>>>(h);

    dim3 gpre(4, (V_ + 63) / 64, 4);
    gemm_pre<<<gpre, 256>>>(emb, Wz, Wr, Wh, Wo);
    split3<<<dim3(256, 3), 256>>>(Wz, Wh, Ur);

    for (int t = 0; t < T_; ++t) {
        if (t > 0)
            gather_step<<<E_ / 4, 256>>>(h, nei_idx + (size_t)t * E_ * NB_,
                                         x_ids + (size_t)t * E_, bur);
        step_mma<<<E_ / 64, 512, SM_TOTAL>>>(
            bz, bh, x_ids + (size_t)t * E_,
            h + (size_t)(1 + t * E_) * H_,
            p_hU + (size_t)(1 + t * E_) * H_,
            (t == 0) ? 1 : 0);
    }

    root_fused<<<B_, 256>>>(h, root_nei, root_wid, Wo + (size_t)H_ * H_, bo, rvec);
}

// round 7
// speedup vs baseline: 1.6748x; 1.0937x over previous
#include <cuda_runtime.h>
#include <cuda_bf16.h>
#include <math.h>
#include <stdint.h>

#define T_  12
#define E_  8192
#define H_  256
#define V_  800
#define B_  256
#define NB_ 8
#define M_  (T_*E_)   // 98304 messages; h has 1+M rows (row 0 = pad)

// ---------------- scratch (static device arrays; no allocs allowed) ----------
__device__ float g_hU[(size_t)(M_+1)*H_];
__device__ float g_Ez[(size_t)V_*H_];
__device__ float g_Er[(size_t)V_*H_];
__device__ float g_Eh[(size_t)V_*H_];
__device__ float g_Eo[(size_t)V_*H_];

__device__ __nv_bfloat16 g_sh_hi[(size_t)E_*H_], g_sh_lo[(size_t)E_*H_];
__device__ __nv_bfloat16 g_sg_hi[(size_t)E_*H_], g_sg_lo[(size_t)E_*H_];
__device__ __nv_bfloat16 g_Wzh_hi[H_*H_], g_Wzh_lo[H_*H_];
__device__ __nv_bfloat16 g_Whh_hi[H_*H_], g_Whh_lo[H_*H_];
__device__ __nv_bfloat16 g_Ur_hi [H_*H_], g_Ur_lo [H_*H_];

// fast sigmoid: ex2.approx (via __expf) + rcp.approx — ~1 ulp class error
__device__ __forceinline__ float sigf(float x) {
    float d = 1.0f + __expf(-x);
    float r;
    asm("rcp.approx.ftz.f32 %0, %1;" : "=f"(r) : "f"(d));
    return r;
}

// ---------------- PTX helpers -------------------------------------------------
__device__ __forceinline__ uint32_t smem_u32(const void* p) {
    return (uint32_t)__cvta_generic_to_shared(p);
}
__device__ __forceinline__ void ldsm4(uint32_t* r, uint32_t a) {
    asm volatile("ldmatrix.sync.aligned.m8n8.x4.shared.b16 {%0,%1,%2,%3},[%4];\n"
                 : "=r"(r[0]), "=r"(r[1]), "=r"(r[2]), "=r"(r[3]) : "r"(a));
}
__device__ __forceinline__ void ldsm4t(uint32_t* r, uint32_t a) {
    asm volatile("ldmatrix.sync.aligned.m8n8.x4.trans.shared.b16 {%0,%1,%2,%3},[%4];\n"
                 : "=r"(r[0]), "=r"(r[1]), "=r"(r[2]), "=r"(r[3]) : "r"(a));
}
__device__ __forceinline__ void mma16816(float* d, const uint32_t* a, const uint32_t* b) {
    asm volatile("mma.sync.aligned.m16n8k16.row.col.f32.bf16.bf16.f32 "
                 "{%0,%1,%2,%3},{%4,%5,%6,%7},{%8,%9},{%0,%1,%2,%3};\n"
                 : "+f"(d[0]), "+f"(d[1]), "+f"(d[2]), "+f"(d[3])
                 : "r"(a[0]), "r"(a[1]), "r"(a[2]), "r"(a[3]), "r"(b[0]), "r"(b[1]));
}
__device__ __forceinline__ void cpa16(uint32_t dst, const void* src) {
    asm volatile("cp.async.cg.shared.global [%0],[%1],16;\n" :: "r"(dst), "l"(src));
}
#define CP_COMMIT()  asm volatile("cp.async.commit_group;\n" ::: "memory")
#define CP_WAIT1()   asm volatile("cp.async.wait_group 1;\n" ::: "memory")

__device__ __forceinline__ uint32_t pack_bf2(float a, float b) {
    __nv_bfloat162 t; t.x = __float2bfloat16(a); t.y = __float2bfloat16(b);
    return *reinterpret_cast<uint32_t*>(&t);
}
__device__ __forceinline__ float2 unpack_bf2(uint32_t u) {
    __nv_bfloat162 t = *reinterpret_cast<__nv_bfloat162*>(&u);
    return make_float2(__bfloat162float(t.x), __bfloat162float(t.y));
}

// ---------------- init --------------------------------------------------------
__global__ void init_zero(float* __restrict__ h)
{
    int c = threadIdx.x;
    h[c]    = 0.0f;
    g_hU[c] = 0.0f;
}

// ---------------- preamble: 4 embedding projections in one launch -------------
__global__ void gemm_pre(const float* __restrict__ emb,
                         const float* __restrict__ Wz, const float* __restrict__ Wr,
                         const float* __restrict__ Wh, const float* __restrict__ Wo)
{
    const float* Bw; float* C;
    switch (blockIdx.z) {
        case 0:  Bw = Wz; C = g_Ez; break;
        case 1:  Bw = Wr; C = g_Er; break;
        case 2:  Bw = Wh; C = g_Eh; break;
        default: Bw = Wo; C = g_Eo; break;
    }
    __shared__ float As[16][64];
    __shared__ float Bs[16][64];
    const int tid = threadIdx.x;
    const int tx = tid & 15, ty = tid >> 4;
    const int rowBase = blockIdx.y * 64;
    const int colBase = blockIdx.x * 64;
    const int lm  = tid >> 2;
    const int lk  = (tid & 3) * 4;
    const int blk = tid >> 4;
    const int bln = (tid & 15) * 4;
    float acc[4][4] = {};
    for (int kb = 0; kb < 256; kb += 16) {
        int ar = rowBase + lm;
        float4 av = make_float4(0.f, 0.f, 0.f, 0.f);
        if (ar < V_)
            av = *reinterpret_cast<const float4*>(&emb[(size_t)ar * 256 + kb + lk]);
        As[lk + 0][lm] = av.x; As[lk + 1][lm] = av.y;
        As[lk + 2][lm] = av.z; As[lk + 3][lm] = av.w;
        float4 bv = *reinterpret_cast<const float4*>(&Bw[(size_t)(kb + blk) * 256 + colBase + bln]);
        *reinterpret_cast<float4*>(&Bs[blk][bln]) = bv;
        __syncthreads();
#pragma unroll
        for (int k = 0; k < 16; ++k) {
            float4 a4 = *reinterpret_cast<const float4*>(&As[k][ty * 4]);
            float4 b4 = *reinterpret_cast<const float4*>(&Bs[k][tx * 4]);
            float aa[4] = {a4.x, a4.y, a4.z, a4.w};
            float bb[4] = {b4.x, b4.y, b4.z, b4.w};
#pragma unroll
            for (int i = 0; i < 4; ++i)
#pragma unroll
                for (int j = 0; j < 4; ++j)
                    acc[i][j] += aa[i] * bb[j];
        }
        __syncthreads();
    }
#pragma unroll
    for (int i = 0; i < 4; ++i) {
        int r = rowBase + ty * 4 + i;
        if (r < V_)
            *reinterpret_cast<float4*>(&C[(size_t)r * 256 + colBase + tx * 4]) =
                make_float4(acc[i][0], acc[i][1], acc[i][2], acc[i][3]);
    }
}

// ---------------- preamble: 3 weight splits in one launch ---------------------
__global__ void split3(const float* __restrict__ Wz, const float* __restrict__ Wh,
                       const float* __restrict__ Ur)
{
    const float* W; __nv_bfloat16 *hi, *lo;
    switch (blockIdx.y) {
        case 0:  W = Wz + H_ * H_; hi = g_Wzh_hi; lo = g_Wzh_lo; break;
        case 1:  W = Wh + H_ * H_; hi = g_Whh_hi; lo = g_Whh_lo; break;
        default: W = Ur;           hi = g_Ur_hi;  lo = g_Ur_lo;  break;
    }
    int i = blockIdx.x * 256 + threadIdx.x;
    float v = W[i];
    __nv_bfloat16 h = __float2bfloat16(v);
    hi[i] = h;
    lo[i] = __float2bfloat16(v - __bfloat162float(h));
}

// ---------------- per-step gather: sum_h / sum_gated -> bf16 hi/lo ------------
__global__ void gather_step(const float* __restrict__ h,
                            const int*   __restrict__ nei,
                            const int*   __restrict__ xids,
                            const float* __restrict__ bur)
{
    const int msg = blockIdx.x * 4 + (threadIdx.x >> 6);
    const int c4  = threadIdx.x & 63;

    const int xid = xids[msg];
    const float4 bu = reinterpret_cast<const float4*>(bur)[c4];
    const float4 er = reinterpret_cast<const float4*>(&g_Er[(size_t)xid * H_])[c4];
    const float bx = er.x + bu.x, by = er.y + bu.y, bz2 = er.z + bu.z, bw = er.w + bu.w;

    float4 sh = make_float4(0.f, 0.f, 0.f, 0.f);
    float4 sg = make_float4(0.f, 0.f, 0.f, 0.f);
#pragma unroll
    for (int n = 0; n < NB_; ++n) {
        const int j = nei[msg * NB_ + n];
        const float4 hv = reinterpret_cast<const float4*>(h)[(size_t)j * 64 + c4];
        const float4 uv = reinterpret_cast<const float4*>(g_hU)[(size_t)j * 64 + c4];
        sh.x += hv.x; sh.y += hv.y; sh.z += hv.z; sh.w += hv.w;
        sg.x += sigf(bx  + uv.x) * hv.x;
        sg.y += sigf(by  + uv.y) * hv.y;
        sg.z += sigf(bz2 + uv.z) * hv.z;
        sg.w += sigf(bw  + uv.w) * hv.w;
    }
    const size_t o4 = (size_t)msg * 64 + c4;
    {
        __nv_bfloat16 h0 = __float2bfloat16(sh.x), h1 = __float2bfloat16(sh.y),
                      h2 = __float2bfloat16(sh.z), h3 = __float2bfloat16(sh.w);
        uint2 u;
        { __nv_bfloat162 a; a.x = h0; a.y = h1; u.x = *reinterpret_cast<uint32_t*>(&a); }
        { __nv_bfloat162 a; a.x = h2; a.y = h3; u.y = *reinterpret_cast<uint32_t*>(&a); }
        reinterpret_cast<uint2*>(g_sh_hi)[o4] = u;
        uint2 v;
        v.x = pack_bf2(sh.x - __bfloat162float(h0), sh.y - __bfloat162float(h1));
        v.y = pack_bf2(sh.z - __bfloat162float(h2), sh.w - __bfloat162float(h3));
        reinterpret_cast<uint2*>(g_sh_lo)[o4] = v;
    }
    {
        __nv_bfloat16 h0 = __float2bfloat16(sg.x), h1 = __float2bfloat16(sg.y),
                      h2 = __float2bfloat16(sg.z), h3 = __float2bfloat16(sg.w);
        uint2 u;
        { __nv_bfloat162 a; a.x = h0; a.y = h1; u.x = *reinterpret_cast<uint32_t*>(&a); }
        { __nv_bfloat162 a; a.x = h2; a.y = h3; u.y = *reinterpret_cast<uint32_t*>(&a); }
        reinterpret_cast<uint2*>(g_sg_hi)[o4] = u;
        uint2 v;
        v.x = pack_bf2(sg.x - __bfloat162float(h0), sg.y - __bfloat162float(h1));
        v.y = pack_bf2(sg.z - __bfloat162float(h2), sg.w - __bfloat162float(h3));
        reinterpret_cast<uint2*>(g_sg_lo)[o4] = v;
    }
}

// ---------------- fused step GEMM: BM=64, BN=256, 512 threads -----------------
// 16 warps = 2(M) x 8(N); warp tile 32x32.
#define A_STRIDE  40     // 32 + 8 pad (bf16)
#define BW_STRIDE 264    // 256 + 8 pad (bf16)
#define NH_STRIDE 264

#define ST_A_HI 0
#define ST_A_LO 5120
#define ST_B_HI 10240
#define ST_B_LO 27136            // 10240 + 16896
#define ST_SZ   44032            // 10240 + 2*16896
#define P_SZ    (2*ST_SZ)        // 88064 (pass1/2 double buffer)
#define U_ST_SZ 33792            // pass3 stage: hi[16896] + lo[16896]
#define NH_HI   P_SZ             // 88064
#define NH_LO   (P_SZ + 33792)
#define SM_TOTAL (P_SZ + 2*33792) // 155648 bytes

// pass over K=256: acc += A(hi+lo) @ B(hi+lo), A/B from global
__device__ __forceinline__ void pass_AB(
    const __nv_bfloat16* __restrict__ Ahi, const __nv_bfloat16* __restrict__ Alo,
    const __nv_bfloat16* __restrict__ Bhi, const __nv_bfloat16* __restrict__ Blo,
    int rowBase, float acc[2][4][4], uint32_t sbase)
{
    const int tid  = threadIdx.x;
    const int lane = tid & 31;
    const int wid  = tid >> 5;
    const int warp_m = wid & 1;
    const int warp_n = wid >> 1;   // 0..7

    const int ahalf = tid & 1;
    const int aidx  = tid >> 1;          // 0..255
    const int arow  = aidx >> 2;         // 0..63
    const int ak    = (aidx & 3) * 8;
    const uint32_t a_soff = (ahalf ? ST_A_LO : ST_A_HI) + (uint32_t)(arow * A_STRIDE + ak) * 2;
    const __nv_bfloat16* Ag = ahalf ? Alo : Ahi;
    const size_t a_goff = (size_t)(rowBase + arow) * 256 + ak;

    const int brow = tid >> 4;           // 0..31
    const int bcol = (tid & 15) * 8;     // 0..120
    const uint32_t b_soff0 = (uint32_t)(brow * BW_STRIDE + bcol) * 2;
    const uint32_t b_soff1 = (uint32_t)(brow * BW_STRIDE + bcol + 128) * 2;
    const size_t b_goff = (size_t)brow * 256 + bcol;

    cpa16(sbase + a_soff, &Ag[a_goff]);
    cpa16(sbase + ST_B_HI + b_soff0, &Bhi[b_goff]);
    cpa16(sbase + ST_B_HI + b_soff1, &Bhi[b_goff + 128]);
    cpa16(sbase + ST_B_LO + b_soff0, &Blo[b_goff]);
    cpa16(sbase + ST_B_LO + b_soff1, &Blo[b_goff + 128]);
    CP_COMMIT();

    for (int it = 0; it < 8; ++it) {
        const uint32_t scur = sbase + (uint32_t)(it & 1) * ST_SZ;
        __syncthreads();
        if (it < 7) {
            const uint32_t snxt = sbase + (uint32_t)((it + 1) & 1) * ST_SZ;
            const int kb = (it + 1) * 32;
            cpa16(snxt + a_soff, &Ag[a_goff + kb]);
            cpa16(snxt + ST_B_HI + b_soff0, &Bhi[b_goff + (size_t)kb * 256]);
            cpa16(snxt + ST_B_HI + b_soff1, &Bhi[b_goff + (size_t)kb * 256 + 128]);
            cpa16(snxt + ST_B_LO + b_soff0, &Blo[b_goff + (size_t)kb * 256]);
            cpa16(snxt + ST_B_LO + b_soff1, &Blo[b_goff + (size_t)kb * 256 + 128]);
        }
        CP_COMMIT();
        CP_WAIT1();
        __syncthreads();

#pragma unroll
        for (int ks = 0; ks < 32; ks += 16) {
            uint32_t ahi[2][4], alo[2][4];
#pragma unroll
            for (int mt = 0; mt < 2; ++mt) {
                const int el = (warp_m * 32 + mt * 16 + (lane & 15)) * A_STRIDE
                             + ks + (lane >> 4) * 8;
                ldsm4(ahi[mt], scur + ST_A_HI + el * 2);
                ldsm4(alo[mt], scur + ST_A_LO + el * 2);
            }
#pragma unroll
            for (int np = 0; np < 2; ++np) {
                const int n0 = warp_n * 32 + np * 16;
                const int el = (ks + (lane & 7) + ((lane >> 3) & 1) * 8) * BW_STRIDE
                             + n0 + (lane >> 4) * 8;
                uint32_t bh_[4], bl_[4];
                ldsm4t(bh_, scur + ST_B_HI + el * 2);
                ldsm4t(bl_, scur + ST_B_LO + el * 2);
#pragma unroll
                for (int mt = 0; mt < 2; ++mt) {
#pragma unroll
                    for (int s = 0; s < 2; ++s) {
                        float* d = acc[mt][np * 2 + s];
                        mma16816(d, ahi[mt], &bh_[2 * s]);
                        mma16816(d, ahi[mt], &bl_[2 * s]);
                        mma16816(d, alo[mt], &bh_[2 * s]);
                    }
                }
            }
        }
    }
}

// pass3: acc += new_h(smem hi/lo) @ Ur(hi+lo from global)
__device__ __forceinline__ void pass_U(float acc[2][4][4], uint32_t sbase)
{
    const int tid  = threadIdx.x;
    const int lane = tid & 31;
    const int wid  = tid >> 5;
    const int warp_m = wid & 1;
    const int warp_n = wid >> 1;

    const int brow = tid >> 4;
    const int bcol = (tid & 15) * 8;
    const uint32_t b_soff0 = (uint32_t)(brow * BW_STRIDE + bcol) * 2;
    const uint32_t b_soff1 = (uint32_t)(brow * BW_STRIDE + bcol + 128) * 2;
    const size_t b_goff = (size_t)brow * 256 + bcol;

    cpa16(sbase + b_soff0,         &g_Ur_hi[b_goff]);
    cpa16(sbase + b_soff1,         &g_Ur_hi[b_goff + 128]);
    cpa16(sbase + 16896 + b_soff0, &g_Ur_lo[b_goff]);
    cpa16(sbase + 16896 + b_soff1, &g_Ur_lo[b_goff + 128]);
    CP_COMMIT();

    for (int it = 0; it < 8; ++it) {
        const uint32_t scur = sbase + (uint32_t)(it & 1) * U_ST_SZ;
        __syncthreads();
        if (it < 7) {
            const uint32_t snxt = sbase + (uint32_t)((it + 1) & 1) * U_ST_SZ;
            const int kb = (it + 1) * 32;
            cpa16(snxt + b_soff0,         &g_Ur_hi[b_goff + (size_t)kb * 256]);
            cpa16(snxt + b_soff1,         &g_Ur_hi[b_goff + (size_t)kb * 256 + 128]);
            cpa16(snxt + 16896 + b_soff0, &g_Ur_lo[b_goff + (size_t)kb * 256]);
            cpa16(snxt + 16896 + b_soff1, &g_Ur_lo[b_goff + (size_t)kb * 256 + 128]);
        }
        CP_COMMIT();
        CP_WAIT1();
        __syncthreads();

        const int kb = it * 32;
#pragma unroll
        for (int ks = 0; ks < 32; ks += 16) {
            uint32_t ahi[2][4], alo[2][4];
#pragma unroll
            for (int mt = 0; mt < 2; ++mt) {
                const int el = (warp_m * 32 + mt * 16 + (lane & 15)) * NH_STRIDE
                             + kb + ks + (lane >> 4) * 8;
                ldsm4(ahi[mt], sbase + NH_HI + el * 2);
                ldsm4(alo[mt], sbase + NH_LO + el * 2);
            }
#pragma unroll
            for (int np = 0; np < 2; ++np) {
                const int n0 = warp_n * 32 + np * 16;
                const int el = (ks + (lane & 7) + ((lane >> 3) & 1) * 8) * BW_STRIDE
                             + n0 + (lane >> 4) * 8;
                uint32_t bh_[4], bl_[4];
                ldsm4t(bh_, scur + el * 2);
                ldsm4t(bl_, scur + 16896 + el * 2);
#pragma unroll
                for (int mt = 0; mt < 2; ++mt) {
#pragma unroll
                    for (int s = 0; s < 2; ++s) {
                        float* d = acc[mt][np * 2 + s];
                        mma16816(d, ahi[mt], &bh_[2 * s]);
                        mma16816(d, ahi[mt], &bl_[2 * s]);
                        mma16816(d, alo[mt], &bh_[2 * s]);
                    }
                }
            }
        }
    }
}

__global__ void __launch_bounds__(512, 1) step_mma(
    const float* __restrict__ bz, const float* __restrict__ bhb,
    const int*   __restrict__ xids,
    float* __restrict__ hout, float* __restrict__ hUout, int first)
{
    extern __shared__ char dsm[];
    const uint32_t sbase = smem_u32(dsm);
    const int rowBase = blockIdx.x * 64;

    float acc1[2][4][4] = {};
    float acc2[2][4][4] = {};
    if (!first) {
        pass_AB(g_sh_hi, g_sh_lo, g_Wzh_hi, g_Wzh_lo, rowBase, acc1, sbase);
        pass_AB(g_sg_hi, g_sg_lo, g_Whh_hi, g_Whh_lo, rowBase, acc2, sbase);
    }

    const int lane = threadIdx.x & 31;
    const int wid  = threadIdx.x >> 5;
    const int warp_m = wid & 1, warp_n = wid >> 1;

    // GRU epilogue -> hout (global) + new_h hi/lo into smem (NH region)
#pragma unroll
    for (int mt = 0; mt < 2; ++mt) {
#pragma unroll
        for (int nt = 0; nt < 4; ++nt) {
            const int col = warp_n * 32 + nt * 8 + (lane & 3) * 2;
#pragma unroll
            for (int half = 0; half < 2; ++half) {
                const int lr = warp_m * 32 + mt * 16 + (lane >> 2) + half * 8;
                const int r  = rowBase + lr;
                const float a1x = acc1[mt][nt][half * 2 + 0];
                const float a1y = acc1[mt][nt][half * 2 + 1];
                const float a2x = acc2[mt][nt][half * 2 + 0];
                const float a2y = acc2[mt][nt][half * 2 + 1];
                const int xid = xids[r];
                const float2 ez  = *reinterpret_cast<const float2*>(&g_Ez[(size_t)xid * H_ + col]);
                const float2 eh  = *reinterpret_cast<const float2*>(&g_Eh[(size_t)xid * H_ + col]);
                const float2 bzv = *reinterpret_cast<const float2*>(&bz[col]);
                const float2 bhv = *reinterpret_cast<const float2*>(&bhb[col]);
                float sh0 = 0.f, sh1 = 0.f;
                if (!first) {
                    const uint32_t shh = *reinterpret_cast<const uint32_t*>(&g_sh_hi[(size_t)r * H_ + col]);
                    const uint32_t shl = *reinterpret_cast<const uint32_t*>(&g_sh_lo[(size_t)r * H_ + col]);
                    const float2 sh_h = unpack_bf2(shh);
                    const float2 sh_l = unpack_bf2(shl);
                    sh0 = sh_h.x + sh_l.x;
                    sh1 = sh_h.y + sh_l.y;
                }
                const float z0 = sigf(ez.x + bzv.x + a1x);
                const float z1 = sigf(ez.y + bzv.y + a1y);
                const float p0 = tanhf(eh.x + bhv.x + a2x);
                const float p1 = tanhf(eh.y + bhv.y + a2y);
                const float o0 = (1.0f - z0) * sh0 + z0 * p0;
                const float o1 = (1.0f - z1) * sh1 + z1 * p1;
                *reinterpret_cast<float2*>(&hout[(size_t)r * H_ + col]) = make_float2(o0, o1);
                const uint32_t soff = (uint32_t)(lr * NH_STRIDE + col) * 2;
                __nv_bfloat162 hp; hp.x = __float2bfloat16(o0); hp.y = __float2bfloat16(o1);
                *reinterpret_cast<__nv_bfloat162*>(dsm + NH_HI + soff) = hp;
                __nv_bfloat162 lp;
                lp.x = __float2bfloat16(o0 - __bfloat162float(hp.x));
                lp.y = __float2bfloat16(o1 - __bfloat162float(hp.y));
                *reinterpret_cast<__nv_bfloat162*>(dsm + NH_LO + soff) = lp;
            }
        }
    }

    // pass3: hU = new_h @ Ur (A from smem)
    float acc3[2][4][4] = {};
    pass_U(acc3, sbase);

#pragma unroll
    for (int mt = 0; mt < 2; ++mt) {
#pragma unroll
        for (int nt = 0; nt < 4; ++nt) {
            const int col = warp_n * 32 + nt * 8 + (lane & 3) * 2;
            const int r0  = rowBase + warp_m * 32 + mt * 16 + (lane >> 2);
            *reinterpret_cast<float2*>(&hUout[(size_t)r0 * H_ + col]) =
                make_float2(acc3[mt][nt][0], acc3[mt][nt][1]);
            *reinterpret_cast<float2*>(&hUout[(size_t)(r0 + 8) * H_ + col]) =
                make_float2(acc3[mt][nt][2], acc3[mt][nt][3]);
        }
    }
}

// ---------------- fused root aggregate ----------------------------------------
__global__ void root_fused(const float* __restrict__ h, const int* __restrict__ rnei,
                           const int* __restrict__ rwid, const float* __restrict__ Woh,
                           const float* __restrict__ bo, float* __restrict__ out)
{
    __shared__ float s_sum[256];
    __shared__ int sj[NB_];
    const int b = blockIdx.x;
    const int c = threadIdx.x;
    if (c < NB_) sj[c] = rnei[b * NB_ + c];
    __syncthreads();
    float s = 0.f;
#pragma unroll
    for (int n = 0; n < NB_; ++n)
        s += h[(size_t)sj[n] * 256 + c];
    s_sum[c] = s;
    __syncthreads();
    float acc = 0.f;
#pragma unroll 8
    for (int k = 0; k < 256; ++k)
        acc += s_sum[k] * Woh[(size_t)k * 256 + c];
    const int xid = rwid[b];
    float v = g_Eo[(size_t)xid * 256 + c] + bo[c] + acc;
    out[(size_t)b * 256 + c] = fmaxf(v, 0.0f);
}

// ---------------- launch ------------------------------------------------------
extern "C" void kernel_launch(void* const* d_in, const int* in_sizes, int n_in,
                              void* d_out, int out_size)
{
    const int*   x_ids    = (const int*)  d_in[0];
    const int*   nei_idx  = (const int*)  d_in[1];
    const int*   root_wid = (const int*)  d_in[2];
    const int*   root_nei = (const int*)  d_in[3];
    const float* emb      = (const float*)d_in[4];
    const float* Wz       = (const float*)d_in[5];
    const float* bz       = (const float*)d_in[6];
    const float* Wr       = (const float*)d_in[7];
    const float* Ur       = (const float*)d_in[8];
    const float* bur      = (const float*)d_in[9];
    const float* Wh       = (const float*)d_in[10];
    const float* bh       = (const float*)d_in[11];
    const float* Wo       = (const float*)d_in[12];
    const float* bo       = (const float*)d_in[13];

    float* out  = (float*)d_out;
    float* h    = out;
    float* rvec = out + (size_t)(M_ + 1) * H_;

    float* p_hU;
    cudaGetSymbolAddress((void**)&p_hU, g_hU);

    cudaFuncSetAttribute(step_mma, cudaFuncAttributeMaxDynamicSharedMemorySize, SM_TOTAL);

    init_zero<<<1, 256>>>(h);

    dim3 gpre(4, (V_ + 63) / 64, 4);
    gemm_pre<<<gpre, 256>>>(emb, Wz, Wr, Wh, Wo);
    split3<<<dim3(256, 3), 256>>>(Wz, Wh, Ur);

    for (int t = 0; t < T_; ++t) {
        if (t > 0)
            gather_step<<<E_ / 4, 256>>>(h, nei_idx + (size_t)t * E_ * NB_,
                                         x_ids + (size_t)t * E_, bur);
        step_mma<<<E_ / 64, 512, SM_TOTAL>>>(
            bz, bh, x_ids + (size_t)t * E_,
            h + (size_t)(1 + t * E_) * H_,
            p_hU + (size_t)(1 + t * E_) * H_,
            (t == 0) ? 1 : 0);
    }

    root_fused<<<B_, 256>>>(h, root_nei, root_wid, Wo + (size_t)H_ * H_, bo, rvec);
}

// round 8
// speedup vs baseline: 1.6859x; 1.0066x over previous
#include <cuda_runtime.h>
#include <cuda_bf16.h>
#include <math.h>
#include <stdint.h>

#define T_  12
#define E_  8192
#define H_  256
#define V_  800
#define B_  256
#define NB_ 8
#define M_  (T_*E_)   // 98304 messages; h has 1+M rows (row 0 = pad)

// ---------------- scratch (static device arrays; no allocs allowed) ----------
__device__ float g_hU[(size_t)(M_+1)*H_];
__device__ float g_Ez[(size_t)V_*H_];
__device__ float g_Er[(size_t)V_*H_];
__device__ float g_Eh[(size_t)V_*H_];
__device__ float g_Eo[(size_t)V_*H_];

__device__ __nv_bfloat16 g_sh_hi[(size_t)E_*H_], g_sh_lo[(size_t)E_*H_];
__device__ __nv_bfloat16 g_sg_hi[(size_t)E_*H_], g_sg_lo[(size_t)E_*H_];
__device__ __nv_bfloat16 g_Wzh_hi[H_*H_], g_Wzh_lo[H_*H_];
__device__ __nv_bfloat16 g_Whh_hi[H_*H_], g_Whh_lo[H_*H_];
__device__ __nv_bfloat16 g_Ur_hi [H_*H_], g_Ur_lo [H_*H_];

// fast sigmoid: ex2.approx (via __expf) + rcp.approx — ~1 ulp class error
__device__ __forceinline__ float sigf(float x) {
    float d = 1.0f + __expf(-x);
    float r;
    asm("rcp.approx.ftz.f32 %0, %1;" : "=f"(r) : "f"(d));
    return r;
}

// ---------------- PTX helpers -------------------------------------------------
__device__ __forceinline__ uint32_t smem_u32(const void* p) {
    return (uint32_t)__cvta_generic_to_shared(p);
}
__device__ __forceinline__ void ldsm4(uint32_t* r, uint32_t a) {
    asm volatile("ldmatrix.sync.aligned.m8n8.x4.shared.b16 {%0,%1,%2,%3},[%4];\n"
                 : "=r"(r[0]), "=r"(r[1]), "=r"(r[2]), "=r"(r[3]) : "r"(a));
}
__device__ __forceinline__ void ldsm4t(uint32_t* r, uint32_t a) {
    asm volatile("ldmatrix.sync.aligned.m8n8.x4.trans.shared.b16 {%0,%1,%2,%3},[%4];\n"
                 : "=r"(r[0]), "=r"(r[1]), "=r"(r[2]), "=r"(r[3]) : "r"(a));
}
__device__ __forceinline__ void mma16816(float* d, const uint32_t* a, const uint32_t* b) {
    asm volatile("mma.sync.aligned.m16n8k16.row.col.f32.bf16.bf16.f32 "
                 "{%0,%1,%2,%3},{%4,%5,%6,%7},{%8,%9},{%0,%1,%2,%3};\n"
                 : "+f"(d[0]), "+f"(d[1]), "+f"(d[2]), "+f"(d[3])
                 : "r"(a[0]), "r"(a[1]), "r"(a[2]), "r"(a[3]), "r"(b[0]), "r"(b[1]));
}
__device__ __forceinline__ void cpa16(uint32_t dst, const void* src) {
    asm volatile("cp.async.cg.shared.global [%0],[%1],16;\n" :: "r"(dst), "l"(src));
}
#define CP_COMMIT()  asm volatile("cp.async.commit_group;\n" ::: "memory")
#define CP_WAIT1()   asm volatile("cp.async.wait_group 1;\n" ::: "memory")

__device__ __forceinline__ uint32_t pack_bf2(float a, float b) {
    __nv_bfloat162 t; t.x = __float2bfloat16(a); t.y = __float2bfloat16(b);
    return *reinterpret_cast<uint32_t*>(&t);
}
__device__ __forceinline__ float2 unpack_bf2(uint32_t u) {
    __nv_bfloat162 t = *reinterpret_cast<__nv_bfloat162*>(&u);
    return make_float2(__bfloat162float(t.x), __bfloat162float(t.y));
}

// ---------------- init --------------------------------------------------------
__global__ void init_zero(float* __restrict__ h)
{
    int c = threadIdx.x;
    h[c]    = 0.0f;
    g_hU[c] = 0.0f;
}

// ---------------- preamble: 4 embedding projections in one launch -------------
__global__ void gemm_pre(const float* __restrict__ emb,
                         const float* __restrict__ Wz, const float* __restrict__ Wr,
                         const float* __restrict__ Wh, const float* __restrict__ Wo)
{
    const float* Bw; float* C;
    switch (blockIdx.z) {
        case 0:  Bw = Wz; C = g_Ez; break;
        case 1:  Bw = Wr; C = g_Er; break;
        case 2:  Bw = Wh; C = g_Eh; break;
        default: Bw = Wo; C = g_Eo; break;
    }
    __shared__ float As[16][64];
    __shared__ float Bs[16][64];
    const int tid = threadIdx.x;
    const int tx = tid & 15, ty = tid >> 4;
    const int rowBase = blockIdx.y * 64;
    const int colBase = blockIdx.x * 64;
    const int lm  = tid >> 2;
    const int lk  = (tid & 3) * 4;
    const int blk = tid >> 4;
    const int bln = (tid & 15) * 4;
    float acc[4][4] = {};
    for (int kb = 0; kb < 256; kb += 16) {
        int ar = rowBase + lm;
        float4 av = make_float4(0.f, 0.f, 0.f, 0.f);
        if (ar < V_)
            av = *reinterpret_cast<const float4*>(&emb[(size_t)ar * 256 + kb + lk]);
        As[lk + 0][lm] = av.x; As[lk + 1][lm] = av.y;
        As[lk + 2][lm] = av.z; As[lk + 3][lm] = av.w;
        float4 bv = *reinterpret_cast<const float4*>(&Bw[(size_t)(kb + blk) * 256 + colBase + bln]);
        *reinterpret_cast<float4*>(&Bs[blk][bln]) = bv;
        __syncthreads();
#pragma unroll
        for (int k = 0; k < 16; ++k) {
            float4 a4 = *reinterpret_cast<const float4*>(&As[k][ty * 4]);
            float4 b4 = *reinterpret_cast<const float4*>(&Bs[k][tx * 4]);
            float aa[4] = {a4.x, a4.y, a4.z, a4.w};
            float bb[4] = {b4.x, b4.y, b4.z, b4.w};
#pragma unroll
            for (int i = 0; i < 4; ++i)
#pragma unroll
                for (int j = 0; j < 4; ++j)
                    acc[i][j] += aa[i] * bb[j];
        }
        __syncthreads();
    }
#pragma unroll
    for (int i = 0; i < 4; ++i) {
        int r = rowBase + ty * 4 + i;
        if (r < V_)
            *reinterpret_cast<float4*>(&C[(size_t)r * 256 + colBase + tx * 4]) =
                make_float4(acc[i][0], acc[i][1], acc[i][2], acc[i][3]);
    }
}

// ---------------- preamble: 3 weight splits in one launch ---------------------
__global__ void split3(const float* __restrict__ Wz, const float* __restrict__ Wh,
                       const float* __restrict__ Ur)
{
    const float* W; __nv_bfloat16 *hi, *lo;
    switch (blockIdx.y) {
        case 0:  W = Wz + H_ * H_; hi = g_Wzh_hi; lo = g_Wzh_lo; break;
        case 1:  W = Wh + H_ * H_; hi = g_Whh_hi; lo = g_Whh_lo; break;
        default: W = Ur;           hi = g_Ur_hi;  lo = g_Ur_lo;  break;
    }
    int i = blockIdx.x * 256 + threadIdx.x;
    float v = W[i];
    __nv_bfloat16 h = __float2bfloat16(v);
    hi[i] = h;
    lo[i] = __float2bfloat16(v - __bfloat162float(h));
}

// ---------------- per-step gather: sum_h / sum_gated -> bf16 hi/lo ------------
__global__ void gather_step(const float* __restrict__ h,
                            const int*   __restrict__ nei,
                            const int*   __restrict__ xids,
                            const float* __restrict__ bur)
{
    const int msg = blockIdx.x * 4 + (threadIdx.x >> 6);
    const int c4  = threadIdx.x & 63;

    const int xid = xids[msg];
    const float4 bu = reinterpret_cast<const float4*>(bur)[c4];
    const float4 er = reinterpret_cast<const float4*>(&g_Er[(size_t)xid * H_])[c4];
    const float bx = er.x + bu.x, by = er.y + bu.y, bz2 = er.z + bu.z, bw = er.w + bu.w;

    float4 sh = make_float4(0.f, 0.f, 0.f, 0.f);
    float4 sg = make_float4(0.f, 0.f, 0.f, 0.f);
#pragma unroll
    for (int n = 0; n < NB_; ++n) {
        const int j = nei[msg * NB_ + n];
        const float4 hv = reinterpret_cast<const float4*>(h)[(size_t)j * 64 + c4];
        const float4 uv = reinterpret_cast<const float4*>(g_hU)[(size_t)j * 64 + c4];
        sh.x += hv.x; sh.y += hv.y; sh.z += hv.z; sh.w += hv.w;
        sg.x += sigf(bx  + uv.x) * hv.x;
        sg.y += sigf(by  + uv.y) * hv.y;
        sg.z += sigf(bz2 + uv.z) * hv.z;
        sg.w += sigf(bw  + uv.w) * hv.w;
    }
    const size_t o4 = (size_t)msg * 64 + c4;
    {
        __nv_bfloat16 h0 = __float2bfloat16(sh.x), h1 = __float2bfloat16(sh.y),
                      h2 = __float2bfloat16(sh.z), h3 = __float2bfloat16(sh.w);
        uint2 u;
        { __nv_bfloat162 a; a.x = h0; a.y = h1; u.x = *reinterpret_cast<uint32_t*>(&a); }
        { __nv_bfloat162 a; a.x = h2; a.y = h3; u.y = *reinterpret_cast<uint32_t*>(&a); }
        reinterpret_cast<uint2*>(g_sh_hi)[o4] = u;
        uint2 v;
        v.x = pack_bf2(sh.x - __bfloat162float(h0), sh.y - __bfloat162float(h1));
        v.y = pack_bf2(sh.z - __bfloat162float(h2), sh.w - __bfloat162float(h3));
        reinterpret_cast<uint2*>(g_sh_lo)[o4] = v;
    }
    {
        __nv_bfloat16 h0 = __float2bfloat16(sg.x), h1 = __float2bfloat16(sg.y),
                      h2 = __float2bfloat16(sg.z), h3 = __float2bfloat16(sg.w);
        uint2 u;
        { __nv_bfloat162 a; a.x = h0; a.y = h1; u.x = *reinterpret_cast<uint32_t*>(&a); }
        { __nv_bfloat162 a; a.x = h2; a.y = h3; u.y = *reinterpret_cast<uint32_t*>(&a); }
        reinterpret_cast<uint2*>(g_sg_hi)[o4] = u;
        uint2 v;
        v.x = pack_bf2(sg.x - __bfloat162float(h0), sg.y - __bfloat162float(h1));
        v.y = pack_bf2(sg.z - __bfloat162float(h2), sg.w - __bfloat162float(h3));
        reinterpret_cast<uint2*>(g_sg_lo)[o4] = v;
    }
}

// ---------------- fused step GEMM: BM=64, BN=256, 512 threads -----------------
// 16 warps = 2(M) x 8(N); warp tile 32x32.
#define A_STRIDE  40     // 32 + 8 pad (bf16)
#define BW_STRIDE 264    // 256 + 8 pad (bf16)
#define NH_STRIDE 264

#define ST_A_HI 0
#define ST_A_LO 5120
#define ST_B_HI 10240
#define ST_B_LO 27136            // 10240 + 16896
#define ST_SZ   44032            // 10240 + 2*16896
#define P_SZ    (2*ST_SZ)        // 88064 (pass1/2 double buffer)
#define U_ST_SZ 33792            // pass3 stage: hi[16896] + lo[16896]
#define NH_HI   P_SZ             // 88064
#define NH_LO   (P_SZ + 33792)
#define SM_TOTAL (P_SZ + 2*33792) // 155648 bytes

// pass over K=256: acc += A(hi+lo) @ B(hi+lo), A/B from global
__device__ __forceinline__ void pass_AB(
    const __nv_bfloat16* __restrict__ Ahi, const __nv_bfloat16* __restrict__ Alo,
    const __nv_bfloat16* __restrict__ Bhi, const __nv_bfloat16* __restrict__ Blo,
    int rowBase, float acc[2][4][4], uint32_t sbase)
{
    const int tid  = threadIdx.x;
    const int lane = tid & 31;
    const int wid  = tid >> 5;
    const int warp_m = wid & 1;
    const int warp_n = wid >> 1;   // 0..7

    const int ahalf = tid & 1;
    const int aidx  = tid >> 1;          // 0..255
    const int arow  = aidx >> 2;         // 0..63
    const int ak    = (aidx & 3) * 8;
    const uint32_t a_soff = (ahalf ? ST_A_LO : ST_A_HI) + (uint32_t)(arow * A_STRIDE + ak) * 2;
    const __nv_bfloat16* Ag = ahalf ? Alo : Ahi;
    const size_t a_goff = (size_t)(rowBase + arow) * 256 + ak;

    const int brow = tid >> 4;           // 0..31
    const int bcol = (tid & 15) * 8;     // 0..120
    const uint32_t b_soff0 = (uint32_t)(brow * BW_STRIDE + bcol) * 2;
    const uint32_t b_soff1 = (uint32_t)(brow * BW_STRIDE + bcol + 128) * 2;
    const size_t b_goff = (size_t)brow * 256 + bcol;

    cpa16(sbase + a_soff, &Ag[a_goff]);
    cpa16(sbase + ST_B_HI + b_soff0, &Bhi[b_goff]);
    cpa16(sbase + ST_B_HI + b_soff1, &Bhi[b_goff + 128]);
    cpa16(sbase + ST_B_LO + b_soff0, &Blo[b_goff]);
    cpa16(sbase + ST_B_LO + b_soff1, &Blo[b_goff + 128]);
    CP_COMMIT();

    for (int it = 0; it < 8; ++it) {
        const uint32_t scur = sbase + (uint32_t)(it & 1) * ST_SZ;
        __syncthreads();
        if (it < 7) {
            const uint32_t snxt = sbase + (uint32_t)((it + 1) & 1) * ST_SZ;
            const int kb = (it + 1) * 32;
            cpa16(snxt + a_soff, &Ag[a_goff + kb]);
            cpa16(snxt + ST_B_HI + b_soff0, &Bhi[b_goff + (size_t)kb * 256]);
            cpa16(snxt + ST_B_HI + b_soff1, &Bhi[b_goff + (size_t)kb * 256 + 128]);
            cpa16(snxt + ST_B_LO + b_soff0, &Blo[b_goff + (size_t)kb * 256]);
            cpa16(snxt + ST_B_LO + b_soff1, &Blo[b_goff + (size_t)kb * 256 + 128]);
        }
        CP_COMMIT();
        CP_WAIT1();
        __syncthreads();

#pragma unroll
        for (int ks = 0; ks < 32; ks += 16) {
            uint32_t ahi[2][4], alo[2][4];
#pragma unroll
            for (int mt = 0; mt < 2; ++mt) {
                const int el = (warp_m * 32 + mt * 16 + (lane & 15)) * A_STRIDE
                             + ks + (lane >> 4) * 8;
                ldsm4(ahi[mt], scur + ST_A_HI + el * 2);
                ldsm4(alo[mt], scur + ST_A_LO + el * 2);
            }
#pragma unroll
            for (int np = 0; np < 2; ++np) {
                const int n0 = warp_n * 32 + np * 16;
                const int el = (ks + (lane & 7) + ((lane >> 3) & 1) * 8) * BW_STRIDE
                             + n0 + (lane >> 4) * 8;
                uint32_t bh_[4], bl_[4];
                ldsm4t(bh_, scur + ST_B_HI + el * 2);
                ldsm4t(bl_, scur + ST_B_LO + el * 2);
#pragma unroll
                for (int mt = 0; mt < 2; ++mt) {
#pragma unroll
                    for (int s = 0; s < 2; ++s) {
                        float* d = acc[mt][np * 2 + s];
                        mma16816(d, ahi[mt], &bh_[2 * s]);
                        mma16816(d, ahi[mt], &bl_[2 * s]);
                        mma16816(d, alo[mt], &bh_[2 * s]);
                    }
                }
            }
        }
    }
}

// pass3: acc += new_h(smem hi/lo) @ Ur(hi+lo from global)
__device__ __forceinline__ void pass_U(float acc[2][4][4], uint32_t sbase)
{
    const int tid  = threadIdx.x;
    const int lane = tid & 31;
    const int wid  = tid >> 5;
    const int warp_m = wid & 1;
    const int warp_n = wid >> 1;

    const int brow = tid >> 4;
    const int bcol = (tid & 15) * 8;
    const uint32_t b_soff0 = (uint32_t)(brow * BW_STRIDE + bcol) * 2;
    const uint32_t b_soff1 = (uint32_t)(brow * BW_STRIDE + bcol + 128) * 2;
    const size_t b_goff = (size_t)brow * 256 + bcol;

    cpa16(sbase + b_soff0,         &g_Ur_hi[b_goff]);
    cpa16(sbase + b_soff1,         &g_Ur_hi[b_goff + 128]);
    cpa16(sbase + 16896 + b_soff0, &g_Ur_lo[b_goff]);
    cpa16(sbase + 16896 + b_soff1, &g_Ur_lo[b_goff + 128]);
    CP_COMMIT();

    for (int it = 0; it < 8; ++it) {
        const uint32_t scur = sbase + (uint32_t)(it & 1) * U_ST_SZ;
        __syncthreads();
        if (it < 7) {
            const uint32_t snxt = sbase + (uint32_t)((it + 1) & 1) * U_ST_SZ;
            const int kb = (it + 1) * 32;
            cpa16(snxt + b_soff0,         &g_Ur_hi[b_goff + (size_t)kb * 256]);
            cpa16(snxt + b_soff1,         &g_Ur_hi[b_goff + (size_t)kb * 256 + 128]);
            cpa16(snxt + 16896 + b_soff0, &g_Ur_lo[b_goff + (size_t)kb * 256]);
            cpa16(snxt + 16896 + b_soff1, &g_Ur_lo[b_goff + (size_t)kb * 256 + 128]);
        }
        CP_COMMIT();
        CP_WAIT1();
        __syncthreads();

        const int kb = it * 32;
#pragma unroll
        for (int ks = 0; ks < 32; ks += 16) {
            uint32_t ahi[2][4], alo[2][4];
#pragma unroll
            for (int mt = 0; mt < 2; ++mt) {
                const int el = (warp_m * 32 + mt * 16 + (lane & 15)) * NH_STRIDE
                             + kb + ks + (lane >> 4) * 8;
                ldsm4(ahi[mt], sbase + NH_HI + el * 2);
                ldsm4(alo[mt], sbase + NH_LO + el * 2);
            }
#pragma unroll
            for (int np = 0; np < 2; ++np) {
                const int n0 = warp_n * 32 + np * 16;
                const int el = (ks + (lane & 7) + ((lane >> 3) & 1) * 8) * BW_STRIDE
                             + n0 + (lane >> 4) * 8;
                uint32_t bh_[4], bl_[4];
                ldsm4t(bh_, scur + el * 2);
                ldsm4t(bl_, scur + 16896 + el * 2);
#pragma unroll
                for (int mt = 0; mt < 2; ++mt) {
#pragma unroll
                    for (int s = 0; s < 2; ++s) {
                        float* d = acc[mt][np * 2 + s];
                        mma16816(d, ahi[mt], &bh_[2 * s]);
                        mma16816(d, ahi[mt], &bl_[2 * s]);
                        mma16816(d, alo[mt], &bh_[2 * s]);
                    }
                }
            }
        }
    }
}

__global__ void __launch_bounds__(512, 1) step_mma(
    const float* __restrict__ bz, const float* __restrict__ bhb,
    const int*   __restrict__ xids,
    float* __restrict__ hout, float* __restrict__ hUout, int first)
{
    extern __shared__ char dsm[];
    const uint32_t sbase = smem_u32(dsm);
    const int rowBase = blockIdx.x * 64;

    float acc1[2][4][4] = {};
    float acc2[2][4][4] = {};
    if (!first) {
        pass_AB(g_sh_hi, g_sh_lo, g_Wzh_hi, g_Wzh_lo, rowBase, acc1, sbase);
        pass_AB(g_sg_hi, g_sg_lo, g_Whh_hi, g_Whh_lo, rowBase, acc2, sbase);
    }

    const int lane = threadIdx.x & 31;
    const int wid  = threadIdx.x >> 5;
    const int warp_m = wid & 1, warp_n = wid >> 1;

    // GRU epilogue -> hout (global) + new_h hi/lo into smem (NH region)
#pragma unroll
    for (int mt = 0; mt < 2; ++mt) {
#pragma unroll
        for (int nt = 0; nt < 4; ++nt) {
            const int col = warp_n * 32 + nt * 8 + (lane & 3) * 2;
#pragma unroll
            for (int half = 0; half < 2; ++half) {
                const int lr = warp_m * 32 + mt * 16 + (lane >> 2) + half * 8;
                const int r  = rowBase + lr;
                const float a1x = acc1[mt][nt][half * 2 + 0];
                const float a1y = acc1[mt][nt][half * 2 + 1];
                const float a2x = acc2[mt][nt][half * 2 + 0];
                const float a2y = acc2[mt][nt][half * 2 + 1];
                const int xid = xids[r];
                const float2 ez  = *reinterpret_cast<const float2*>(&g_Ez[(size_t)xid * H_ + col]);
                const float2 eh  = *reinterpret_cast<const float2*>(&g_Eh[(size_t)xid * H_ + col]);
                const float2 bzv = *reinterpret_cast<const float2*>(&bz[col]);
                const float2 bhv = *reinterpret_cast<const float2*>(&bhb[col]);
                float sh0 = 0.f, sh1 = 0.f;
                if (!first) {
                    const uint32_t shh = *reinterpret_cast<const uint32_t*>(&g_sh_hi[(size_t)r * H_ + col]);
                    const uint32_t shl = *reinterpret_cast<const uint32_t*>(&g_sh_lo[(size_t)r * H_ + col]);
                    const float2 sh_h = unpack_bf2(shh);
                    const float2 sh_l = unpack_bf2(shl);
                    sh0 = sh_h.x + sh_l.x;
                    sh1 = sh_h.y + sh_l.y;
                }
                const float z0 = sigf(ez.x + bzv.x + a1x);
                const float z1 = sigf(ez.y + bzv.y + a1y);
                const float p0 = tanhf(eh.x + bhv.x + a2x);
                const float p1 = tanhf(eh.y + bhv.y + a2y);
                const float o0 = (1.0f - z0) * sh0 + z0 * p0;
                const float o1 = (1.0f - z1) * sh1 + z1 * p1;
                *reinterpret_cast<float2*>(&hout[(size_t)r * H_ + col]) = make_float2(o0, o1);
                const uint32_t soff = (uint32_t)(lr * NH_STRIDE + col) * 2;
                __nv_bfloat162 hp; hp.x = __float2bfloat16(o0); hp.y = __float2bfloat16(o1);
                *reinterpret_cast<__nv_bfloat162*>(dsm + NH_HI + soff) = hp;
                __nv_bfloat162 lp;
                lp.x = __float2bfloat16(o0 - __bfloat162float(hp.x));
                lp.y = __float2bfloat16(o1 - __bfloat162float(hp.y));
                *reinterpret_cast<__nv_bfloat162*>(dsm + NH_LO + soff) = lp;
            }
        }
    }

    // pass3: hU = new_h @ Ur (A from smem)
    float acc3[2][4][4] = {};
    pass_U(acc3, sbase);

#pragma unroll
    for (int mt = 0; mt < 2; ++mt) {
#pragma unroll
        for (int nt = 0; nt < 4; ++nt) {
            const int col = warp_n * 32 + nt * 8 + (lane & 3) * 2;
            const int r0  = rowBase + warp_m * 32 + mt * 16 + (lane >> 2);
            *reinterpret_cast<float2*>(&hUout[(size_t)r0 * H_ + col]) =
                make_float2(acc3[mt][nt][0], acc3[mt][nt][1]);
            *reinterpret_cast<float2*>(&hUout[(size_t)(r0 + 8) * H_ + col]) =
                make_float2(acc3[mt][nt][2], acc3[mt][nt][3]);
        }
    }
}

// ---------------- fused root aggregate ----------------------------------------
__global__ void root_fused(const float* __restrict__ h, const int* __restrict__ rnei,
                           const int* __restrict__ rwid, const float* __restrict__ Woh,
                           const float* __restrict__ bo, float* __restrict__ out)
{
    __shared__ float s_sum[256];
    __shared__ int sj[NB_];
    const int b = blockIdx.x;
    const int c = threadIdx.x;
    if (c < NB_) sj[c] = rnei[b * NB_ + c];
    __syncthreads();
    float s = 0.f;
#pragma unroll
    for (int n = 0; n < NB_; ++n)
        s += h[(size_t)sj[n] * 256 + c];
    s_sum[c] = s;
    __syncthreads();
    float acc = 0.f;
#pragma unroll 8
    for (int k = 0; k < 256; ++k)
        acc += s_sum[k] * Woh[(size_t)k * 256 + c];
    const int xid = rwid[b];
    float v = g_Eo[(size_t)xid * 256 + c] + bo[c] + acc;
    out[(size_t)b * 256 + c] = fmaxf(v, 0.0f);
}

// ---------------- launch ------------------------------------------------------
extern "C" void kernel_launch(void* const* d_in, const int* in_sizes, int n_in,
                              void* d_out, int out_size)
{
    const int*   x_ids    = (const int*)  d_in[0];
    const int*   nei_idx  = (const int*)  d_in[1];
    const int*   root_wid = (const int*)  d_in[2];
    const int*   root_nei = (const int*)  d_in[3];
    const float* emb      = (const float*)d_in[4];
    const float* Wz       = (const float*)d_in[5];
    const float* bz       = (const float*)d_in[6];
    const float* Wr       = (const float*)d_in[7];
    const float* Ur       = (const float*)d_in[8];
    const float* bur      = (const float*)d_in[9];
    const float* Wh       = (const float*)d_in[10];
    const float* bh       = (const float*)d_in[11];
    const float* Wo       = (const float*)d_in[12];
    const float* bo       = (const float*)d_in[13];

    float* out  = (float*)d_out;
    float* h    = out;
    float* rvec = out + (size_t)(M_ + 1) * H_;

    float* p_hU;
    cudaGetSymbolAddress((void**)&p_hU, g_hU);

    cudaFuncSetAttribute(step_mma, cudaFuncAttributeMaxDynamicSharedMemorySize, SM_TOTAL);

    init_zero<<<1, 256>>>(h);

    dim3 gpre(4, (V_ + 63) / 64, 4);
    gemm_pre<<<gpre, 256>>>(emb, Wz, Wr, Wh, Wo);
    split3<<<dim3(256, 3), 256>>>(Wz, Wh, Ur);

    for (int t = 0; t < T_; ++t) {
        if (t > 0)
            gather_step<<<E_ / 4, 256>>>(h, nei_idx + (size_t)t * E_ * NB_,
                                         x_ids + (size_t)t * E_, bur);
        step_mma<<<E_ / 64, 512, SM_TOTAL>>>(
            bz, bh, x_ids + (size_t)t * E_,
            h + (size_t)(1 + t * E_) * H_,
            p_hU + (size_t)(1 + t * E_) * H_,
            (t == 0) ? 1 : 0);
    }

    root_fused<<<B_, 256>>>(h, root_nei, root_wid, Wo + (size_t)H_ * H_, bo, rvec);
}

// round 9
// speedup vs baseline: 2.0382x; 1.2090x over previous
#include <cuda_runtime.h>
#include <cuda_fp16.h>
#include <math.h>
#include <stdint.h>

#define T_  12
#define E_  8192
#define H_  256
#define V_  800
#define B_  256
#define NB_ 8
#define M_  (T_*E_)   // 98304 messages; h has 1+M rows (row 0 = pad)

// ---------------- scratch (static device arrays; no allocs allowed) ----------
__device__ float g_hU[(size_t)(M_+1)*H_];
__device__ float g_Ez[(size_t)V_*H_];
__device__ float g_Er[(size_t)V_*H_];
__device__ float g_Eh[(size_t)V_*H_];
__device__ float g_Eo[(size_t)V_*H_];

// fp16 operands: activations single, sum_h also keeps a lo part for the epilogue
__device__ __half g_sh_hi[(size_t)E_*H_], g_sh_lo[(size_t)E_*H_];
__device__ __half g_sg   [(size_t)E_*H_];
__device__ __half g_Wzh_hi[H_*H_], g_Wzh_lo[H_*H_];
__device__ __half g_Whh_hi[H_*H_], g_Whh_lo[H_*H_];
__device__ __half g_Ur_hi [H_*H_], g_Ur_lo [H_*H_];

// fast sigmoid: ex2.approx (via __expf) + rcp.approx
__device__ __forceinline__ float sigf(float x) {
    float d = 1.0f + __expf(-x);
    float r;
    asm("rcp.approx.ftz.f32 %0, %1;" : "=f"(r) : "f"(d));
    return r;
}

// ---------------- PTX helpers -------------------------------------------------
__device__ __forceinline__ uint32_t smem_u32(const void* p) {
    return (uint32_t)__cvta_generic_to_shared(p);
}
__device__ __forceinline__ void ldsm4(uint32_t* r, uint32_t a) {
    asm volatile("ldmatrix.sync.aligned.m8n8.x4.shared.b16 {%0,%1,%2,%3},[%4];\n"
                 : "=r"(r[0]), "=r"(r[1]), "=r"(r[2]), "=r"(r[3]) : "r"(a));
}
__device__ __forceinline__ void ldsm4t(uint32_t* r, uint32_t a) {
    asm volatile("ldmatrix.sync.aligned.m8n8.x4.trans.shared.b16 {%0,%1,%2,%3},[%4];\n"
                 : "=r"(r[0]), "=r"(r[1]), "=r"(r[2]), "=r"(r[3]) : "r"(a));
}
__device__ __forceinline__ void mma16816(float* d, const uint32_t* a, const uint32_t* b) {
    asm volatile("mma.sync.aligned.m16n8k16.row.col.f32.f16.f16.f32 "
                 "{%0,%1,%2,%3},{%4,%5,%6,%7},{%8,%9},{%0,%1,%2,%3};\n"
                 : "+f"(d[0]), "+f"(d[1]), "+f"(d[2]), "+f"(d[3])
                 : "r"(a[0]), "r"(a[1]), "r"(a[2]), "r"(a[3]), "r"(b[0]), "r"(b[1]));
}
__device__ __forceinline__ void cpa16(uint32_t dst, const void* src) {
    asm volatile("cp.async.cg.shared.global [%0],[%1],16;\n" :: "r"(dst), "l"(src));
}
#define CP_COMMIT()  asm volatile("cp.async.commit_group;\n" ::: "memory")
#define CP_WAIT1()   asm volatile("cp.async.wait_group 1;\n" ::: "memory")

__device__ __forceinline__ uint32_t pack_h2(float a, float b) {
    __half2 t; t.x = __float2half_rn(a); t.y = __float2half_rn(b);
    return *reinterpret_cast<uint32_t*>(&t);
}
__device__ __forceinline__ float2 unpack_h2(uint32_t u) {
    __half2 t = *reinterpret_cast<__half2*>(&u);
    return make_float2(__half2float(t.x), __half2float(t.y));
}

// ---------------- init --------------------------------------------------------
__global__ void init_zero(float* __restrict__ h)
{
    int c = threadIdx.x;
    h[c]    = 0.0f;
    g_hU[c] = 0.0f;
}

// ---------------- preamble: 4 embedding projections in one launch -------------
__global__ void gemm_pre(const float* __restrict__ emb,
                         const float* __restrict__ Wz, const float* __restrict__ Wr,
                         const float* __restrict__ Wh, const float* __restrict__ Wo)
{
    const float* Bw; float* C;
    switch (blockIdx.z) {
        case 0:  Bw = Wz; C = g_Ez; break;
        case 1:  Bw = Wr; C = g_Er; break;
        case 2:  Bw = Wh; C = g_Eh; break;
        default: Bw = Wo; C = g_Eo; break;
    }
    __shared__ float As[16][64];
    __shared__ float Bs[16][64];
    const int tid = threadIdx.x;
    const int tx = tid & 15, ty = tid >> 4;
    const int rowBase = blockIdx.y * 64;
    const int colBase = blockIdx.x * 64;
    const int lm  = tid >> 2;
    const int lk  = (tid & 3) * 4;
    const int blk = tid >> 4;
    const int bln = (tid & 15) * 4;
    float acc[4][4] = {};
    for (int kb = 0; kb < 256; kb += 16) {
        int ar = rowBase + lm;
        float4 av = make_float4(0.f, 0.f, 0.f, 0.f);
        if (ar < V_)
            av = *reinterpret_cast<const float4*>(&emb[(size_t)ar * 256 + kb + lk]);
        As[lk + 0][lm] = av.x; As[lk + 1][lm] = av.y;
        As[lk + 2][lm] = av.z; As[lk + 3][lm] = av.w;
        float4 bv = *reinterpret_cast<const float4*>(&Bw[(size_t)(kb + blk) * 256 + colBase + bln]);
        *reinterpret_cast<float4*>(&Bs[blk][bln]) = bv;
        __syncthreads();
#pragma unroll
        for (int k = 0; k < 16; ++k) {
            float4 a4 = *reinterpret_cast<const float4*>(&As[k][ty * 4]);
            float4 b4 = *reinterpret_cast<const float4*>(&Bs[k][tx * 4]);
            float aa[4] = {a4.x, a4.y, a4.z, a4.w};
            float bb[4] = {b4.x, b4.y, b4.z, b4.w};
#pragma unroll
            for (int i = 0; i < 4; ++i)
#pragma unroll
                for (int j = 0; j < 4; ++j)
                    acc[i][j] += aa[i] * bb[j];
        }
        __syncthreads();
    }
#pragma unroll
    for (int i = 0; i < 4; ++i) {
        int r = rowBase + ty * 4 + i;
        if (r < V_)
            *reinterpret_cast<float4*>(&C[(size_t)r * 256 + colBase + tx * 4]) =
                make_float4(acc[i][0], acc[i][1], acc[i][2], acc[i][3]);
    }
}

// ---------------- preamble: 3 weight splits (fp16 hi/lo) ----------------------
__global__ void split3(const float* __restrict__ Wz, const float* __restrict__ Wh,
                       const float* __restrict__ Ur)
{
    const float* W; __half *hi, *lo;
    switch (blockIdx.y) {
        case 0:  W = Wz + H_ * H_; hi = g_Wzh_hi; lo = g_Wzh_lo; break;
        case 1:  W = Wh + H_ * H_; hi = g_Whh_hi; lo = g_Whh_lo; break;
        default: W = Ur;           hi = g_Ur_hi;  lo = g_Ur_lo;  break;
    }
    int i = blockIdx.x * 256 + threadIdx.x;
    float v = W[i];
    __half h = __float2half_rn(v);
    hi[i] = h;
    lo[i] = __float2half_rn(v - __half2float(h));
}

// ---------------- per-step gather -> fp16 outputs ------------------------------
__global__ void gather_step(const float* __restrict__ h,
                            const int*   __restrict__ nei,
                            const int*   __restrict__ xids,
                            const float* __restrict__ bur)
{
    const int msg = blockIdx.x * 4 + (threadIdx.x >> 6);
    const int c4  = threadIdx.x & 63;

    const int xid = xids[msg];
    const float4 bu = reinterpret_cast<const float4*>(bur)[c4];
    const float4 er = reinterpret_cast<const float4*>(&g_Er[(size_t)xid * H_])[c4];
    const float bx = er.x + bu.x, by = er.y + bu.y, bz2 = er.z + bu.z, bw = er.w + bu.w;

    float4 sh = make_float4(0.f, 0.f, 0.f, 0.f);
    float4 sg = make_float4(0.f, 0.f, 0.f, 0.f);
#pragma unroll
    for (int n = 0; n < NB_; ++n) {
        const int j = nei[msg * NB_ + n];
        const float4 hv = reinterpret_cast<const float4*>(h)[(size_t)j * 64 + c4];
        const float4 uv = reinterpret_cast<const float4*>(g_hU)[(size_t)j * 64 + c4];
        sh.x += hv.x; sh.y += hv.y; sh.z += hv.z; sh.w += hv.w;
        sg.x += sigf(bx  + uv.x) * hv.x;
        sg.y += sigf(by  + uv.y) * hv.y;
        sg.z += sigf(bz2 + uv.z) * hv.z;
        sg.w += sigf(bw  + uv.w) * hv.w;
    }
    const size_t o4 = (size_t)msg * 64 + c4;
    {
        __half h0 = __float2half_rn(sh.x), h1 = __float2half_rn(sh.y),
               h2 = __float2half_rn(sh.z), h3 = __float2half_rn(sh.w);
        uint2 u;
        { __half2 a; a.x = h0; a.y = h1; u.x = *reinterpret_cast<uint32_t*>(&a); }
        { __half2 a; a.x = h2; a.y = h3; u.y = *reinterpret_cast<uint32_t*>(&a); }
        reinterpret_cast<uint2*>(g_sh_hi)[o4] = u;
        uint2 v;
        v.x = pack_h2(sh.x - __half2float(h0), sh.y - __half2float(h1));
        v.y = pack_h2(sh.z - __half2float(h2), sh.w - __half2float(h3));
        reinterpret_cast<uint2*>(g_sh_lo)[o4] = v;
    }
    {
        uint2 u;
        u.x = pack_h2(sg.x, sg.y);
        u.y = pack_h2(sg.z, sg.w);
        reinterpret_cast<uint2*>(g_sg)[o4] = u;
    }
}

// ---------------- fused step GEMM: BM=64, BN=256, 512 threads -----------------
// 16 warps = 2(M) x 8(N); warp tile 32x32. 2-term fp16: A*Whi + A*Wlo.
#define A_STRIDE  40     // 32 + 8 pad (fp16)
#define BW_STRIDE 264    // 256 + 8 pad
#define NH_STRIDE 264

#define ST_A     0                // 64*40*2      = 5120
#define ST_B_HI  5120             // 32*264*2     = 16896
#define ST_B_LO  22016
#define ST_SZ    38912
#define P_SZ     (2*ST_SZ)        // 77824
#define U_LO     16896
#define U_ST_SZ  33792            // hi + lo
#define NH_OFF   P_SZ             // 77824, size 64*264*2 = 33792
#define SM_TOTAL (P_SZ + 33792)   // 111616 bytes

// pass over K=256: acc += A(fp16) @ (Bhi + Blo), A/B from global
__device__ __forceinline__ void pass_AB(
    const __half* __restrict__ A,
    const __half* __restrict__ Bhi, const __half* __restrict__ Blo,
    int rowBase, float acc[2][4][4], uint32_t sbase)
{
    const int tid  = threadIdx.x;
    const int lane = tid & 31;
    const int wid  = tid >> 5;
    const int warp_m = wid & 1;
    const int warp_n = wid >> 1;   // 0..7

    // A: 256 threads do one cpa16 each (64 rows x 32 halves)
    const bool doA  = tid < 256;
    const int  arow = (tid & 255) >> 2;
    const int  ak   = (tid & 3) * 8;
    const uint32_t a_soff = ST_A + (uint32_t)(arow * A_STRIDE + ak) * 2;
    const size_t a_goff = (size_t)(rowBase + arow) * 256 + ak;

    // B: [32 k, 256 n]; 2 cpa16/thread per buffer
    const int brow = tid >> 4;           // 0..31
    const int bcol = (tid & 15) * 8;     // 0..120
    const uint32_t b_soff0 = (uint32_t)(brow * BW_STRIDE + bcol) * 2;
    const uint32_t b_soff1 = (uint32_t)(brow * BW_STRIDE + bcol + 128) * 2;
    const size_t b_goff = (size_t)brow * 256 + bcol;

    if (doA) cpa16(sbase + a_soff, &A[a_goff]);
    cpa16(sbase + ST_B_HI + b_soff0, &Bhi[b_goff]);
    cpa16(sbase + ST_B_HI + b_soff1, &Bhi[b_goff + 128]);
    cpa16(sbase + ST_B_LO + b_soff0, &Blo[b_goff]);
    cpa16(sbase + ST_B_LO + b_soff1, &Blo[b_goff + 128]);
    CP_COMMIT();

    for (int it = 0; it < 8; ++it) {
        const uint32_t scur = sbase + (uint32_t)(it & 1) * ST_SZ;
        __syncthreads();
        if (it < 7) {
            const uint32_t snxt = sbase + (uint32_t)((it + 1) & 1) * ST_SZ;
            const int kb = (it + 1) * 32;
            if (doA) cpa16(snxt + a_soff, &A[a_goff + kb]);
            cpa16(snxt + ST_B_HI + b_soff0, &Bhi[b_goff + (size_t)kb * 256]);
            cpa16(snxt + ST_B_HI + b_soff1, &Bhi[b_goff + (size_t)kb * 256 + 128]);
            cpa16(snxt + ST_B_LO + b_soff0, &Blo[b_goff + (size_t)kb * 256]);
            cpa16(snxt + ST_B_LO + b_soff1, &Blo[b_goff + (size_t)kb * 256 + 128]);
        }
        CP_COMMIT();
        CP_WAIT1();
        __syncthreads();

#pragma unroll
        for (int ks = 0; ks < 32; ks += 16) {
            uint32_t a_[2][4];
#pragma unroll
            for (int mt = 0; mt < 2; ++mt) {
                const int el = (warp_m * 32 + mt * 16 + (lane & 15)) * A_STRIDE
                             + ks + (lane >> 4) * 8;
                ldsm4(a_[mt], scur + ST_A + el * 2);
            }
#pragma unroll
            for (int np = 0; np < 2; ++np) {
                const int n0 = warp_n * 32 + np * 16;
                const int el = (ks + (lane & 7) + ((lane >> 3) & 1) * 8) * BW_STRIDE
                             + n0 + (lane >> 4) * 8;
                uint32_t bh_[4], bl_[4];
                ldsm4t(bh_, scur + ST_B_HI + el * 2);
                ldsm4t(bl_, scur + ST_B_LO + el * 2);
#pragma unroll
                for (int mt = 0; mt < 2; ++mt) {
#pragma unroll
                    for (int s = 0; s < 2; ++s) {
                        float* d = acc[mt][np * 2 + s];
                        mma16816(d, a_[mt], &bh_[2 * s]);
                        mma16816(d, a_[mt], &bl_[2 * s]);
                    }
                }
            }
        }
    }
}

// pass3: acc += new_h(smem fp16) @ (Ur_hi + Ur_lo)
__device__ __forceinline__ void pass_U(float acc[2][4][4], uint32_t sbase)
{
    const int tid  = threadIdx.x;
    const int lane = tid & 31;
    const int wid  = tid >> 5;
    const int warp_m = wid & 1;
    const int warp_n = wid >> 1;

    const int brow = tid >> 4;
    const int bcol = (tid & 15) * 8;
    const uint32_t b_soff0 = (uint32_t)(brow * BW_STRIDE + bcol) * 2;
    const uint32_t b_soff1 = (uint32_t)(brow * BW_STRIDE + bcol + 128) * 2;
    const size_t b_goff = (size_t)brow * 256 + bcol;

    cpa16(sbase + b_soff0,        &g_Ur_hi[b_goff]);
    cpa16(sbase + b_soff1,        &g_Ur_hi[b_goff + 128]);
    cpa16(sbase + U_LO + b_soff0, &g_Ur_lo[b_goff]);
    cpa16(sbase + U_LO + b_soff1, &g_Ur_lo[b_goff + 128]);
    CP_COMMIT();

    for (int it = 0; it < 8; ++it) {
        const uint32_t scur = sbase + (uint32_t)(it & 1) * U_ST_SZ;
        __syncthreads();
        if (it < 7) {
            const uint32_t snxt = sbase + (uint32_t)((it + 1) & 1) * U_ST_SZ;
            const int kb = (it + 1) * 32;
            cpa16(snxt + b_soff0,        &g_Ur_hi[b_goff + (size_t)kb * 256]);
            cpa16(snxt + b_soff1,        &g_Ur_hi[b_goff + (size_t)kb * 256 + 128]);
            cpa16(snxt + U_LO + b_soff0, &g_Ur_lo[b_goff + (size_t)kb * 256]);
            cpa16(snxt + U_LO + b_soff1, &g_Ur_lo[b_goff + (size_t)kb * 256 + 128]);
        }
        CP_COMMIT();
        CP_WAIT1();
        __syncthreads();

        const int kb = it * 32;
#pragma unroll
        for (int ks = 0; ks < 32; ks += 16) {
            uint32_t a_[2][4];
#pragma unroll
            for (int mt = 0; mt < 2; ++mt) {
                const int el = (warp_m * 32 + mt * 16 + (lane & 15)) * NH_STRIDE
                             + kb + ks + (lane >> 4) * 8;
                ldsm4(a_[mt], sbase + NH_OFF + el * 2);
            }
#pragma unroll
            for (int np = 0; np < 2; ++np) {
                const int n0 = warp_n * 32 + np * 16;
                const int el = (ks + (lane & 7) + ((lane >> 3) & 1) * 8) * BW_STRIDE
                             + n0 + (lane >> 4) * 8;
                uint32_t bh_[4], bl_[4];
                ldsm4t(bh_, scur + el * 2);
                ldsm4t(bl_, scur + U_LO + el * 2);
#pragma unroll
                for (int mt = 0; mt < 2; ++mt) {
#pragma unroll
                    for (int s = 0; s < 2; ++s) {
                        float* d = acc[mt][np * 2 + s];
                        mma16816(d, a_[mt], &bh_[2 * s]);
                        mma16816(d, a_[mt], &bl_[2 * s]);
                    }
                }
            }
        }
    }
}

__global__ void __launch_bounds__(512, 1) step_mma(
    const float* __restrict__ bz, const float* __restrict__ bhb,
    const int*   __restrict__ xids,
    float* __restrict__ hout, float* __restrict__ hUout, int first)
{
    extern __shared__ char dsm[];
    const uint32_t sbase = smem_u32(dsm);
    const int rowBase = blockIdx.x * 64;

    float acc1[2][4][4] = {};
    float acc2[2][4][4] = {};
    if (!first) {
        pass_AB(g_sh_hi, g_Wzh_hi, g_Wzh_lo, rowBase, acc1, sbase);
        pass_AB(g_sg,    g_Whh_hi, g_Whh_lo, rowBase, acc2, sbase);
    }

    const int lane = threadIdx.x & 31;
    const int wid  = threadIdx.x >> 5;
    const int warp_m = wid & 1, warp_n = wid >> 1;

    // GRU epilogue -> hout (global fp32) + new_h fp16 into smem (NH region)
#pragma unroll
    for (int mt = 0; mt < 2; ++mt) {
#pragma unroll
        for (int nt = 0; nt < 4; ++nt) {
            const int col = warp_n * 32 + nt * 8 + (lane & 3) * 2;
#pragma unroll
            for (int half = 0; half < 2; ++half) {
                const int lr = warp_m * 32 + mt * 16 + (lane >> 2) + half * 8;
                const int r  = rowBase + lr;
                const float a1x = acc1[mt][nt][half * 2 + 0];
                const float a1y = acc1[mt][nt][half * 2 + 1];
                const float a2x = acc2[mt][nt][half * 2 + 0];
                const float a2y = acc2[mt][nt][half * 2 + 1];
                const int xid = xids[r];
                const float2 ez  = *reinterpret_cast<const float2*>(&g_Ez[(size_t)xid * H_ + col]);
                const float2 eh  = *reinterpret_cast<const float2*>(&g_Eh[(size_t)xid * H_ + col]);
                const float2 bzv = *reinterpret_cast<const float2*>(&bz[col]);
                const float2 bhv = *reinterpret_cast<const float2*>(&bhb[col]);
                float sh0 = 0.f, sh1 = 0.f;
                if (!first) {
                    const uint32_t shh = *reinterpret_cast<const uint32_t*>(&g_sh_hi[(size_t)r * H_ + col]);
                    const uint32_t shl = *reinterpret_cast<const uint32_t*>(&g_sh_lo[(size_t)r * H_ + col]);
                    const float2 sh_h = unpack_h2(shh);
                    const float2 sh_l = unpack_h2(shl);
                    sh0 = sh_h.x + sh_l.x;
                    sh1 = sh_h.y + sh_l.y;
                }
                const float z0 = sigf(ez.x + bzv.x + a1x);
                const float z1 = sigf(ez.y + bzv.y + a1y);
                const float p0 = tanhf(eh.x + bhv.x + a2x);
                const float p1 = tanhf(eh.y + bhv.y + a2y);
                const float o0 = (1.0f - z0) * sh0 + z0 * p0;
                const float o1 = (1.0f - z1) * sh1 + z1 * p1;
                *reinterpret_cast<float2*>(&hout[(size_t)r * H_ + col]) = make_float2(o0, o1);
                const uint32_t soff = (uint32_t)(lr * NH_STRIDE + col) * 2;
                __half2 hp; hp.x = __float2half_rn(o0); hp.y = __float2half_rn(o1);
                *reinterpret_cast<__half2*>(dsm + NH_OFF + soff) = hp;
            }
        }
    }

    // pass3: hU = new_h @ Ur (A from smem)
    float acc3[2][4][4] = {};
    pass_U(acc3, sbase);

#pragma unroll
    for (int mt = 0; mt < 2; ++mt) {
#pragma unroll
        for (int nt = 0; nt < 4; ++nt) {
            const int col = warp_n * 32 + nt * 8 + (lane & 3) * 2;
            const int r0  = rowBase + warp_m * 32 + mt * 16 + (lane >> 2);
            *reinterpret_cast<float2*>(&hUout[(size_t)r0 * H_ + col]) =
                make_float2(acc3[mt][nt][0], acc3[mt][nt][1]);
            *reinterpret_cast<float2*>(&hUout[(size_t)(r0 + 8) * H_ + col]) =
                make_float2(acc3[mt][nt][2], acc3[mt][nt][3]);
        }
    }
}

// ---------------- fused root aggregate ----------------------------------------
__global__ void root_fused(const float* __restrict__ h, const int* __restrict__ rnei,
                           const int* __restrict__ rwid, const float* __restrict__ Woh,
                           const float* __restrict__ bo, float* __restrict__ out)
{
    __shared__ float s_sum[256];
    __shared__ int sj[NB_];
    const int b = blockIdx.x;
    const int c = threadIdx.x;
    if (c < NB_) sj[c] = rnei[b * NB_ + c];
    __syncthreads();
    float s = 0.f;
#pragma unroll
    for (int n = 0; n < NB_; ++n)
        s += h[(size_t)sj[n] * 256 + c];
    s_sum[c] = s;
    __syncthreads();
    float acc = 0.f;
#pragma unroll 8
    for (int k = 0; k < 256; ++k)
        acc += s_sum[k] * Woh[(size_t)k * 256 + c];
    const int xid = rwid[b];
    float v = g_Eo[(size_t)xid * 256 + c] + bo[c] + acc;
    out[(size_t)b * 256 + c] = fmaxf(v, 0.0f);
}

// ---------------- launch ------------------------------------------------------
extern "C" void kernel_launch(void* const* d_in, const int* in_sizes, int n_in,
                              void* d_out, int out_size)
{
    const int*   x_ids    = (const int*)  d_in[0];
    const int*   nei_idx  = (const int*)  d_in[1];
    const int*   root_wid = (const int*)  d_in[2];
    const int*   root_nei = (const int*)  d_in[3];
    const float* emb      = (const float*)d_in[4];
    const float* Wz       = (const float*)d_in[5];
    const float* bz       = (const float*)d_in[6];
    const float* Wr       = (const float*)d_in[7];
    const float* Ur       = (const float*)d_in[8];
    const float* bur      = (const float*)d_in[9];
    const float* Wh       = (const float*)d_in[10];
    const float* bh       = (const float*)d_in[11];
    const float* Wo       = (const float*)d_in[12];
    const float* bo       = (const float*)d_in[13];

    float* out  = (float*)d_out;
    float* h    = out;
    float* rvec = out + (size_t)(M_ + 1) * H_;

    float* p_hU;
    cudaGetSymbolAddress((void**)&p_hU, g_hU);

    cudaFuncSetAttribute(step_mma, cudaFuncAttributeMaxDynamicSharedMemorySize, SM_TOTAL);

    init_zero<<<1, 256>>>(h);

    dim3 gpre(4, (V_ + 63) / 64, 4);
    gemm_pre<<<gpre, 256>>>(emb, Wz, Wr, Wh, Wo);
    split3<<<dim3(256, 3), 256>>>(Wz, Wh, Ur);

    for (int t = 0; t < T_; ++t) {
        if (t > 0)
            gather_step<<<E_ / 4, 256>>>(h, nei_idx + (size_t)t * E_ * NB_,
                                         x_ids + (size_t)t * E_, bur);
        step_mma<<<E_ / 64, 512, SM_TOTAL>>>(
            bz, bh, x_ids + (size_t)t * E_,
            h + (size_t)(1 + t * E_) * H_,
            p_hU + (size_t)(1 + t * E_) * H_,
            (t == 0) ? 1 : 0);
    }

    root_fused<<<B_, 256>>>(h, root_nei, root_wid, Wo + (size_t)H_ * H_, bo, rvec);
}

// round 10
// speedup vs baseline: 2.1352x; 1.0476x over previous
#include <cuda_runtime.h>
#include <cuda_fp16.h>
#include <math.h>
#include <stdint.h>

#define T_  12
#define E_  8192
#define H_  256
#define V_  800
#define B_  256
#define NB_ 8
#define M_  (T_*E_)   // 98304 messages; h has 1+M rows (row 0 = pad)

// ---------------- scratch (static device arrays; no allocs allowed) ----------
__device__ __half g_hU16[(size_t)(M_+1)*H_];   // h @ Ur, fp16 (sigmoid arg only)
__device__ float g_Ez[(size_t)V_*H_];
__device__ float g_Er[(size_t)V_*H_];
__device__ float g_Eh[(size_t)V_*H_];
__device__ float g_Eo[(size_t)V_*H_];

// fp16 operands: activations single, sum_h also keeps a lo part for the epilogue
__device__ __half g_sh_hi[(size_t)E_*H_], g_sh_lo[(size_t)E_*H_];
__device__ __half g_sg   [(size_t)E_*H_];
__device__ __half g_Wzh_hi[H_*H_], g_Wzh_lo[H_*H_];
__device__ __half g_Whh_hi[H_*H_], g_Whh_lo[H_*H_];
__device__ __half g_Ur_hi [H_*H_], g_Ur_lo [H_*H_];

// fast sigmoid: ex2.approx (via __expf) + rcp.approx
__device__ __forceinline__ float sigf(float x) {
    float d = 1.0f + __expf(-x);
    float r;
    asm("rcp.approx.ftz.f32 %0, %1;" : "=f"(r) : "f"(d));
    return r;
}

// ---------------- PTX helpers -------------------------------------------------
__device__ __forceinline__ uint32_t smem_u32(const void* p) {
    return (uint32_t)__cvta_generic_to_shared(p);
}
__device__ __forceinline__ void ldsm4(uint32_t* r, uint32_t a) {
    asm volatile("ldmatrix.sync.aligned.m8n8.x4.shared.b16 {%0,%1,%2,%3},[%4];\n"
                 : "=r"(r[0]), "=r"(r[1]), "=r"(r[2]), "=r"(r[3]) : "r"(a));
}
__device__ __forceinline__ void ldsm4t(uint32_t* r, uint32_t a) {
    asm volatile("ldmatrix.sync.aligned.m8n8.x4.trans.shared.b16 {%0,%1,%2,%3},[%4];\n"
                 : "=r"(r[0]), "=r"(r[1]), "=r"(r[2]), "=r"(r[3]) : "r"(a));
}
__device__ __forceinline__ void mma16816(float* d, const uint32_t* a, const uint32_t* b) {
    asm volatile("mma.sync.aligned.m16n8k16.row.col.f32.f16.f16.f32 "
                 "{%0,%1,%2,%3},{%4,%5,%6,%7},{%8,%9},{%0,%1,%2,%3};\n"
                 : "+f"(d[0]), "+f"(d[1]), "+f"(d[2]), "+f"(d[3])
                 : "r"(a[0]), "r"(a[1]), "r"(a[2]), "r"(a[3]), "r"(b[0]), "r"(b[1]));
}
__device__ __forceinline__ void cpa16(uint32_t dst, const void* src) {
    asm volatile("cp.async.cg.shared.global [%0],[%1],16;\n" :: "r"(dst), "l"(src));
}
#define CP_COMMIT()  asm volatile("cp.async.commit_group;\n" ::: "memory")
#define CP_WAIT1()   asm volatile("cp.async.wait_group 1;\n" ::: "memory")

__device__ __forceinline__ uint32_t pack_h2(float a, float b) {
    __half2 t; t.x = __float2half_rn(a); t.y = __float2half_rn(b);
    return *reinterpret_cast<uint32_t*>(&t);
}
__device__ __forceinline__ float2 unpack_h2(uint32_t u) {
    __half2 t = *reinterpret_cast<__half2*>(&u);
    return make_float2(__half2float(t.x), __half2float(t.y));
}

// ---------------- init --------------------------------------------------------
__global__ void init_zero(float* __restrict__ h)
{
    int c = threadIdx.x;
    h[c]      = 0.0f;
    g_hU16[c] = __float2half_rn(0.0f);
}

// ---------------- preamble: 4 embedding projections in one launch -------------
__global__ void gemm_pre(const float* __restrict__ emb,
                         const float* __restrict__ Wz, const float* __restrict__ Wr,
                         const float* __restrict__ Wh, const float* __restrict__ Wo)
{
    const float* Bw; float* C;
    switch (blockIdx.z) {
        case 0:  Bw = Wz; C = g_Ez; break;
        case 1:  Bw = Wr; C = g_Er; break;
        case 2:  Bw = Wh; C = g_Eh; break;
        default: Bw = Wo; C = g_Eo; break;
    }
    __shared__ float As[16][64];
    __shared__ float Bs[16][64];
    const int tid = threadIdx.x;
    const int tx = tid & 15, ty = tid >> 4;
    const int rowBase = blockIdx.y * 64;
    const int colBase = blockIdx.x * 64;
    const int lm  = tid >> 2;
    const int lk  = (tid & 3) * 4;
    const int blk = tid >> 4;
    const int bln = (tid & 15) * 4;
    float acc[4][4] = {};
    for (int kb = 0; kb < 256; kb += 16) {
        int ar = rowBase + lm;
        float4 av = make_float4(0.f, 0.f, 0.f, 0.f);
        if (ar < V_)
            av = *reinterpret_cast<const float4*>(&emb[(size_t)ar * 256 + kb + lk]);
        As[lk + 0][lm] = av.x; As[lk + 1][lm] = av.y;
        As[lk + 2][lm] = av.z; As[lk + 3][lm] = av.w;
        float4 bv = *reinterpret_cast<const float4*>(&Bw[(size_t)(kb + blk) * 256 + colBase + bln]);
        *reinterpret_cast<float4*>(&Bs[blk][bln]) = bv;
        __syncthreads();
#pragma unroll
        for (int k = 0; k < 16; ++k) {
            float4 a4 = *reinterpret_cast<const float4*>(&As[k][ty * 4]);
            float4 b4 = *reinterpret_cast<const float4*>(&Bs[k][tx * 4]);
            float aa[4] = {a4.x, a4.y, a4.z, a4.w};
            float bb[4] = {b4.x, b4.y, b4.z, b4.w};
#pragma unroll
            for (int i = 0; i < 4; ++i)
#pragma unroll
                for (int j = 0; j < 4; ++j)
                    acc[i][j] += aa[i] * bb[j];
        }
        __syncthreads();
    }
#pragma unroll
    for (int i = 0; i < 4; ++i) {
        int r = rowBase + ty * 4 + i;
        if (r < V_)
            *reinterpret_cast<float4*>(&C[(size_t)r * 256 + colBase + tx * 4]) =
                make_float4(acc[i][0], acc[i][1], acc[i][2], acc[i][3]);
    }
}

// ---------------- preamble: 3 weight splits (fp16 hi/lo) ----------------------
__global__ void split3(const float* __restrict__ Wz, const float* __restrict__ Wh,
                       const float* __restrict__ Ur)
{
    const float* W; __half *hi, *lo;
    switch (blockIdx.y) {
        case 0:  W = Wz + H_ * H_; hi = g_Wzh_hi; lo = g_Wzh_lo; break;
        case 1:  W = Wh + H_ * H_; hi = g_Whh_hi; lo = g_Whh_lo; break;
        default: W = Ur;           hi = g_Ur_hi;  lo = g_Ur_lo;  break;
    }
    int i = blockIdx.x * 256 + threadIdx.x;
    float v = W[i];
    __half h = __float2half_rn(v);
    hi[i] = h;
    lo[i] = __float2half_rn(v - __half2float(h));
}

// ---------------- per-step gather -> fp16 outputs ------------------------------
__global__ void gather_step(const float* __restrict__ h,
                            const int*   __restrict__ nei,
                            const int*   __restrict__ xids,
                            const float* __restrict__ bur)
{
    const int msg = blockIdx.x * 4 + (threadIdx.x >> 6);
    const int c4  = threadIdx.x & 63;

    const int xid = xids[msg];
    const float4 bu = reinterpret_cast<const float4*>(bur)[c4];
    const float4 er = reinterpret_cast<const float4*>(&g_Er[(size_t)xid * H_])[c4];
    const float bx = er.x + bu.x, by = er.y + bu.y, bz2 = er.z + bu.z, bw = er.w + bu.w;

    float4 sh = make_float4(0.f, 0.f, 0.f, 0.f);
    float4 sg = make_float4(0.f, 0.f, 0.f, 0.f);
#pragma unroll
    for (int n = 0; n < NB_; ++n) {
        const int j = nei[msg * NB_ + n];
        const float4 hv = reinterpret_cast<const float4*>(h)[(size_t)j * 64 + c4];
        const uint2 up = reinterpret_cast<const uint2*>(g_hU16)[(size_t)j * 64 + c4];
        const float2 u01 = unpack_h2(up.x);
        const float2 u23 = unpack_h2(up.y);
        sh.x += hv.x; sh.y += hv.y; sh.z += hv.z; sh.w += hv.w;
        sg.x += sigf(bx  + u01.x) * hv.x;
        sg.y += sigf(by  + u01.y) * hv.y;
        sg.z += sigf(bz2 + u23.x) * hv.z;
        sg.w += sigf(bw  + u23.y) * hv.w;
    }
    const size_t o4 = (size_t)msg * 64 + c4;
    {
        __half h0 = __float2half_rn(sh.x), h1 = __float2half_rn(sh.y),
               h2 = __float2half_rn(sh.z), h3 = __float2half_rn(sh.w);
        uint2 u;
        { __half2 a; a.x = h0; a.y = h1; u.x = *reinterpret_cast<uint32_t*>(&a); }
        { __half2 a; a.x = h2; a.y = h3; u.y = *reinterpret_cast<uint32_t*>(&a); }
        reinterpret_cast<uint2*>(g_sh_hi)[o4] = u;
        uint2 v;
        v.x = pack_h2(sh.x - __half2float(h0), sh.y - __half2float(h1));
        v.y = pack_h2(sh.z - __half2float(h2), sh.w - __half2float(h3));
        reinterpret_cast<uint2*>(g_sh_lo)[o4] = v;
    }
    {
        uint2 u;
        u.x = pack_h2(sg.x, sg.y);
        u.y = pack_h2(sg.z, sg.w);
        reinterpret_cast<uint2*>(g_sg)[o4] = u;
    }
}

// ---------------- fused step GEMM: BM=64, BN=256, 512 threads -----------------
// 16 warps = 2(M) x 8(N); warp tile 32x32. 2-term fp16: A*Whi + A*Wlo.
#define A_STRIDE  40     // 32 + 8 pad (fp16)
#define BW_STRIDE 264    // 256 + 8 pad
#define NH_STRIDE 264

#define ST_A     0                // 64*40*2      = 5120
#define ST_B_HI  5120             // 32*264*2     = 16896
#define ST_B_LO  22016
#define ST_SZ    38912
#define P_SZ     (2*ST_SZ)        // 77824
#define U_LO     16896
#define U_ST_SZ  33792            // hi + lo
#define NH_OFF   P_SZ             // 77824, size 64*264*2 = 33792
#define SM_TOTAL (P_SZ + 33792)   // 111616 bytes

// pass over K=256: acc += A(fp16) @ (Bhi + Blo), A/B from global
__device__ __forceinline__ void pass_AB(
    const __half* __restrict__ A,
    const __half* __restrict__ Bhi, const __half* __restrict__ Blo,
    int rowBase, float acc[2][4][4], uint32_t sbase)
{
    const int tid  = threadIdx.x;
    const int lane = tid & 31;
    const int wid  = tid >> 5;
    const int warp_m = wid & 1;
    const int warp_n = wid >> 1;   // 0..7

    const bool doA  = tid < 256;
    const int  arow = (tid & 255) >> 2;
    const int  ak   = (tid & 3) * 8;
    const uint32_t a_soff = ST_A + (uint32_t)(arow * A_STRIDE + ak) * 2;
    const size_t a_goff = (size_t)(rowBase + arow) * 256 + ak;

    const int brow = tid >> 4;           // 0..31
    const int bcol = (tid & 15) * 8;     // 0..120
    const uint32_t b_soff0 = (uint32_t)(brow * BW_STRIDE + bcol) * 2;
    const uint32_t b_soff1 = (uint32_t)(brow * BW_STRIDE + bcol + 128) * 2;
    const size_t b_goff = (size_t)brow * 256 + bcol;

    if (doA) cpa16(sbase + a_soff, &A[a_goff]);
    cpa16(sbase + ST_B_HI + b_soff0, &Bhi[b_goff]);
    cpa16(sbase + ST_B_HI + b_soff1, &Bhi[b_goff + 128]);
    cpa16(sbase + ST_B_LO + b_soff0, &Blo[b_goff]);
    cpa16(sbase + ST_B_LO + b_soff1, &Blo[b_goff + 128]);
    CP_COMMIT();

    for (int it = 0; it < 8; ++it) {
        const uint32_t scur = sbase + (uint32_t)(it & 1) * ST_SZ;
        __syncthreads();
        if (it < 7) {
            const uint32_t snxt = sbase + (uint32_t)((it + 1) & 1) * ST_SZ;
            const int kb = (it + 1) * 32;
            if (doA) cpa16(snxt + a_soff, &A[a_goff + kb]);
            cpa16(snxt + ST_B_HI + b_soff0, &Bhi[b_goff + (size_t)kb * 256]);
            cpa16(snxt + ST_B_HI + b_soff1, &Bhi[b_goff + (size_t)kb * 256 + 128]);
            cpa16(snxt + ST_B_LO + b_soff0, &Blo[b_goff + (size_t)kb * 256]);
            cpa16(snxt + ST_B_LO + b_soff1, &Blo[b_goff + (size_t)kb * 256 + 128]);
        }
        CP_COMMIT();
        CP_WAIT1();
        __syncthreads();

#pragma unroll
        for (int ks = 0; ks < 32; ks += 16) {
            uint32_t a_[2][4];
#pragma unroll
            for (int mt = 0; mt < 2; ++mt) {
                const int el = (warp_m * 32 + mt * 16 + (lane & 15)) * A_STRIDE
                             + ks + (lane >> 4) * 8;
                ldsm4(a_[mt], scur + ST_A + el * 2);
            }
#pragma unroll
            for (int np = 0; np < 2; ++np) {
                const int n0 = warp_n * 32 + np * 16;
                const int el = (ks + (lane & 7) + ((lane >> 3) & 1) * 8) * BW_STRIDE
                             + n0 + (lane >> 4) * 8;
                uint32_t bh_[4], bl_[4];
                ldsm4t(bh_, scur + ST_B_HI + el * 2);
                ldsm4t(bl_, scur + ST_B_LO + el * 2);
#pragma unroll
                for (int mt = 0; mt < 2; ++mt) {
#pragma unroll
                    for (int s = 0; s < 2; ++s) {
                        float* d = acc[mt][np * 2 + s];
                        mma16816(d, a_[mt], &bh_[2 * s]);
                        mma16816(d, a_[mt], &bl_[2 * s]);
                    }
                }
            }
        }
    }
}

// pass3: acc += new_h(smem fp16) @ (Ur_hi + Ur_lo)
__device__ __forceinline__ void pass_U(float acc[2][4][4], uint32_t sbase)
{
    const int tid  = threadIdx.x;
    const int lane = tid & 31;
    const int wid  = tid >> 5;
    const int warp_m = wid & 1;
    const int warp_n = wid >> 1;

    const int brow = tid >> 4;
    const int bcol = (tid & 15) * 8;
    const uint32_t b_soff0 = (uint32_t)(brow * BW_STRIDE + bcol) * 2;
    const uint32_t b_soff1 = (uint32_t)(brow * BW_STRIDE + bcol + 128) * 2;
    const size_t b_goff = (size_t)brow * 256 + bcol;

    cpa16(sbase + b_soff0,        &g_Ur_hi[b_goff]);
    cpa16(sbase + b_soff1,        &g_Ur_hi[b_goff + 128]);
    cpa16(sbase + U_LO + b_soff0, &g_Ur_lo[b_goff]);
    cpa16(sbase + U_LO + b_soff1, &g_Ur_lo[b_goff + 128]);
    CP_COMMIT();

    for (int it = 0; it < 8; ++it) {
        const uint32_t scur = sbase + (uint32_t)(it & 1) * U_ST_SZ;
        __syncthreads();
        if (it < 7) {
            const uint32_t snxt = sbase + (uint32_t)((it + 1) & 1) * U_ST_SZ;
            const int kb = (it + 1) * 32;
            cpa16(snxt + b_soff0,        &g_Ur_hi[b_goff + (size_t)kb * 256]);
            cpa16(snxt + b_soff1,        &g_Ur_hi[b_goff + (size_t)kb * 256 + 128]);
            cpa16(snxt + U_LO + b_soff0, &g_Ur_lo[b_goff + (size_t)kb * 256]);
            cpa16(snxt + U_LO + b_soff1, &g_Ur_lo[b_goff + (size_t)kb * 256 + 128]);
        }
        CP_COMMIT();
        CP_WAIT1();
        __syncthreads();

        const int kb = it * 32;
#pragma unroll
        for (int ks = 0; ks < 32; ks += 16) {
            uint32_t a_[2][4];
#pragma unroll
            for (int mt = 0; mt < 2; ++mt) {
                const int el = (warp_m * 32 + mt * 16 + (lane & 15)) * NH_STRIDE
                             + kb + ks + (lane >> 4) * 8;
                ldsm4(a_[mt], sbase + NH_OFF + el * 2);
            }
#pragma unroll
            for (int np = 0; np < 2; ++np) {
                const int n0 = warp_n * 32 + np * 16;
                const int el = (ks + (lane & 7) + ((lane >> 3) & 1) * 8) * BW_STRIDE
                             + n0 + (lane >> 4) * 8;
                uint32_t bh_[4], bl_[4];
                ldsm4t(bh_, scur + el * 2);
                ldsm4t(bl_, scur + U_LO + el * 2);
#pragma unroll
                for (int mt = 0; mt < 2; ++mt) {
#pragma unroll
                    for (int s = 0; s < 2; ++s) {
                        float* d = acc[mt][np * 2 + s];
                        mma16816(d, a_[mt], &bh_[2 * s]);
                        mma16816(d, a_[mt], &bl_[2 * s]);
                    }
                }
            }
        }
    }
}

__global__ void __launch_bounds__(512, 1) step_mma(
    const float* __restrict__ bz, const float* __restrict__ bhb,
    const int*   __restrict__ xids,
    float* __restrict__ hout, __half* __restrict__ hUout, int first)
{
    extern __shared__ char dsm[];
    const uint32_t sbase = smem_u32(dsm);
    const int rowBase = blockIdx.x * 64;

    float acc1[2][4][4] = {};
    float acc2[2][4][4] = {};
    if (!first) {
        pass_AB(g_sh_hi, g_Wzh_hi, g_Wzh_lo, rowBase, acc1, sbase);
        pass_AB(g_sg,    g_Whh_hi, g_Whh_lo, rowBase, acc2, sbase);
    }

    const int lane = threadIdx.x & 31;
    const int wid  = threadIdx.x >> 5;
    const int warp_m = wid & 1, warp_n = wid >> 1;

    // GRU epilogue -> hout (global fp32) + new_h fp16 into smem (NH region)
#pragma unroll
    for (int mt = 0; mt < 2; ++mt) {
#pragma unroll
        for (int nt = 0; nt < 4; ++nt) {
            const int col = warp_n * 32 + nt * 8 + (lane & 3) * 2;
#pragma unroll
            for (int half = 0; half < 2; ++half) {
                const int lr = warp_m * 32 + mt * 16 + (lane >> 2) + half * 8;
                const int r  = rowBase + lr;
                const float a1x = acc1[mt][nt][half * 2 + 0];
                const float a1y = acc1[mt][nt][half * 2 + 1];
                const float a2x = acc2[mt][nt][half * 2 + 0];
                const float a2y = acc2[mt][nt][half * 2 + 1];
                const int xid = xids[r];
                const float2 ez  = *reinterpret_cast<const float2*>(&g_Ez[(size_t)xid * H_ + col]);
                const float2 eh  = *reinterpret_cast<const float2*>(&g_Eh[(size_t)xid * H_ + col]);
                const float2 bzv = *reinterpret_cast<const float2*>(&bz[col]);
                const float2 bhv = *reinterpret_cast<const float2*>(&bhb[col]);
                float sh0 = 0.f, sh1 = 0.f;
                if (!first) {
                    const uint32_t shh = *reinterpret_cast<const uint32_t*>(&g_sh_hi[(size_t)r * H_ + col]);
                    const uint32_t shl = *reinterpret_cast<const uint32_t*>(&g_sh_lo[(size_t)r * H_ + col]);
                    const float2 sh_h = unpack_h2(shh);
                    const float2 sh_l = unpack_h2(shl);
                    sh0 = sh_h.x + sh_l.x;
                    sh1 = sh_h.y + sh_l.y;
                }
                const float z0 = sigf(ez.x + bzv.x + a1x);
                const float z1 = sigf(ez.y + bzv.y + a1y);
                const float p0 = tanhf(eh.x + bhv.x + a2x);
                const float p1 = tanhf(eh.y + bhv.y + a2y);
                const float o0 = (1.0f - z0) * sh0 + z0 * p0;
                const float o1 = (1.0f - z1) * sh1 + z1 * p1;
                *reinterpret_cast<float2*>(&hout[(size_t)r * H_ + col]) = make_float2(o0, o1);
                const uint32_t soff = (uint32_t)(lr * NH_STRIDE + col) * 2;
                __half2 hp; hp.x = __float2half_rn(o0); hp.y = __float2half_rn(o1);
                *reinterpret_cast<__half2*>(dsm + NH_OFF + soff) = hp;
            }
        }
    }

    // pass3: hU = new_h @ Ur (A from smem), store fp16
    float acc3[2][4][4] = {};
    pass_U(acc3, sbase);

#pragma unroll
    for (int mt = 0; mt < 2; ++mt) {
#pragma unroll
        for (int nt = 0; nt < 4; ++nt) {
            const int col = warp_n * 32 + nt * 8 + (lane & 3) * 2;
            const int r0  = rowBase + warp_m * 32 + mt * 16 + (lane >> 2);
            __half2 u0; u0.x = __float2half_rn(acc3[mt][nt][0]);
                        u0.y = __float2half_rn(acc3[mt][nt][1]);
            *reinterpret_cast<__half2*>(&hUout[(size_t)r0 * H_ + col]) = u0;
            __half2 u1; u1.x = __float2half_rn(acc3[mt][nt][2]);
                        u1.y = __float2half_rn(acc3[mt][nt][3]);
            *reinterpret_cast<__half2*>(&hUout[(size_t)(r0 + 8) * H_ + col]) = u1;
        }
    }
}

// ---------------- fused root aggregate ----------------------------------------
__global__ void root_fused(const float* __restrict__ h, const int* __restrict__ rnei,
                           const int* __restrict__ rwid, const float* __restrict__ Woh,
                           const float* __restrict__ bo, float* __restrict__ out)
{
    __shared__ float s_sum[256];
    __shared__ int sj[NB_];
    const int b = blockIdx.x;
    const int c = threadIdx.x;
    if (c < NB_) sj[c] = rnei[b * NB_ + c];
    __syncthreads();
    float s = 0.f;
#pragma unroll
    for (int n = 0; n < NB_; ++n)
        s += h[(size_t)sj[n] * 256 + c];
    s_sum[c] = s;
    __syncthreads();
    float acc = 0.f;
#pragma unroll 8
    for (int k = 0; k < 256; ++k)
        acc += s_sum[k] * Woh[(size_t)k * 256 + c];
    const int xid = rwid[b];
    float v = g_Eo[(size_t)xid * 256 + c] + bo[c] + acc;
    out[(size_t)b * 256 + c] = fmaxf(v, 0.0f);
}

// ---------------- launch ------------------------------------------------------
extern "C" void kernel_launch(void* const* d_in, const int* in_sizes, int n_in,
                              void* d_out, int out_size)
{
    const int*   x_ids    = (const int*)  d_in[0];
    const int*   nei_idx  = (const int*)  d_in[1];
    const int*   root_wid = (const int*)  d_in[2];
    const int*   root_nei = (const int*)  d_in[3];
    const float* emb      = (const float*)d_in[4];
    const float* Wz       = (const float*)d_in[5];
    const float* bz       = (const float*)d_in[6];
    const float* Wr       = (const float*)d_in[7];
    const float* Ur       = (const float*)d_in[8];
    const float* bur      = (const float*)d_in[9];
    const float* Wh       = (const float*)d_in[10];
    const float* bh       = (const float*)d_in[11];
    const float* Wo       = (const float*)d_in[12];
    const float* bo       = (const float*)d_in[13];

    float* out  = (float*)d_out;
    float* h    = out;
    float* rvec = out + (size_t)(M_ + 1) * H_;

    __half* p_hU16;
    cudaGetSymbolAddress((void**)&p_hU16, g_hU16);

    cudaFuncSetAttribute(step_mma, cudaFuncAttributeMaxDynamicSharedMemorySize, SM_TOTAL);

    init_zero<<<1, 256>>>(h);

    dim3 gpre(4, (V_ + 63) / 64, 4);
    gemm_pre<<<gpre, 256>>>(emb, Wz, Wr, Wh, Wo);
    split3<<<dim3(256, 3), 256>>>(Wz, Wh, Ur);

    for (int t = 0; t < T_; ++t) {
        if (t > 0)
            gather_step<<<E_ / 4, 256>>>(h, nei_idx + (size_t)t * E_ * NB_,
                                         x_ids + (size_t)t * E_, bur);
        step_mma<<<E_ / 64, 512, SM_TOTAL>>>(
            bz, bh, x_ids + (size_t)t * E_,
            h + (size_t)(1 + t * E_) * H_,
            p_hU16 + (size_t)(1 + t * E_) * H_,
            (t == 0) ? 1 : 0);
    }

    root_fused<<<B_, 256>>>(h, root_nei, root_wid, Wo + (size_t)H_ * H_, bo, rvec);
}

// round 11
// speedup vs baseline: 2.7069x; 1.2677x over previous
#include <cuda_runtime.h>
#include <cuda_fp16.h>
#include <math.h>
#include <stdint.h>

#define T_  12
#define E_  8192
#define H_  256
#define V_  800
#define B_  256
#define NB_ 8
#define M_  (T_*E_)   // 98304 messages; h has 1+M rows (row 0 = pad)

// ---------------- scratch (static device arrays; no allocs allowed) ----------
__device__ __half g_hU16[(size_t)(M_+1)*H_];   // h @ Ur, fp16 (sigmoid arg only)
__device__ float g_Ez[(size_t)V_*H_];
__device__ float g_Er[(size_t)V_*H_];
__device__ float g_Eh[(size_t)V_*H_];
__device__ float g_Eo[(size_t)V_*H_];

// fp16 operands (single-term weights; sum_h keeps hi+lo for the epilogue path)
__device__ __half g_sh_hi[(size_t)E_*H_], g_sh_lo[(size_t)E_*H_];
__device__ __half g_sg   [(size_t)E_*H_];
__device__ __half g_Wzh[H_*H_];
__device__ __half g_Whh[H_*H_];
__device__ __half g_Ur [H_*H_];

// hardware tanh (sm_75+): ~2^-11 max rel error
__device__ __forceinline__ float tanha(float x) {
    float t;
    asm("tanh.approx.f32 %0, %1;" : "=f"(t) : "f"(x));
    return t;
}
// sigmoid via tanh: sigma(x) = 0.5*tanh(x/2) + 0.5  (1 MUFU)
__device__ __forceinline__ float sigf(float x) {
    return fmaf(0.5f, tanha(0.5f * x), 0.5f);
}

// ---------------- PTX helpers -------------------------------------------------
__device__ __forceinline__ uint32_t smem_u32(const void* p) {
    return (uint32_t)__cvta_generic_to_shared(p);
}
__device__ __forceinline__ void ldsm4(uint32_t* r, uint32_t a) {
    asm volatile("ldmatrix.sync.aligned.m8n8.x4.shared.b16 {%0,%1,%2,%3},[%4];\n"
                 : "=r"(r[0]), "=r"(r[1]), "=r"(r[2]), "=r"(r[3]) : "r"(a));
}
__device__ __forceinline__ void ldsm4t(uint32_t* r, uint32_t a) {
    asm volatile("ldmatrix.sync.aligned.m8n8.x4.trans.shared.b16 {%0,%1,%2,%3},[%4];\n"
                 : "=r"(r[0]), "=r"(r[1]), "=r"(r[2]), "=r"(r[3]) : "r"(a));
}
__device__ __forceinline__ void mma16816(float* d, const uint32_t* a, const uint32_t* b) {
    asm volatile("mma.sync.aligned.m16n8k16.row.col.f32.f16.f16.f32 "
                 "{%0,%1,%2,%3},{%4,%5,%6,%7},{%8,%9},{%0,%1,%2,%3};\n"
                 : "+f"(d[0]), "+f"(d[1]), "+f"(d[2]), "+f"(d[3])
                 : "r"(a[0]), "r"(a[1]), "r"(a[2]), "r"(a[3]), "r"(b[0]), "r"(b[1]));
}
__device__ __forceinline__ void cpa16(uint32_t dst, const void* src) {
    asm volatile("cp.async.cg.shared.global [%0],[%1],16;\n" :: "r"(dst), "l"(src));
}
#define CP_COMMIT()  asm volatile("cp.async.commit_group;\n" ::: "memory")
#define CP_WAIT1()   asm volatile("cp.async.wait_group 1;\n" ::: "memory")

__device__ __forceinline__ uint32_t pack_h2(float a, float b) {
    __half2 t; t.x = __float2half_rn(a); t.y = __float2half_rn(b);
    return *reinterpret_cast<uint32_t*>(&t);
}
__device__ __forceinline__ float2 unpack_h2(uint32_t u) {
    __half2 t = *reinterpret_cast<__half2*>(&u);
    return make_float2(__half2float(t.x), __half2float(t.y));
}

// ---------------- init --------------------------------------------------------
__global__ void init_zero(float* __restrict__ h)
{
    int c = threadIdx.x;
    h[c]      = 0.0f;
    g_hU16[c] = __float2half_rn(0.0f);
}

// ---------------- preamble: 4 embedding projections in one launch -------------
__global__ void gemm_pre(const float* __restrict__ emb,
                         const float* __restrict__ Wz, const float* __restrict__ Wr,
                         const float* __restrict__ Wh, const float* __restrict__ Wo)
{
    const float* Bw; float* C;
    switch (blockIdx.z) {
        case 0:  Bw = Wz; C = g_Ez; break;
        case 1:  Bw = Wr; C = g_Er; break;
        case 2:  Bw = Wh; C = g_Eh; break;
        default: Bw = Wo; C = g_Eo; break;
    }
    __shared__ float As[16][64];
    __shared__ float Bs[16][64];
    const int tid = threadIdx.x;
    const int tx = tid & 15, ty = tid >> 4;
    const int rowBase = blockIdx.y * 64;
    const int colBase = blockIdx.x * 64;
    const int lm  = tid >> 2;
    const int lk  = (tid & 3) * 4;
    const int blk = tid >> 4;
    const int bln = (tid & 15) * 4;
    float acc[4][4] = {};
    for (int kb = 0; kb < 256; kb += 16) {
        int ar = rowBase + lm;
        float4 av = make_float4(0.f, 0.f, 0.f, 0.f);
        if (ar < V_)
            av = *reinterpret_cast<const float4*>(&emb[(size_t)ar * 256 + kb + lk]);
        As[lk + 0][lm] = av.x; As[lk + 1][lm] = av.y;
        As[lk + 2][lm] = av.z; As[lk + 3][lm] = av.w;
        float4 bv = *reinterpret_cast<const float4*>(&Bw[(size_t)(kb + blk) * 256 + colBase + bln]);
        *reinterpret_cast<float4*>(&Bs[blk][bln]) = bv;
        __syncthreads();
#pragma unroll
        for (int k = 0; k < 16; ++k) {
            float4 a4 = *reinterpret_cast<const float4*>(&As[k][ty * 4]);
            float4 b4 = *reinterpret_cast<const float4*>(&Bs[k][tx * 4]);
            float aa[4] = {a4.x, a4.y, a4.z, a4.w};
            float bb[4] = {b4.x, b4.y, b4.z, b4.w};
#pragma unroll
            for (int i = 0; i < 4; ++i)
#pragma unroll
                for (int j = 0; j < 4; ++j)
                    acc[i][j] += aa[i] * bb[j];
        }
        __syncthreads();
    }
#pragma unroll
    for (int i = 0; i < 4; ++i) {
        int r = rowBase + ty * 4 + i;
        if (r < V_)
            *reinterpret_cast<float4*>(&C[(size_t)r * 256 + colBase + tx * 4]) =
                make_float4(acc[i][0], acc[i][1], acc[i][2], acc[i][3]);
    }
}

// ---------------- preamble: 3 weight conversions (single fp16) ----------------
__global__ void conv3(const float* __restrict__ Wz, const float* __restrict__ Wh,
                      const float* __restrict__ Ur)
{
    const float* W; __half* dst;
    switch (blockIdx.y) {
        case 0:  W = Wz + H_ * H_; dst = g_Wzh; break;
        case 1:  W = Wh + H_ * H_; dst = g_Whh; break;
        default: W = Ur;           dst = g_Ur;  break;
    }
    int i = blockIdx.x * 256 + threadIdx.x;
    dst[i] = __float2half_rn(W[i]);
}

// ---------------- per-step gather -> fp16 outputs ------------------------------
__global__ void gather_step(const float* __restrict__ h,
                            const int*   __restrict__ nei,
                            const int*   __restrict__ xids,
                            const float* __restrict__ bur)
{
    const int msg = blockIdx.x * 4 + (threadIdx.x >> 6);
    const int c4  = threadIdx.x & 63;

    const int xid = xids[msg];
    const float4 bu = reinterpret_cast<const float4*>(bur)[c4];
    const float4 er = reinterpret_cast<const float4*>(&g_Er[(size_t)xid * H_])[c4];
    const float bx = er.x + bu.x, by = er.y + bu.y, bz2 = er.z + bu.z, bw = er.w + bu.w;

    float4 sh = make_float4(0.f, 0.f, 0.f, 0.f);
    float4 sg = make_float4(0.f, 0.f, 0.f, 0.f);
#pragma unroll
    for (int n = 0; n < NB_; ++n) {
        const int j = nei[msg * NB_ + n];
        const float4 hv = reinterpret_cast<const float4*>(h)[(size_t)j * 64 + c4];
        const uint2 up = reinterpret_cast<const uint2*>(g_hU16)[(size_t)j * 64 + c4];
        const float2 u01 = unpack_h2(up.x);
        const float2 u23 = unpack_h2(up.y);
        sh.x += hv.x; sh.y += hv.y; sh.z += hv.z; sh.w += hv.w;
        sg.x += sigf(bx  + u01.x) * hv.x;
        sg.y += sigf(by  + u01.y) * hv.y;
        sg.z += sigf(bz2 + u23.x) * hv.z;
        sg.w += sigf(bw  + u23.y) * hv.w;
    }
    const size_t o4 = (size_t)msg * 64 + c4;
    {
        __half h0 = __float2half_rn(sh.x), h1 = __float2half_rn(sh.y),
               h2 = __float2half_rn(sh.z), h3 = __float2half_rn(sh.w);
        uint2 u;
        { __half2 a; a.x = h0; a.y = h1; u.x = *reinterpret_cast<uint32_t*>(&a); }
        { __half2 a; a.x = h2; a.y = h3; u.y = *reinterpret_cast<uint32_t*>(&a); }
        reinterpret_cast<uint2*>(g_sh_hi)[o4] = u;
        uint2 v;
        v.x = pack_h2(sh.x - __half2float(h0), sh.y - __half2float(h1));
        v.y = pack_h2(sh.z - __half2float(h2), sh.w - __half2float(h3));
        reinterpret_cast<uint2*>(g_sh_lo)[o4] = v;
    }
    {
        uint2 u;
        u.x = pack_h2(sg.x, sg.y);
        u.y = pack_h2(sg.z, sg.w);
        reinterpret_cast<uint2*>(g_sg)[o4] = u;
    }
}

// ---------------- fused step GEMM: BM=64, BN=256, 512 threads -----------------
// 16 warps = 2(M) x 8(N); warp tile 32x32. Single-term fp16: A @ W.
#define A_STRIDE  40     // 32 + 8 pad (fp16)
#define BW_STRIDE 264    // 256 + 8 pad
#define NH_STRIDE 264

#define ST_A     0                // 64*40*2  = 5120
#define ST_B     5120             // 32*264*2 = 16896
#define ST_SZ    22016
#define P_SZ     (2*ST_SZ)        // 44032
#define U_ST_SZ  16896            // pass3 stage (Ur only), double-buffered in P region
#define NH_OFF   P_SZ             // 44032, size 64*264*2 = 33792
#define SM_TOTAL (P_SZ + 33792)   // 77824 bytes

// pass over K=256: acc += A(fp16) @ B(fp16), A/B from global
__device__ __forceinline__ void pass_AB(
    const __half* __restrict__ A, const __half* __restrict__ Bw,
    int rowBase, float acc[2][4][4], uint32_t sbase)
{
    const int tid  = threadIdx.x;
    const int lane = tid & 31;
    const int wid  = tid >> 5;
    const int warp_m = wid & 1;
    const int warp_n = wid >> 1;   // 0..7

    const bool doA  = tid < 256;
    const int  arow = (tid & 255) >> 2;
    const int  ak   = (tid & 3) * 8;
    const uint32_t a_soff = ST_A + (uint32_t)(arow * A_STRIDE + ak) * 2;
    const size_t a_goff = (size_t)(rowBase + arow) * 256 + ak;

    const int brow = tid >> 4;           // 0..31
    const int bcol = (tid & 15) * 8;     // 0..120
    const uint32_t b_soff0 = (uint32_t)(brow * BW_STRIDE + bcol) * 2;
    const uint32_t b_soff1 = (uint32_t)(brow * BW_STRIDE + bcol + 128) * 2;
    const size_t b_goff = (size_t)brow * 256 + bcol;

    if (doA) cpa16(sbase + a_soff, &A[a_goff]);
    cpa16(sbase + ST_B + b_soff0, &Bw[b_goff]);
    cpa16(sbase + ST_B + b_soff1, &Bw[b_goff + 128]);
    CP_COMMIT();

    for (int it = 0; it < 8; ++it) {
        const uint32_t scur = sbase + (uint32_t)(it & 1) * ST_SZ;
        __syncthreads();
        if (it < 7) {
            const uint32_t snxt = sbase + (uint32_t)((it + 1) & 1) * ST_SZ;
            const int kb = (it + 1) * 32;
            if (doA) cpa16(snxt + a_soff, &A[a_goff + kb]);
            cpa16(snxt + ST_B + b_soff0, &Bw[b_goff + (size_t)kb * 256]);
            cpa16(snxt + ST_B + b_soff1, &Bw[b_goff + (size_t)kb * 256 + 128]);
        }
        CP_COMMIT();
        CP_WAIT1();
        __syncthreads();

#pragma unroll
        for (int ks = 0; ks < 32; ks += 16) {
            uint32_t a_[2][4];
#pragma unroll
            for (int mt = 0; mt < 2; ++mt) {
                const int el = (warp_m * 32 + mt * 16 + (lane & 15)) * A_STRIDE
                             + ks + (lane >> 4) * 8;
                ldsm4(a_[mt], scur + ST_A + el * 2);
            }
#pragma unroll
            for (int np = 0; np < 2; ++np) {
                const int n0 = warp_n * 32 + np * 16;
                const int el = (ks + (lane & 7) + ((lane >> 3) & 1) * 8) * BW_STRIDE
                             + n0 + (lane >> 4) * 8;
                uint32_t bh_[4];
                ldsm4t(bh_, scur + ST_B + el * 2);
#pragma unroll
                for (int mt = 0; mt < 2; ++mt) {
#pragma unroll
                    for (int s = 0; s < 2; ++s)
                        mma16816(acc[mt][np * 2 + s], a_[mt], &bh_[2 * s]);
                }
            }
        }
    }
}

// pass3: acc += new_h(smem fp16) @ Ur(fp16)
__device__ __forceinline__ void pass_U(float acc[2][4][4], uint32_t sbase)
{
    const int tid  = threadIdx.x;
    const int lane = tid & 31;
    const int wid  = tid >> 5;
    const int warp_m = wid & 1;
    const int warp_n = wid >> 1;

    const int brow = tid >> 4;
    const int bcol = (tid & 15) * 8;
    const uint32_t b_soff0 = (uint32_t)(brow * BW_STRIDE + bcol) * 2;
    const uint32_t b_soff1 = (uint32_t)(brow * BW_STRIDE + bcol + 128) * 2;
    const size_t b_goff = (size_t)brow * 256 + bcol;

    cpa16(sbase + b_soff0, &g_Ur[b_goff]);
    cpa16(sbase + b_soff1, &g_Ur[b_goff + 128]);
    CP_COMMIT();

    for (int it = 0; it < 8; ++it) {
        const uint32_t scur = sbase + (uint32_t)(it & 1) * U_ST_SZ;
        __syncthreads();
        if (it < 7) {
            const uint32_t snxt = sbase + (uint32_t)((it + 1) & 1) * U_ST_SZ;
            const int kb = (it + 1) * 32;
            cpa16(snxt + b_soff0, &g_Ur[b_goff + (size_t)kb * 256]);
            cpa16(snxt + b_soff1, &g_Ur[b_goff + (size_t)kb * 256 + 128]);
        }
        CP_COMMIT();
        CP_WAIT1();
        __syncthreads();

        const int kb = it * 32;
#pragma unroll
        for (int ks = 0; ks < 32; ks += 16) {
            uint32_t a_[2][4];
#pragma unroll
            for (int mt = 0; mt < 2; ++mt) {
                const int el = (warp_m * 32 + mt * 16 + (lane & 15)) * NH_STRIDE
                             + kb + ks + (lane >> 4) * 8;
                ldsm4(a_[mt], sbase + NH_OFF + el * 2);
            }
#pragma unroll
            for (int np = 0; np < 2; ++np) {
                const int n0 = warp_n * 32 + np * 16;
                const int el = (ks + (lane & 7) + ((lane >> 3) & 1) * 8) * BW_STRIDE
                             + n0 + (lane >> 4) * 8;
                uint32_t bh_[4];
                ldsm4t(bh_, scur + el * 2);
#pragma unroll
                for (int mt = 0; mt < 2; ++mt) {
#pragma unroll
                    for (int s = 0; s < 2; ++s)
                        mma16816(acc[mt][np * 2 + s], a_[mt], &bh_[2 * s]);
                }
            }
        }
    }
}

__global__ void __launch_bounds__(512, 1) step_mma(
    const float* __restrict__ bz, const float* __restrict__ bhb,
    const int*   __restrict__ xids,
    float* __restrict__ hout, __half* __restrict__ hUout, int first)
{
    extern __shared__ char dsm[];
    const uint32_t sbase = smem_u32(dsm);
    const int rowBase = blockIdx.x * 64;

    float acc1[2][4][4] = {};
    float acc2[2][4][4] = {};
    if (!first) {
        pass_AB(g_sh_hi, g_Wzh, rowBase, acc1, sbase);
        pass_AB(g_sg,    g_Whh, rowBase, acc2, sbase);
    }

    const int lane = threadIdx.x & 31;
    const int wid  = threadIdx.x >> 5;
    const int warp_m = wid & 1, warp_n = wid >> 1;

    // GRU epilogue -> hout (global fp32) + new_h fp16 into smem (NH region)
#pragma unroll
    for (int mt = 0; mt < 2; ++mt) {
#pragma unroll
        for (int nt = 0; nt < 4; ++nt) {
            const int col = warp_n * 32 + nt * 8 + (lane & 3) * 2;
#pragma unroll
            for (int half = 0; half < 2; ++half) {
                const int lr = warp_m * 32 + mt * 16 + (lane >> 2) + half * 8;
                const int r  = rowBase + lr;
                const float a1x = acc1[mt][nt][half * 2 + 0];
                const float a1y = acc1[mt][nt][half * 2 + 1];
                const float a2x = acc2[mt][nt][half * 2 + 0];
                const float a2y = acc2[mt][nt][half * 2 + 1];
                const int xid = xids[r];
                const float2 ez  = *reinterpret_cast<const float2*>(&g_Ez[(size_t)xid * H_ + col]);
                const float2 eh  = *reinterpret_cast<const float2*>(&g_Eh[(size_t)xid * H_ + col]);
                const float2 bzv = *reinterpret_cast<const float2*>(&bz[col]);
                const float2 bhv = *reinterpret_cast<const float2*>(&bhb[col]);
                float sh0 = 0.f, sh1 = 0.f;
                if (!first) {
                    const uint32_t shh = *reinterpret_cast<const uint32_t*>(&g_sh_hi[(size_t)r * H_ + col]);
                    const uint32_t shl = *reinterpret_cast<const uint32_t*>(&g_sh_lo[(size_t)r * H_ + col]);
                    const float2 sh_h = unpack_h2(shh);
                    const float2 sh_l = unpack_h2(shl);
                    sh0 = sh_h.x + sh_l.x;
                    sh1 = sh_h.y + sh_l.y;
                }
                const float z0 = sigf(ez.x + bzv.x + a1x);
                const float z1 = sigf(ez.y + bzv.y + a1y);
                const float p0 = tanha(eh.x + bhv.x + a2x);
                const float p1 = tanha(eh.y + bhv.y + a2y);
                const float o0 = (1.0f - z0) * sh0 + z0 * p0;
                const float o1 = (1.0f - z1) * sh1 + z1 * p1;
                *reinterpret_cast<float2*>(&hout[(size_t)r * H_ + col]) = make_float2(o0, o1);
                const uint32_t soff = (uint32_t)(lr * NH_STRIDE + col) * 2;
                __half2 hp; hp.x = __float2half_rn(o0); hp.y = __float2half_rn(o1);
                *reinterpret_cast<__half2*>(dsm + NH_OFF + soff) = hp;
            }
        }
    }

    // pass3: hU = new_h @ Ur (A from smem), store fp16
    float acc3[2][4][4] = {};
    pass_U(acc3, sbase);

#pragma unroll
    for (int mt = 0; mt < 2; ++mt) {
#pragma unroll
        for (int nt = 0; nt < 4; ++nt) {
            const int col = warp_n * 32 + nt * 8 + (lane & 3) * 2;
            const int r0  = rowBase + warp_m * 32 + mt * 16 + (lane >> 2);
            __half2 u0; u0.x = __float2half_rn(acc3[mt][nt][0]);
                        u0.y = __float2half_rn(acc3[mt][nt][1]);
            *reinterpret_cast<__half2*>(&hUout[(size_t)r0 * H_ + col]) = u0;
            __half2 u1; u1.x = __float2half_rn(acc3[mt][nt][2]);
                        u1.y = __float2half_rn(acc3[mt][nt][3]);
            *reinterpret_cast<__half2*>(&hUout[(size_t)(r0 + 8) * H_ + col]) = u1;
        }
    }
}

// ---------------- fused root aggregate ----------------------------------------
__global__ void root_fused(const float* __restrict__ h, const int* __restrict__ rnei,
                           const int* __restrict__ rwid, const float* __restrict__ Woh,
                           const float* __restrict__ bo, float* __restrict__ out)
{
    __shared__ float s_sum[256];
    __shared__ int sj[NB_];
    const int b = blockIdx.x;
    const int c = threadIdx.x;
    if (c < NB_) sj[c] = rnei[b * NB_ + c];
    __syncthreads();
    float s = 0.f;
#pragma unroll
    for (int n = 0; n < NB_; ++n)
        s += h[(size_t)sj[n] * 256 + c];
    s_sum[c] = s;
    __syncthreads();
    float acc = 0.f;
#pragma unroll 8
    for (int k = 0; k < 256; ++k)
        acc += s_sum[k] * Woh[(size_t)k * 256 + c];
    const int xid = rwid[b];
    float v = g_Eo[(size_t)xid * 256 + c] + bo[c] + acc;
    out[(size_t)b * 256 + c] = fmaxf(v, 0.0f);
}

// ---------------- launch ------------------------------------------------------
extern "C" void kernel_launch(void* const* d_in, const int* in_sizes, int n_in,
                              void* d_out, int out_size)
{
    const int*   x_ids    = (const int*)  d_in[0];
    const int*   nei_idx  = (const int*)  d_in[1];
    const int*   root_wid = (const int*)  d_in[2];
    const int*   root_nei = (const int*)  d_in[3];
    const float* emb      = (const float*)d_in[4];
    const float* Wz       = (const float*)d_in[5];
    const float* bz       = (const float*)d_in[6];
    const float* Wr       = (const float*)d_in[7];
    const float* Ur       = (const float*)d_in[8];
    const float* bur      = (const float*)d_in[9];
    const float* Wh       = (const float*)d_in[10];
    const float* bh       = (const float*)d_in[11];
    const float* Wo       = (const float*)d_in[12];
    const float* bo       = (const float*)d_in[13];

    float* out  = (float*)d_out;
    float* h    = out;
    float* rvec = out + (size_t)(M_ + 1) * H_;

    __half* p_hU16;
    cudaGetSymbolAddress((void**)&p_hU16, g_hU16);

    cudaFuncSetAttribute(step_mma, cudaFuncAttributeMaxDynamicSharedMemorySize, SM_TOTAL);

    init_zero<<<1, 256>>>(h);

    dim3 gpre(4, (V_ + 63) / 64, 4);
    gemm_pre<<<gpre, 256>>>(emb, Wz, Wr, Wh, Wo);
    conv3<<<dim3(256, 3), 256>>>(Wz, Wh, Ur);

    for (int t = 0; t < T_; ++t) {
        if (t > 0)
            gather_step<<<E_ / 4, 256>>>(h, nei_idx + (size_t)t * E_ * NB_,
                                         x_ids + (size_t)t * E_, bur);
        step_mma<<<E_ / 64, 512, SM_TOTAL>>>(
            bz, bh, x_ids + (size_t)t * E_,
            h + (size_t)(1 + t * E_) * H_,
            p_hU16 + (size_t)(1 + t * E_) * H_,
            (t == 0) ? 1 : 0);
    }

    root_fused<<<B_, 256>>>(h, root_nei, root_wid, Wo + (size_t)H_ * H_, bo, rvec);
}

// round 12
// speedup vs baseline: 2.7282x; 1.0079x over previous
#include <cuda_runtime.h>
#include <cuda_fp16.h>
#include <math.h>
#include <stdint.h>

#define T_  12
#define E_  8192
#define H_  256
#define V_  800
#define B_  256
#define NB_ 8
#define M_  (T_*E_)   // 98304 messages; h has 1+M rows (row 0 = pad)

// ---------------- scratch (static device arrays; no allocs allowed) ----------
__device__ __half g_hU16[(size_t)(M_+1)*H_];   // h @ Ur, fp16 (sigmoid arg only)
__device__ float g_Ez[(size_t)V_*H_];
__device__ float g_Er[(size_t)V_*H_];
__device__ float g_Eh[(size_t)V_*H_];
__device__ float g_Eo[(size_t)V_*H_];

// fp16 operands (single-term weights; sum_h keeps hi+lo for the epilogue path)
__device__ __half g_sh_hi[(size_t)E_*H_], g_sh_lo[(size_t)E_*H_];
__device__ __half g_sg   [(size_t)E_*H_];
__device__ __half g_Wzh[H_*H_];
__device__ __half g_Whh[H_*H_];
__device__ __half g_Ur [H_*H_];

// hardware tanh (sm_75+): ~2^-11 max rel error
__device__ __forceinline__ float tanha(float x) {
    float t;
    asm("tanh.approx.f32 %0, %1;" : "=f"(t) : "f"(x));
    return t;
}
// sigmoid via tanh: sigma(x) = 0.5*tanh(x/2) + 0.5  (1 MUFU)
__device__ __forceinline__ float sigf(float x) {
    return fmaf(0.5f, tanha(0.5f * x), 0.5f);
}

// ---------------- PTX helpers -------------------------------------------------
__device__ __forceinline__ uint32_t smem_u32(const void* p) {
    return (uint32_t)__cvta_generic_to_shared(p);
}
__device__ __forceinline__ void ldsm4(uint32_t* r, uint32_t a) {
    asm volatile("ldmatrix.sync.aligned.m8n8.x4.shared.b16 {%0,%1,%2,%3},[%4];\n"
                 : "=r"(r[0]), "=r"(r[1]), "=r"(r[2]), "=r"(r[3]) : "r"(a));
}
__device__ __forceinline__ void ldsm4t(uint32_t* r, uint32_t a) {
    asm volatile("ldmatrix.sync.aligned.m8n8.x4.trans.shared.b16 {%0,%1,%2,%3},[%4];\n"
                 : "=r"(r[0]), "=r"(r[1]), "=r"(r[2]), "=r"(r[3]) : "r"(a));
}
__device__ __forceinline__ void mma16816(float* d, const uint32_t* a, const uint32_t* b) {
    asm volatile("mma.sync.aligned.m16n8k16.row.col.f32.f16.f16.f32 "
                 "{%0,%1,%2,%3},{%4,%5,%6,%7},{%8,%9},{%0,%1,%2,%3};\n"
                 : "+f"(d[0]), "+f"(d[1]), "+f"(d[2]), "+f"(d[3])
                 : "r"(a[0]), "r"(a[1]), "r"(a[2]), "r"(a[3]), "r"(b[0]), "r"(b[1]));
}
__device__ __forceinline__ void cpa16(uint32_t dst, const void* src) {
    asm volatile("cp.async.cg.shared.global [%0],[%1],16;\n" :: "r"(dst), "l"(src));
}
#define CP_COMMIT()  asm volatile("cp.async.commit_group;\n" ::: "memory")
#define CP_WAIT1()   asm volatile("cp.async.wait_group 1;\n" ::: "memory")

__device__ __forceinline__ uint32_t pack_h2(float a, float b) {
    __half2 t; t.x = __float2half_rn(a); t.y = __float2half_rn(b);
    return *reinterpret_cast<uint32_t*>(&t);
}
__device__ __forceinline__ float2 unpack_h2(uint32_t u) {
    __half2 t = *reinterpret_cast<__half2*>(&u);
    return make_float2(__half2float(t.x), __half2float(t.y));
}

// ---------------- init --------------------------------------------------------
__global__ void init_zero(float* __restrict__ h)
{
    int c = threadIdx.x;
    h[c]      = 0.0f;
    g_hU16[c] = __float2half_rn(0.0f);
}

// ---------------- preamble: 4 embedding projections in one launch -------------
__global__ void gemm_pre(const float* __restrict__ emb,
                         const float* __restrict__ Wz, const float* __restrict__ Wr,
                         const float* __restrict__ Wh, const float* __restrict__ Wo)
{
    const float* Bw; float* C;
    switch (blockIdx.z) {
        case 0:  Bw = Wz; C = g_Ez; break;
        case 1:  Bw = Wr; C = g_Er; break;
        case 2:  Bw = Wh; C = g_Eh; break;
        default: Bw = Wo; C = g_Eo; break;
    }
    __shared__ float As[16][64];
    __shared__ float Bs[16][64];
    const int tid = threadIdx.x;
    const int tx = tid & 15, ty = tid >> 4;
    const int rowBase = blockIdx.y * 64;
    const int colBase = blockIdx.x * 64;
    const int lm  = tid >> 2;
    const int lk  = (tid & 3) * 4;
    const int blk = tid >> 4;
    const int bln = (tid & 15) * 4;
    float acc[4][4] = {};
    for (int kb = 0; kb < 256; kb += 16) {
        int ar = rowBase + lm;
        float4 av = make_float4(0.f, 0.f, 0.f, 0.f);
        if (ar < V_)
            av = *reinterpret_cast<const float4*>(&emb[(size_t)ar * 256 + kb + lk]);
        As[lk + 0][lm] = av.x; As[lk + 1][lm] = av.y;
        As[lk + 2][lm] = av.z; As[lk + 3][lm] = av.w;
        float4 bv = *reinterpret_cast<const float4*>(&Bw[(size_t)(kb + blk) * 256 + colBase + bln]);
        *reinterpret_cast<float4*>(&Bs[blk][bln]) = bv;
        __syncthreads();
#pragma unroll
        for (int k = 0; k < 16; ++k) {
            float4 a4 = *reinterpret_cast<const float4*>(&As[k][ty * 4]);
            float4 b4 = *reinterpret_cast<const float4*>(&Bs[k][tx * 4]);
            float aa[4] = {a4.x, a4.y, a4.z, a4.w};
            float bb[4] = {b4.x, b4.y, b4.z, b4.w};
#pragma unroll
            for (int i = 0; i < 4; ++i)
#pragma unroll
                for (int j = 0; j < 4; ++j)
                    acc[i][j] += aa[i] * bb[j];
        }
        __syncthreads();
    }
#pragma unroll
    for (int i = 0; i < 4; ++i) {
        int r = rowBase + ty * 4 + i;
        if (r < V_)
            *reinterpret_cast<float4*>(&C[(size_t)r * 256 + colBase + tx * 4]) =
                make_float4(acc[i][0], acc[i][1], acc[i][2], acc[i][3]);
    }
}

// ---------------- preamble: 3 weight conversions (single fp16) ----------------
__global__ void conv3(const float* __restrict__ Wz, const float* __restrict__ Wh,
                      const float* __restrict__ Ur)
{
    const float* W; __half* dst;
    switch (blockIdx.y) {
        case 0:  W = Wz + H_ * H_; dst = g_Wzh; break;
        case 1:  W = Wh + H_ * H_; dst = g_Whh; break;
        default: W = Ur;           dst = g_Ur;  break;
    }
    int i = blockIdx.x * 256 + threadIdx.x;
    dst[i] = __float2half_rn(W[i]);
}

// ---------------- per-step gather -> fp16 outputs ------------------------------
__global__ void gather_step(const float* __restrict__ h,
                            const int*   __restrict__ nei,
                            const int*   __restrict__ xids,
                            const float* __restrict__ bur)
{
    const int msg = blockIdx.x * 4 + (threadIdx.x >> 6);
    const int c4  = threadIdx.x & 63;

    const int xid = xids[msg];
    const float4 bu = reinterpret_cast<const float4*>(bur)[c4];
    const float4 er = reinterpret_cast<const float4*>(&g_Er[(size_t)xid * H_])[c4];
    const float bx = er.x + bu.x, by = er.y + bu.y, bz2 = er.z + bu.z, bw = er.w + bu.w;

    float4 sh = make_float4(0.f, 0.f, 0.f, 0.f);
    float4 sg = make_float4(0.f, 0.f, 0.f, 0.f);
#pragma unroll
    for (int n = 0; n < NB_; ++n) {
        const int j = nei[msg * NB_ + n];
        const float4 hv = reinterpret_cast<const float4*>(h)[(size_t)j * 64 + c4];
        const uint2 up = reinterpret_cast<const uint2*>(g_hU16)[(size_t)j * 64 + c4];
        const float2 u01 = unpack_h2(up.x);
        const float2 u23 = unpack_h2(up.y);
        sh.x += hv.x; sh.y += hv.y; sh.z += hv.z; sh.w += hv.w;
        sg.x += sigf(bx  + u01.x) * hv.x;
        sg.y += sigf(by  + u01.y) * hv.y;
        sg.z += sigf(bz2 + u23.x) * hv.z;
        sg.w += sigf(bw  + u23.y) * hv.w;
    }
    const size_t o4 = (size_t)msg * 64 + c4;
    {
        __half h0 = __float2half_rn(sh.x), h1 = __float2half_rn(sh.y),
               h2 = __float2half_rn(sh.z), h3 = __float2half_rn(sh.w);
        uint2 u;
        { __half2 a; a.x = h0; a.y = h1; u.x = *reinterpret_cast<uint32_t*>(&a); }
        { __half2 a; a.x = h2; a.y = h3; u.y = *reinterpret_cast<uint32_t*>(&a); }
        reinterpret_cast<uint2*>(g_sh_hi)[o4] = u;
        uint2 v;
        v.x = pack_h2(sh.x - __half2float(h0), sh.y - __half2float(h1));
        v.y = pack_h2(sh.z - __half2float(h2), sh.w - __half2float(h3));
        reinterpret_cast<uint2*>(g_sh_lo)[o4] = v;
    }
    {
        uint2 u;
        u.x = pack_h2(sg.x, sg.y);
        u.y = pack_h2(sg.z, sg.w);
        reinterpret_cast<uint2*>(g_sg)[o4] = u;
    }
}

// ---------------- fused step GEMM: BM=64, BN=256, 512 threads -----------------
// 16 warps = 2(M) x 8(N); warp tile 32x32. Single-term fp16.
// Passes 1+2 fused in ONE k-loop (dual A, dual B).
#define A_STRIDE  40     // 32 + 8 pad (fp16)
#define BW_STRIDE 264    // 256 + 8 pad
#define NH_STRIDE 264

#define ST_A1    0                // 64*40*2  = 5120
#define ST_A2    5120
#define ST_B1    10240            // 32*264*2 = 16896
#define ST_B2    27136
#define ST_SZ    44032            // per stage
#define P_SZ     (2*ST_SZ)        // 88064
#define U_ST_SZ  16896            // pass3 stage (Ur only), double-buffered at base
#define NH_OFF   P_SZ             // 88064, size 64*264*2 = 33792
#define SM_TOTAL (P_SZ + 33792)   // 121856 bytes

// fused dual pass over K=256: acc1 += A1 @ B1, acc2 += A2 @ B2
__device__ __forceinline__ void pass_AB2(
    const __half* __restrict__ A1, const __half* __restrict__ A2,
    const __half* __restrict__ B1, const __half* __restrict__ B2,
    int rowBase, float acc1[2][4][4], float acc2[2][4][4], uint32_t sbase)
{
    const int tid  = threadIdx.x;
    const int lane = tid & 31;
    const int wid  = tid >> 5;
    const int warp_m = wid & 1;
    const int warp_n = wid >> 1;   // 0..7

    // A: tid<256 stages A1, tid>=256 stages A2 (one cpa16 each)
    const int  asel = tid >> 8;          // 0 or 1
    const int  arow = (tid & 255) >> 2;  // 0..63
    const int  ak   = (tid & 3) * 8;
    const uint32_t a_soff = (asel ? ST_A2 : ST_A1) + (uint32_t)(arow * A_STRIDE + ak) * 2;
    const __half* Ag = asel ? A2 : A1;
    const size_t a_goff = (size_t)(rowBase + arow) * 256 + ak;

    // B: [32 k, 256 n]; 2 cpa16/thread per matrix
    const int brow = tid >> 4;           // 0..31
    const int bcol = (tid & 15) * 8;     // 0..120
    const uint32_t b_soff0 = (uint32_t)(brow * BW_STRIDE + bcol) * 2;
    const uint32_t b_soff1 = (uint32_t)(brow * BW_STRIDE + bcol + 128) * 2;
    const size_t b_goff = (size_t)brow * 256 + bcol;

    cpa16(sbase + a_soff, &Ag[a_goff]);
    cpa16(sbase + ST_B1 + b_soff0, &B1[b_goff]);
    cpa16(sbase + ST_B1 + b_soff1, &B1[b_goff + 128]);
    cpa16(sbase + ST_B2 + b_soff0, &B2[b_goff]);
    cpa16(sbase + ST_B2 + b_soff1, &B2[b_goff + 128]);
    CP_COMMIT();

    for (int it = 0; it < 8; ++it) {
        const uint32_t scur = sbase + (uint32_t)(it & 1) * ST_SZ;
        __syncthreads();
        if (it < 7) {
            const uint32_t snxt = sbase + (uint32_t)((it + 1) & 1) * ST_SZ;
            const int kb = (it + 1) * 32;
            cpa16(snxt + a_soff, &Ag[a_goff + kb]);
            cpa16(snxt + ST_B1 + b_soff0, &B1[b_goff + (size_t)kb * 256]);
            cpa16(snxt + ST_B1 + b_soff1, &B1[b_goff + (size_t)kb * 256 + 128]);
            cpa16(snxt + ST_B2 + b_soff0, &B2[b_goff + (size_t)kb * 256]);
            cpa16(snxt + ST_B2 + b_soff1, &B2[b_goff + (size_t)kb * 256 + 128]);
        }
        CP_COMMIT();
        CP_WAIT1();
        __syncthreads();

#pragma unroll
        for (int ks = 0; ks < 32; ks += 16) {
            uint32_t a1_[2][4], a2_[2][4];
#pragma unroll
            for (int mt = 0; mt < 2; ++mt) {
                const int el = (warp_m * 32 + mt * 16 + (lane & 15)) * A_STRIDE
                             + ks + (lane >> 4) * 8;
                ldsm4(a1_[mt], scur + ST_A1 + el * 2);
                ldsm4(a2_[mt], scur + ST_A2 + el * 2);
            }
#pragma unroll
            for (int np = 0; np < 2; ++np) {
                const int n0 = warp_n * 32 + np * 16;
                const int el = (ks + (lane & 7) + ((lane >> 3) & 1) * 8) * BW_STRIDE
                             + n0 + (lane >> 4) * 8;
                uint32_t b1_[4], b2_[4];
                ldsm4t(b1_, scur + ST_B1 + el * 2);
                ldsm4t(b2_, scur + ST_B2 + el * 2);
#pragma unroll
                for (int mt = 0; mt < 2; ++mt) {
#pragma unroll
                    for (int s = 0; s < 2; ++s) {
                        mma16816(acc1[mt][np * 2 + s], a1_[mt], &b1_[2 * s]);
                        mma16816(acc2[mt][np * 2 + s], a2_[mt], &b2_[2 * s]);
                    }
                }
            }
        }
    }
}

// pass3: acc += new_h(smem fp16) @ Ur(fp16)
__device__ __forceinline__ void pass_U(float acc[2][4][4], uint32_t sbase)
{
    const int tid  = threadIdx.x;
    const int lane = tid & 31;
    const int wid  = tid >> 5;
    const int warp_m = wid & 1;
    const int warp_n = wid >> 1;

    const int brow = tid >> 4;
    const int bcol = (tid & 15) * 8;
    const uint32_t b_soff0 = (uint32_t)(brow * BW_STRIDE + bcol) * 2;
    const uint32_t b_soff1 = (uint32_t)(brow * BW_STRIDE + bcol + 128) * 2;
    const size_t b_goff = (size_t)brow * 256 + bcol;

    cpa16(sbase + b_soff0, &g_Ur[b_goff]);
    cpa16(sbase + b_soff1, &g_Ur[b_goff + 128]);
    CP_COMMIT();

    for (int it = 0; it < 8; ++it) {
        const uint32_t scur = sbase + (uint32_t)(it & 1) * U_ST_SZ;
        __syncthreads();
        if (it < 7) {
            const uint32_t snxt = sbase + (uint32_t)((it + 1) & 1) * U_ST_SZ;
            const int kb = (it + 1) * 32;
            cpa16(snxt + b_soff0, &g_Ur[b_goff + (size_t)kb * 256]);
            cpa16(snxt + b_soff1, &g_Ur[b_goff + (size_t)kb * 256 + 128]);
        }
        CP_COMMIT();
        CP_WAIT1();
        __syncthreads();

        const int kb = it * 32;
#pragma unroll
        for (int ks = 0; ks < 32; ks += 16) {
            uint32_t a_[2][4];
#pragma unroll
            for (int mt = 0; mt < 2; ++mt) {
                const int el = (warp_m * 32 + mt * 16 + (lane & 15)) * NH_STRIDE
                             + kb + ks + (lane >> 4) * 8;
                ldsm4(a_[mt], sbase + NH_OFF + el * 2);
            }
#pragma unroll
            for (int np = 0; np < 2; ++np) {
                const int n0 = warp_n * 32 + np * 16;
                const int el = (ks + (lane & 7) + ((lane >> 3) & 1) * 8) * BW_STRIDE
                             + n0 + (lane >> 4) * 8;
                uint32_t bh_[4];
                ldsm4t(bh_, scur + el * 2);
#pragma unroll
                for (int mt = 0; mt < 2; ++mt) {
#pragma unroll
                    for (int s = 0; s < 2; ++s)
                        mma16816(acc[mt][np * 2 + s], a_[mt], &bh_[2 * s]);
                }
            }
        }
    }
}

__global__ void __launch_bounds__(512, 1) step_mma(
    const float* __restrict__ bz, const float* __restrict__ bhb,
    const int*   __restrict__ xids,
    float* __restrict__ hout, __half* __restrict__ hUout, int first)
{
    extern __shared__ char dsm[];
    const uint32_t sbase = smem_u32(dsm);
    const int rowBase = blockIdx.x * 64;

    float acc1[2][4][4] = {};
    float acc2[2][4][4] = {};
    if (!first)
        pass_AB2(g_sh_hi, g_sg, g_Wzh, g_Whh, rowBase, acc1, acc2, sbase);

    const int lane = threadIdx.x & 31;
    const int wid  = threadIdx.x >> 5;
    const int warp_m = wid & 1, warp_n = wid >> 1;

    // GRU epilogue -> hout (global fp32) + new_h fp16 into smem (NH region)
#pragma unroll
    for (int mt = 0; mt < 2; ++mt) {
#pragma unroll
        for (int nt = 0; nt < 4; ++nt) {
            const int col = warp_n * 32 + nt * 8 + (lane & 3) * 2;
#pragma unroll
            for (int half = 0; half < 2; ++half) {
                const int lr = warp_m * 32 + mt * 16 + (lane >> 2) + half * 8;
                const int r  = rowBase + lr;
                const float a1x = acc1[mt][nt][half * 2 + 0];
                const float a1y = acc1[mt][nt][half * 2 + 1];
                const float a2x = acc2[mt][nt][half * 2 + 0];
                const float a2y = acc2[mt][nt][half * 2 + 1];
                const int xid = xids[r];
                const float2 ez  = *reinterpret_cast<const float2*>(&g_Ez[(size_t)xid * H_ + col]);
                const float2 eh  = *reinterpret_cast<const float2*>(&g_Eh[(size_t)xid * H_ + col]);
                const float2 bzv = *reinterpret_cast<const float2*>(&bz[col]);
                const float2 bhv = *reinterpret_cast<const float2*>(&bhb[col]);
                float sh0 = 0.f, sh1 = 0.f;
                if (!first) {
                    const uint32_t shh = *reinterpret_cast<const uint32_t*>(&g_sh_hi[(size_t)r * H_ + col]);
                    const uint32_t shl = *reinterpret_cast<const uint32_t*>(&g_sh_lo[(size_t)r * H_ + col]);
                    const float2 sh_h = unpack_h2(shh);
                    const float2 sh_l = unpack_h2(shl);
                    sh0 = sh_h.x + sh_l.x;
                    sh1 = sh_h.y + sh_l.y;
                }
                const float z0 = sigf(ez.x + bzv.x + a1x);
                const float z1 = sigf(ez.y + bzv.y + a1y);
                const float p0 = tanha(eh.x + bhv.x + a2x);
                const float p1 = tanha(eh.y + bhv.y + a2y);
                const float o0 = (1.0f - z0) * sh0 + z0 * p0;
                const float o1 = (1.0f - z1) * sh1 + z1 * p1;
                *reinterpret_cast<float2*>(&hout[(size_t)r * H_ + col]) = make_float2(o0, o1);
                const uint32_t soff = (uint32_t)(lr * NH_STRIDE + col) * 2;
                __half2 hp; hp.x = __float2half_rn(o0); hp.y = __float2half_rn(o1);
                *reinterpret_cast<__half2*>(dsm + NH_OFF + soff) = hp;
            }
        }
    }

    // pass3: hU = new_h @ Ur (A from smem), store fp16
    float acc3[2][4][4] = {};
    pass_U(acc3, sbase);

#pragma unroll
    for (int mt = 0; mt < 2; ++mt) {
#pragma unroll
        for (int nt = 0; nt < 4; ++nt) {
            const int col = warp_n * 32 + nt * 8 + (lane & 3) * 2;
            const int r0  = rowBase + warp_m * 32 + mt * 16 + (lane >> 2);
            __half2 u0; u0.x = __float2half_rn(acc3[mt][nt][0]);
                        u0.y = __float2half_rn(acc3[mt][nt][1]);
            *reinterpret_cast<__half2*>(&hUout[(size_t)r0 * H_ + col]) = u0;
            __half2 u1; u1.x = __float2half_rn(acc3[mt][nt][2]);
                        u1.y = __float2half_rn(acc3[mt][nt][3]);
            *reinterpret_cast<__half2*>(&hUout[(size_t)(r0 + 8) * H_ + col]) = u1;
        }
    }
}

// ---------------- fused root aggregate ----------------------------------------
__global__ void root_fused(const float* __restrict__ h, const int* __restrict__ rnei,
                           const int* __restrict__ rwid, const float* __restrict__ Woh,
                           const float* __restrict__ bo, float* __restrict__ out)
{
    __shared__ float s_sum[256];
    __shared__ int sj[NB_];
    const int b = blockIdx.x;
    const int c = threadIdx.x;
    if (c < NB_) sj[c] = rnei[b * NB_ + c];
    __syncthreads();
    float s = 0.f;
#pragma unroll
    for (int n = 0; n < NB_; ++n)
        s += h[(size_t)sj[n] * 256 + c];
    s_sum[c] = s;
    __syncthreads();
    float acc = 0.f;
#pragma unroll 8
    for (int k = 0; k < 256; ++k)
        acc += s_sum[k] * Woh[(size_t)k * 256 + c];
    const int xid = rwid[b];
    float v = g_Eo[(size_t)xid * 256 + c] + bo[c] + acc;
    out[(size_t)b * 256 + c] = fmaxf(v, 0.0f);
}

// ---------------- launch ------------------------------------------------------
extern "C" void kernel_launch(void* const* d_in, const int* in_sizes, int n_in,
                              void* d_out, int out_size)
{
    const int*   x_ids    = (const int*)  d_in[0];
    const int*   nei_idx  = (const int*)  d_in[1];
    const int*   root_wid = (const int*)  d_in[2];
    const int*   root_nei = (const int*)  d_in[3];
    const float* emb      = (const float*)d_in[4];
    const float* Wz       = (const float*)d_in[5];
    const float* bz       = (const float*)d_in[6];
    const float* Wr       = (const float*)d_in[7];
    const float* Ur       = (const float*)d_in[8];
    const float* bur      = (const float*)d_in[9];
    const float* Wh       = (const float*)d_in[10];
    const float* bh       = (const float*)d_in[11];
    const float* Wo       = (const float*)d_in[12];
    const float* bo       = (const float*)d_in[13];

    float* out  = (float*)d_out;
    float* h    = out;
    float* rvec = out + (size_t)(M_ + 1) * H_;

    __half* p_hU16;
    cudaGetSymbolAddress((void**)&p_hU16, g_hU16);

    cudaFuncSetAttribute(step_mma, cudaFuncAttributeMaxDynamicSharedMemorySize, SM_TOTAL);

    init_zero<<<1, 256>>>(h);

    dim3 gpre(4, (V_ + 63) / 64, 4);
    gemm_pre<<<gpre, 256>>>(emb, Wz, Wr, Wh, Wo);
    conv3<<<dim3(256, 3), 256>>>(Wz, Wh, Ur);

    for (int t = 0; t < T_; ++t) {
        if (t > 0)
            gather_step<<<E_ / 4, 256>>>(h, nei_idx + (size_t)t * E_ * NB_,
                                         x_ids + (size_t)t * E_, bur);
        step_mma<<<E_ / 64, 512, SM_TOTAL>>>(
            bz, bh, x_ids + (size_t)t * E_,
            h + (size_t)(1 + t * E_) * H_,
            p_hU16 + (size_t)(1 + t * E_) * H_,
            (t == 0) ? 1 : 0);
    }

    root_fused<<<B_, 256>>>(h, root_nei, root_wid, Wo + (size_t)H_ * H_, bo, rvec);
}